// round 1
// baseline (speedup 1.0000x reference)
#include <cuda_runtime.h>
#include <cuda_bf16.h>
#include <math.h>

// ---------------------------------------------------------------------------
// Problem constants
// ---------------------------------------------------------------------------
#define BB 2
#define TT 2048
#define DD 1024
#define HH 16
#define DH 64
#define NTOK (BB*TT)            // 4096
#define EE 16
#define KK 2
#define FF 2048
#define CAP 640
#define DP 256
#define NPRIM 512
#define NFLAT (NTOK*KK)         // 8192

// ---------------------------------------------------------------------------
// Scratch (device globals; no allocation allowed)
// ---------------------------------------------------------------------------
__device__ float g_x[NTOK*DD];
__device__ float g_xn[NTOK*DD];
__device__ float g_qkv[NTOK*3*DD];
__device__ float g_attn[NTOK*DD];
__device__ float g_logits[NTOK*EE];
__device__ float g_probs[NTOK*EE];
__device__ int   g_topi[NFLAT];
__device__ float g_topw[NFLAT];
__device__ int   g_slot[NFLAT];
__device__ int   g_keep[NFLAT];
__device__ float g_wcomb[NFLAT];
__device__ int   g_counts[EE];
__device__ float g_pmean[EE];
__device__ float g_buf[EE*CAP*DD];
__device__ float g_h[EE*CAP*FF];
__device__ float g_yb[EE*CAP*DD];
__device__ float g_tq[NTOK*DP];
__device__ float g_tk[NPRIM*DP];
__device__ float g_tv[NPRIM*DP];
__device__ float g_tl[NTOK*NPRIM];
__device__ float g_tout[NTOK*DP];
__device__ float g_gate[NTOK];

// ---------------------------------------------------------------------------
// RMSNorm: one block per token, 256 threads, float4
// ---------------------------------------------------------------------------
__global__ void rmsnorm_kernel(const float* __restrict__ x,
                               const float* __restrict__ w,
                               float* __restrict__ out)
{
    int n = blockIdx.x;
    int tid = threadIdx.x;
    const float4* xp = (const float4*)(x + (size_t)n*DD);
    float4 xv = xp[tid];
    float ss = xv.x*xv.x + xv.y*xv.y + xv.z*xv.z + xv.w*xv.w;
    __shared__ float red[256];
    red[tid] = ss;
    __syncthreads();
    for (int s = 128; s; s >>= 1) {
        if (tid < s) red[tid] += red[tid+s];
        __syncthreads();
    }
    float scale = rsqrtf(red[0] / (float)DD + 1e-6f);
    const float4* wp = (const float4*)w;
    float4 wv = wp[tid];
    float4* op = (float4*)(out + (size_t)n*DD);
    op[tid] = make_float4(xv.x*scale*wv.x, xv.y*scale*wv.y,
                          xv.z*scale*wv.z, xv.w*scale*wv.w);
}

// ---------------------------------------------------------------------------
// Generic 128x128x8 SGEMM, C[M,N] = A[M,K] * op(B)
//   BT=true : B stored [N,K] row-major (use B^T)
//   BT=false: B stored [K,N] row-major
// EPI: 0=store, 1=C+=, 2=silu store, 3=C += gate[row]*v
// blockIdx.z = batch, with strides (in elements)
// Requires M%128==0, N%128==0, K%8==0.
// ---------------------------------------------------------------------------
template<bool BT, int EPI>
__global__ void gemm128(const float* __restrict__ A, const float* __restrict__ Bm,
                        float* __restrict__ C, int M, int N, int K,
                        long long sA, long long sB, long long sC,
                        const float* __restrict__ gate)
{
    A  += blockIdx.z * sA;
    Bm += blockIdx.z * sB;
    C  += blockIdx.z * sC;
    __shared__ float As[8][128];
    __shared__ float Bs[8][128];
    int tid = threadIdx.x;               // 256
    int tx = tid & 15, ty = tid >> 4;
    int row0 = blockIdx.y * 128, col0 = blockIdx.x * 128;
    int ar = tid >> 1, ak = (tid & 1) * 4;
    int bk = tid >> 5, bn = (tid & 31) * 4;
    float acc[8][8];
    #pragma unroll
    for (int i = 0; i < 8; i++)
        #pragma unroll
        for (int j = 0; j < 8; j++) acc[i][j] = 0.f;

    for (int k0 = 0; k0 < K; k0 += 8) {
        float4 av = *(const float4*)&A[(size_t)(row0+ar)*K + k0 + ak];
        As[ak+0][ar] = av.x; As[ak+1][ar] = av.y;
        As[ak+2][ar] = av.z; As[ak+3][ar] = av.w;
        if (BT) {
            float4 bv = *(const float4*)&Bm[(size_t)(col0+ar)*K + k0 + ak];
            Bs[ak+0][ar] = bv.x; Bs[ak+1][ar] = bv.y;
            Bs[ak+2][ar] = bv.z; Bs[ak+3][ar] = bv.w;
        } else {
            float4 bv = *(const float4*)&Bm[(size_t)(k0+bk)*N + col0 + bn];
            *(float4*)&Bs[bk][bn] = bv;
        }
        __syncthreads();
        #pragma unroll
        for (int kk = 0; kk < 8; kk++) {
            float a[8], b[8];
            #pragma unroll
            for (int i = 0; i < 8; i++) a[i] = As[kk][ty*8+i];
            #pragma unroll
            for (int j = 0; j < 8; j++) b[j] = Bs[kk][tx*8+j];
            #pragma unroll
            for (int i = 0; i < 8; i++)
                #pragma unroll
                for (int j = 0; j < 8; j++)
                    acc[i][j] += a[i]*b[j];
        }
        __syncthreads();
    }
    #pragma unroll
    for (int i = 0; i < 8; i++) {
        int row = row0 + ty*8 + i;
        float g = (EPI == 3) ? gate[row] : 0.f;
        #pragma unroll
        for (int j = 0; j < 8; j++) {
            size_t idx = (size_t)row * N + col0 + tx*8 + j;
            float v = acc[i][j];
            if (EPI == 0) C[idx] = v;
            else if (EPI == 1) C[idx] += v;
            else if (EPI == 2) C[idx] = v / (1.f + __expf(-v));
            else C[idx] += g * v;
        }
    }
}

// ---------------------------------------------------------------------------
// RoPE (NeoX-style), applied in place to q and k inside g_qkv
// ---------------------------------------------------------------------------
__global__ void rope_kernel(float* __restrict__ qkv)
{
    int n = blockIdx.x;           // token
    int t = n & (TT-1);
    for (int p = threadIdx.x; p < 1024; p += 256) {
        int which = p >> 9;       // 0=q, 1=k
        int rem = p & 511;
        int h = rem >> 5;
        int i = rem & 31;
        float inv = powf(10000.f, -(float)i / 32.f);
        float ang = (float)t * inv;
        float s, c;
        sincosf(ang, &s, &c);
        size_t base = (size_t)n*3072 + (size_t)which*1024 + h*64 + i;
        float u1 = qkv[base], u2 = qkv[base+32];
        qkv[base]    = u1*c - u2*s;
        qkv[base+32] = u2*c + u1*s;
    }
}

// ---------------------------------------------------------------------------
// Flash attention, causal. grid(32 qblocks, 32 bh), 128 threads.
// BQ=64 queries, key tiles of 32. Thread pair (2q,2q+1) owns one query row.
// ---------------------------------------------------------------------------
__global__ void flash_attn_kernel(const float* __restrict__ qkv,
                                  float* __restrict__ out)
{
    __shared__ float Qs[64][65];
    __shared__ float Ks[32][65];
    __shared__ float Vs[32][65];
    __shared__ float Ps[64][33];
    int qb = blockIdx.x;
    int bh = blockIdx.y;
    int b = bh >> 4, h = bh & 15;
    int tid = threadIdx.x;
    int qr = tid >> 1, half = tid & 1;
    int q0 = qb * 64;

    for (int i = tid; i < 64*64; i += 128) {
        int r = i >> 6, d = i & 63;
        Qs[r][d] = qkv[(size_t)(b*TT + q0 + r)*3072 + h*64 + d];
    }
    float m = -1e30f, l = 0.f;
    float o[32];
    #pragma unroll
    for (int i = 0; i < 32; i++) o[i] = 0.f;
    int qg = q0 + qr;
    int ntiles = 2 * (qb + 1);

    for (int kb = 0; kb < ntiles; kb++) {
        __syncthreads();
        for (int i = tid; i < 32*64; i += 128) {
            int r = i >> 6, d = i & 63;
            size_t base = (size_t)(b*TT + kb*32 + r)*3072 + h*64 + d;
            Ks[r][d] = qkv[base + 1024];
            Vs[r][d] = qkv[base + 2048];
        }
        __syncthreads();

        float s[16];
        #pragma unroll
        for (int j = 0; j < 16; j++) s[j] = 0.f;
        int c0 = half * 16;
        #pragma unroll
        for (int d0 = 0; d0 < 64; d0 += 8) {
            float q[8];
            #pragma unroll
            for (int dd = 0; dd < 8; dd++) q[dd] = Qs[qr][d0+dd];
            #pragma unroll
            for (int j = 0; j < 16; j++)
                #pragma unroll
                for (int dd = 0; dd < 8; dd++)
                    s[j] += q[dd] * Ks[c0+j][d0+dd];
        }
        float mymax = -1e30f;
        #pragma unroll
        for (int j = 0; j < 16; j++) {
            int kg = kb*32 + c0 + j;
            s[j] = (kg <= qg) ? s[j]*0.125f : -1e30f;
            mymax = fmaxf(mymax, s[j]);
        }
        float om = __shfl_xor_sync(0xffffffffu, mymax, 1);
        float m_new = fmaxf(m, fmaxf(mymax, om));
        float corr = __expf(m - m_new);
        float rs = 0.f;
        #pragma unroll
        for (int j = 0; j < 16; j++) {
            float p = __expf(s[j] - m_new);
            s[j] = p; rs += p;
        }
        rs += __shfl_xor_sync(0xffffffffu, rs, 1);
        l = l*corr + rs;
        #pragma unroll
        for (int i = 0; i < 32; i++) o[i] *= corr;
        #pragma unroll
        for (int j = 0; j < 16; j++) Ps[qr][c0+j] = s[j];
        m = m_new;
        __syncthreads();
        #pragma unroll
        for (int j = 0; j < 32; j++) {
            float p = Ps[qr][j];
            #pragma unroll
            for (int i = 0; i < 32; i++)
                o[i] += p * Vs[j][half*32 + i];
        }
    }
    float inv = 1.f / l;
    #pragma unroll
    for (int i = 0; i < 32; i++)
        out[(size_t)(b*TT + qg)*DD + h*64 + half*32 + i] = o[i]*inv;
}

// ---------------------------------------------------------------------------
// Router logits: block per token (128 thr, 4 warps x 4 experts)
// ---------------------------------------------------------------------------
__global__ void router_kernel(const float* __restrict__ xn,
                              const float* __restrict__ rw,
                              float* __restrict__ logits)
{
    int n = blockIdx.x;
    int warp = threadIdx.x >> 5, lane = threadIdx.x & 31;
    const float* xp = xn + (size_t)n*DD;
    for (int j = 0; j < 4; j++) {
        int e = warp*4 + j;
        const float* wp = rw + (size_t)e*DD;
        float s = 0.f;
        for (int i = lane; i < DD; i += 32) s += xp[i]*wp[i];
        #pragma unroll
        for (int off = 16; off; off >>= 1) s += __shfl_xor_sync(0xffffffffu, s, off);
        if (lane == 0) logits[n*EE + e] = s;
    }
}

// ---------------------------------------------------------------------------
// Softmax over 16 experts + top-2 (ties: lowest index, matching lax.top_k)
// ---------------------------------------------------------------------------
__global__ void top2_kernel(const float* __restrict__ logits,
                            float* __restrict__ probs,
                            int* __restrict__ topi, float* __restrict__ topw)
{
    int n = blockIdx.x*blockDim.x + threadIdx.x;
    if (n >= NTOK) return;
    float l[EE];
    float mx = -1e30f;
    #pragma unroll
    for (int e = 0; e < EE; e++) { l[e] = logits[n*EE+e]; mx = fmaxf(mx, l[e]); }
    float sum = 0.f;
    #pragma unroll
    for (int e = 0; e < EE; e++) { l[e] = __expf(l[e]-mx); sum += l[e]; }
    float inv = 1.f/sum;
    #pragma unroll
    for (int e = 0; e < EE; e++) { l[e] *= inv; probs[n*EE+e] = l[e]; }
    int i0 = 0; float p0 = l[0];
    #pragma unroll
    for (int e = 1; e < EE; e++) if (l[e] > p0) { p0 = l[e]; i0 = e; }
    int i1 = (i0 == 0) ? 1 : 0; float p1 = l[i1];
    #pragma unroll
    for (int e = 0; e < EE; e++) if (e != i0 && l[e] > p1) { p1 = l[e]; i1 = e; }
    float ws = p0 + p1;
    topi[n*2]   = i0; topi[n*2+1] = i1;
    topw[n*2]   = p0/ws; topw[n*2+1] = p1/ws;
}

// ---------------------------------------------------------------------------
// Deterministic pmean reduction (16 blocks, fixed tree)
// ---------------------------------------------------------------------------
__global__ void pmean_kernel(const float* __restrict__ probs, float* __restrict__ pmean)
{
    int e = blockIdx.x, tid = threadIdx.x;
    float s = 0.f;
    for (int t = tid; t < NTOK; t += 256) s += probs[t*EE + e];
    __shared__ float red[256];
    red[tid] = s;
    __syncthreads();
    for (int k = 128; k; k >>= 1) {
        if (tid < k) red[tid] += red[tid+k];
        __syncthreads();
    }
    if (tid == 0) pmean[e] = red[0] / (float)NTOK;
}

// ---------------------------------------------------------------------------
// Capacity position assignment: 16 blocks (one per expert), ballot scan over
// the flat assignment list in order (deterministic, matches cumsum).
// ---------------------------------------------------------------------------
__global__ void assign_kernel(const int* __restrict__ topi,
                              const float* __restrict__ topw,
                              int* __restrict__ slot, int* __restrict__ keep,
                              float* __restrict__ wcomb, int* __restrict__ counts)
{
    int e = blockIdx.x;
    int tid = threadIdx.x;            // 256
    int lane = tid & 31, warp = tid >> 5;
    __shared__ int warpsum[8];
    int running = 0;
    for (int base = 0; base < NFLAT; base += 256) {
        int i = base + tid;
        int match = (topi[i] == e) ? 1 : 0;
        unsigned mask = __ballot_sync(0xffffffffu, match);
        if (lane == 0) warpsum[warp] = __popc(mask);
        __syncthreads();
        int wbase = 0, tot = 0;
        #pragma unroll
        for (int w = 0; w < 8; w++) {
            int c = warpsum[w];
            if (w < warp) wbase += c;
            tot += c;
        }
        if (match) {
            int pos = running + wbase + __popc(mask & ((1u << lane) - 1u));
            int kp = (pos < CAP) ? 1 : 0;
            slot[i]  = (pos < CAP-1) ? pos : (CAP-1);
            keep[i]  = kp;
            wcomb[i] = kp ? topw[i] : 0.f;
        }
        running += tot;
        __syncthreads();
    }
    if (tid == 0) counts[e] = running;
}

// ---------------------------------------------------------------------------
// Scatter tokens into expert buffers (each kept (e,slot) unique)
// ---------------------------------------------------------------------------
__global__ void scatter_kernel(const int* __restrict__ topi,
                               const int* __restrict__ slot,
                               const int* __restrict__ keep,
                               const float* __restrict__ xn,
                               float* __restrict__ buf)
{
    int i = blockIdx.x;
    if (!keep[i]) return;
    int e = topi[i], s = slot[i], tok = i >> 1;
    const float4* src = (const float4*)(xn + (size_t)tok*DD);
    float4* dst = (float4*)(buf + ((size_t)e*CAP + s)*DD);
    dst[threadIdx.x] = src[threadIdx.x];
}

// ---------------------------------------------------------------------------
// Gather expert outputs + residual into x
// ---------------------------------------------------------------------------
__global__ void gather_kernel(const int* __restrict__ topi,
                              const int* __restrict__ slot,
                              const float* __restrict__ wcomb,
                              const float* __restrict__ yb,
                              float* __restrict__ x)
{
    int n = blockIdx.x;
    int t4 = threadIdx.x;
    float4* xp = (float4*)(x + (size_t)n*DD);
    float4 a = xp[t4];
    #pragma unroll
    for (int k = 0; k < 2; k++) {
        int i = n*2 + k;
        float w = wcomb[i];
        if (w != 0.f) {
            int e = topi[i], s = slot[i];
            const float4* yp = (const float4*)(yb + ((size_t)e*CAP + s)*DD);
            float4 yv = yp[t4];
            a.x += w*yv.x; a.y += w*yv.y; a.z += w*yv.z; a.w += w*yv.w;
        }
    }
    xp[t4] = a;
}

// ---------------------------------------------------------------------------
// aux = E * sum(frac * pmean); written at d_out[B*T*D]
// ---------------------------------------------------------------------------
__global__ void aux_kernel(const int* __restrict__ counts,
                           const float* __restrict__ pmean,
                           float* __restrict__ out, int out_size)
{
    if (threadIdx.x == 0 && out_size > NTOK*DD) {
        float s = 0.f;
        for (int e = 0; e < EE; e++)
            s += ((float)counts[e] / (float)NTOK) * pmean[e];
        out[NTOK*DD] = (float)EE * s;
    }
}

// ---------------------------------------------------------------------------
// ToU gate: sigmoid(xn . gw + gb) per token
// ---------------------------------------------------------------------------
__global__ void gate_kernel(const float* __restrict__ xn,
                            const float* __restrict__ gw,
                            const float* __restrict__ gb,
                            float* __restrict__ gate)
{
    int n = blockIdx.x, tid = threadIdx.x;
    const float4* xp = (const float4*)(xn + (size_t)n*DD);
    const float4* wp = (const float4*)gw;
    float4 xv = xp[tid], wv = wp[tid];
    float s = xv.x*wv.x + xv.y*wv.y + xv.z*wv.z + xv.w*wv.w;
    __shared__ float red[256];
    red[tid] = s;
    __syncthreads();
    for (int k = 128; k; k >>= 1) {
        if (tid < k) red[tid] += red[tid+k];
        __syncthreads();
    }
    if (tid == 0) gate[n] = 1.f / (1.f + __expf(-(red[0] + gb[0])));
}

// ---------------------------------------------------------------------------
// Softmax over 512 primitives (scale 1/16 folded in), in place
// ---------------------------------------------------------------------------
__global__ void softmax512_kernel(float* __restrict__ tl)
{
    int n = blockIdx.x, tid = threadIdx.x;
    float* row = tl + (size_t)n*NPRIM;
    float v0 = row[tid]       * 0.0625f;
    float v1 = row[tid + 256] * 0.0625f;
    __shared__ float red[256];
    red[tid] = fmaxf(v0, v1);
    __syncthreads();
    for (int s = 128; s; s >>= 1) {
        if (tid < s) red[tid] = fmaxf(red[tid], red[tid+s]);
        __syncthreads();
    }
    float mx = red[0];
    __syncthreads();
    v0 = __expf(v0 - mx); v1 = __expf(v1 - mx);
    red[tid] = v0 + v1;
    __syncthreads();
    for (int s = 128; s; s >>= 1) {
        if (tid < s) red[tid] += red[tid+s];
        __syncthreads();
    }
    float inv = 1.f / red[0];
    row[tid] = v0*inv; row[tid+256] = v1*inv;
}

// ---------------------------------------------------------------------------
// Host launch
// ---------------------------------------------------------------------------
extern "C" void kernel_launch(void* const* d_in, const int* in_sizes, int n_in,
                              void* d_out, int out_size)
{
    const float* x          = (const float*)d_in[0];
    const float* tou_embeds = (const float*)d_in[1];
    const float* norm1_w    = (const float*)d_in[2];
    const float* qkv_w      = (const float*)d_in[3];
    const float* attn_o_w   = (const float*)d_in[4];
    const float* norm2_w    = (const float*)d_in[5];
    const float* router_w   = (const float*)d_in[6];
    const float* moe_w1     = (const float*)d_in[7];
    const float* moe_w2     = (const float*)d_in[8];
    const float* norm3_w    = (const float*)d_in[9];
    const float* tou_q_w    = (const float*)d_in[10];
    const float* tou_k_w    = (const float*)d_in[11];
    const float* tou_v_w    = (const float*)d_in[12];
    const float* tou_o_w    = (const float*)d_in[13];
    const float* tou_gate_w = (const float*)d_in[14];
    const float* tou_gate_b = (const float*)d_in[15];

    float *gx, *gxn, *gqkv, *gattn, *glogits, *gprobs, *gtopw, *gwcomb,
          *gpmean, *gbuf, *gh, *gyb, *gtq, *gtk, *gtv, *gtl, *gtout, *ggate;
    int *gtopi, *gslot, *gkeep, *gcounts;
    cudaGetSymbolAddress((void**)&gx, g_x);
    cudaGetSymbolAddress((void**)&gxn, g_xn);
    cudaGetSymbolAddress((void**)&gqkv, g_qkv);
    cudaGetSymbolAddress((void**)&gattn, g_attn);
    cudaGetSymbolAddress((void**)&glogits, g_logits);
    cudaGetSymbolAddress((void**)&gprobs, g_probs);
    cudaGetSymbolAddress((void**)&gtopi, g_topi);
    cudaGetSymbolAddress((void**)&gtopw, g_topw);
    cudaGetSymbolAddress((void**)&gslot, g_slot);
    cudaGetSymbolAddress((void**)&gkeep, g_keep);
    cudaGetSymbolAddress((void**)&gwcomb, g_wcomb);
    cudaGetSymbolAddress((void**)&gcounts, g_counts);
    cudaGetSymbolAddress((void**)&gpmean, g_pmean);
    cudaGetSymbolAddress((void**)&gbuf, g_buf);
    cudaGetSymbolAddress((void**)&gh, g_h);
    cudaGetSymbolAddress((void**)&gyb, g_yb);
    cudaGetSymbolAddress((void**)&gtq, g_tq);
    cudaGetSymbolAddress((void**)&gtk, g_tk);
    cudaGetSymbolAddress((void**)&gtv, g_tv);
    cudaGetSymbolAddress((void**)&gtl, g_tl);
    cudaGetSymbolAddress((void**)&gtout, g_tout);
    cudaGetSymbolAddress((void**)&ggate, g_gate);

    // residual stream
    cudaMemcpyAsync(gx, x, (size_t)NTOK*DD*sizeof(float), cudaMemcpyDeviceToDevice);

    // ---- Block 1: RoPE attention ----
    rmsnorm_kernel<<<NTOK, 256>>>(x, norm1_w, gxn);
    gemm128<true,0><<<dim3(3*DD/128, NTOK/128, 1), 256>>>(gxn, qkv_w, gqkv,
        NTOK, 3*DD, DD, 0, 0, 0, nullptr);
    rope_kernel<<<NTOK, 256>>>(gqkv);
    flash_attn_kernel<<<dim3(TT/64, BB*HH), 128>>>(gqkv, gattn);
    gemm128<true,1><<<dim3(DD/128, NTOK/128, 1), 256>>>(gattn, attn_o_w, gx,
        NTOK, DD, DD, 0, 0, 0, nullptr);

    // ---- Block 2: MoE ----
    rmsnorm_kernel<<<NTOK, 256>>>(gx, norm2_w, gxn);
    router_kernel<<<NTOK, 128>>>(gxn, router_w, glogits);
    top2_kernel<<<NTOK/128, 128>>>(glogits, gprobs, gtopi, gtopw);
    pmean_kernel<<<EE, 256>>>(gprobs, gpmean);
    assign_kernel<<<EE, 256>>>(gtopi, gtopw, gslot, gkeep, gwcomb, gcounts);
    cudaMemsetAsync(gbuf, 0, (size_t)EE*CAP*DD*sizeof(float));
    scatter_kernel<<<NFLAT, 256>>>(gtopi, gslot, gkeep, gxn, gbuf);
    gemm128<false,2><<<dim3(FF/128, CAP/128, EE), 256>>>(gbuf, moe_w1, gh,
        CAP, FF, DD, (long long)CAP*DD, (long long)DD*FF, (long long)CAP*FF, nullptr);
    gemm128<false,0><<<dim3(DD/128, CAP/128, EE), 256>>>(gh, moe_w2, gyb,
        CAP, DD, FF, (long long)CAP*FF, (long long)FF*DD, (long long)CAP*DD, nullptr);
    gather_kernel<<<NTOK, 256>>>(gtopi, gslot, gwcomb, gyb, gx);
    aux_kernel<<<1, 32>>>(gcounts, gpmean, (float*)d_out, out_size);

    // ---- Block 3: ToU cross-attention ----
    rmsnorm_kernel<<<NTOK, 256>>>(gx, norm3_w, gxn);
    gemm128<true,0><<<dim3(DP/128, NTOK/128, 1), 256>>>(gxn, tou_q_w, gtq,
        NTOK, DP, DD, 0, 0, 0, nullptr);
    gemm128<true,0><<<dim3(DP/128, NPRIM/128, 1), 256>>>(tou_embeds, tou_k_w, gtk,
        NPRIM, DP, DP, 0, 0, 0, nullptr);
    gemm128<true,0><<<dim3(DP/128, NPRIM/128, 1), 256>>>(tou_embeds, tou_v_w, gtv,
        NPRIM, DP, DP, 0, 0, 0, nullptr);
    gemm128<true,0><<<dim3(NPRIM/128, NTOK/128, 1), 256>>>(gtq, gtk, gtl,
        NTOK, NPRIM, DP, 0, 0, 0, nullptr);
    softmax512_kernel<<<NTOK, 256>>>(gtl);
    gemm128<false,0><<<dim3(DP/128, NTOK/128, 1), 256>>>(gtl, gtv, gtout,
        NTOK, DP, NPRIM, 0, 0, 0, nullptr);
    gate_kernel<<<NTOK, 256>>>(gxn, tou_gate_w, tou_gate_b, ggate);
    gemm128<true,3><<<dim3(DD/128, NTOK/128, 1), 256>>>(gtout, tou_o_w, gx,
        NTOK, DD, DP, 0, 0, 0, ggate);

    // output
    cudaMemcpyAsync(d_out, gx, (size_t)NTOK*DD*sizeof(float), cudaMemcpyDeviceToDevice);
}

// round 2
// speedup vs baseline: 1.9613x; 1.9613x over previous
#include <cuda_runtime.h>
#include <cuda_bf16.h>
#include <math.h>

// ---------------------------------------------------------------------------
// Problem constants
// ---------------------------------------------------------------------------
#define BB 2
#define TT 2048
#define DD 1024
#define HH 16
#define DH 64
#define NTOK (BB*TT)            // 4096
#define EE 16
#define KK 2
#define FF 2048
#define CAP 640
#define DP 256
#define NPRIM 512
#define NFLAT (NTOK*KK)         // 8192

// ---------------------------------------------------------------------------
// Scratch (device globals; no allocation allowed)
// ---------------------------------------------------------------------------
__device__ float g_x[NTOK*DD];
__device__ float g_xn[NTOK*DD];
__device__ float g_qkv[NTOK*3*DD];
__device__ float g_attn[NTOK*DD];
__device__ float g_logits[NTOK*EE];
__device__ float g_probs[NTOK*EE];
__device__ int   g_topi[NFLAT];
__device__ float g_topw[NFLAT];
__device__ int   g_slot[NFLAT];
__device__ int   g_keep[NFLAT];
__device__ float g_wcomb[NFLAT];
__device__ int   g_counts[EE];
__device__ float g_pmean[EE];
__device__ float g_buf[EE*CAP*DD];
__device__ float g_h[EE*CAP*FF];
__device__ float g_yb[EE*CAP*DD];
__device__ float g_tq[NTOK*DP];
__device__ float g_tk[NPRIM*DP];
__device__ float g_tv[NPRIM*DP];
__device__ float g_tl[NTOK*NPRIM];
__device__ float g_tout[NTOK*DP];
__device__ float g_gate[NTOK];

// ---------------------------------------------------------------------------
// RMSNorm: one block per token, 256 threads, float4
// ---------------------------------------------------------------------------
__global__ void rmsnorm_kernel(const float* __restrict__ x,
                               const float* __restrict__ w,
                               float* __restrict__ out)
{
    int n = blockIdx.x;
    int tid = threadIdx.x;
    const float4* xp = (const float4*)(x + (size_t)n*DD);
    float4 xv = xp[tid];
    float ss = xv.x*xv.x + xv.y*xv.y + xv.z*xv.z + xv.w*xv.w;
    __shared__ float red[256];
    red[tid] = ss;
    __syncthreads();
    for (int s = 128; s; s >>= 1) {
        if (tid < s) red[tid] += red[tid+s];
        __syncthreads();
    }
    float scale = rsqrtf(red[0] / (float)DD + 1e-6f);
    const float4* wp = (const float4*)w;
    float4 wv = wp[tid];
    float4* op = (float4*)(out + (size_t)n*DD);
    op[tid] = make_float4(xv.x*scale*wv.x, xv.y*scale*wv.y,
                          xv.z*scale*wv.z, xv.w*scale*wv.w);
}

// ---------------------------------------------------------------------------
// TF32 tensor-core GEMM, C[M,N] = A[M,K] * op(B)
//   BT=true : B stored [N,K] row-major (use B^T)
//   BT=false: B stored [K,N] row-major
// EPI: 0=store, 1=C+=, 2=silu store, 3=C += gate[row]*v
// blockIdx.z = batch, with strides (in elements)
// Tiles: block 128x128, BK=16; 8 warps, warp tile 64x32 via m16n8k8 MMA.
// Requires M%128==0, N%128==0, K%16==0.
// ---------------------------------------------------------------------------
__device__ __forceinline__ unsigned f2tf(float x)
{
    unsigned r;
    asm("cvt.rna.tf32.f32 %0, %1;" : "=r"(r) : "f"(x));
    return r;
}

__device__ __forceinline__ void mma_tf32(float c[4], const unsigned a[4], const unsigned b[2])
{
    asm volatile(
        "mma.sync.aligned.m16n8k8.row.col.f32.tf32.tf32.f32 "
        "{%0,%1,%2,%3},{%4,%5,%6,%7},{%8,%9},{%0,%1,%2,%3};"
        : "+f"(c[0]), "+f"(c[1]), "+f"(c[2]), "+f"(c[3])
        : "r"(a[0]), "r"(a[1]), "r"(a[2]), "r"(a[3]),
          "r"(b[0]), "r"(b[1]));
}

#define SM_STRIDE 136   // 16-float4-aligned, bank map 8*lq+lr => conflict-free frag loads

template<bool BT, int EPI>
__global__ __launch_bounds__(256, 2)
void gemm128(const float* __restrict__ A, const float* __restrict__ Bm,
             float* __restrict__ C, int M, int N, int K,
             long long sA, long long sB, long long sC,
             const float* __restrict__ gate)
{
    A  += blockIdx.z * sA;
    Bm += blockIdx.z * sB;
    C  += blockIdx.z * sC;
    __shared__ unsigned As[16][SM_STRIDE];
    __shared__ unsigned Bs[16][SM_STRIDE];

    const int tid  = threadIdx.x;
    const int lane = tid & 31;
    const int warp = tid >> 5;
    const int lr   = lane >> 2;      // 0..7
    const int lq   = lane & 3;       // 0..3
    const int wm   = warp & 1, wn = warp >> 1;
    const int m0   = wm * 64, n0 = wn * 32;
    const int row0 = blockIdx.y * 128, col0 = blockIdx.x * 128;

    // global-load assignments
    const int arow = tid >> 2;            // 0..63
    const int ak4  = (tid & 3) * 4;       // 0,4,8,12
    const int bkr  = tid >> 5;            // 0..7   (BT=false)
    const int bn4  = (tid & 31) * 4;      // 0..124 (BT=false)

    const float* Aptr = A + (size_t)(row0 + arow) * K + ak4;
    const float* Bptr = BT ? (Bm + (size_t)(col0 + arow) * K + ak4)
                           : (Bm + (size_t)bkr * N + col0 + bn4);

    float4 ra0, ra1, rb0, rb1;
    ra0 = *(const float4*)(Aptr);
    ra1 = *(const float4*)(Aptr + (size_t)64 * K);
    if (BT) {
        rb0 = *(const float4*)(Bptr);
        rb1 = *(const float4*)(Bptr + (size_t)64 * K);
    } else {
        rb0 = *(const float4*)(Bptr);
        rb1 = *(const float4*)(Bptr + (size_t)8 * N);
    }

    float c[4][4][4];
    #pragma unroll
    for (int mt = 0; mt < 4; mt++)
        #pragma unroll
        for (int nt = 0; nt < 4; nt++)
            #pragma unroll
            for (int i = 0; i < 4; i++) c[mt][nt][i] = 0.f;

    for (int k0 = 0; k0 < K; k0 += 16) {
        // stage current tile into smem (tf32-rounded)
        As[ak4+0][arow]    = f2tf(ra0.x);
        As[ak4+1][arow]    = f2tf(ra0.y);
        As[ak4+2][arow]    = f2tf(ra0.z);
        As[ak4+3][arow]    = f2tf(ra0.w);
        As[ak4+0][arow+64] = f2tf(ra1.x);
        As[ak4+1][arow+64] = f2tf(ra1.y);
        As[ak4+2][arow+64] = f2tf(ra1.z);
        As[ak4+3][arow+64] = f2tf(ra1.w);
        if (BT) {
            Bs[ak4+0][arow]    = f2tf(rb0.x);
            Bs[ak4+1][arow]    = f2tf(rb0.y);
            Bs[ak4+2][arow]    = f2tf(rb0.z);
            Bs[ak4+3][arow]    = f2tf(rb0.w);
            Bs[ak4+0][arow+64] = f2tf(rb1.x);
            Bs[ak4+1][arow+64] = f2tf(rb1.y);
            Bs[ak4+2][arow+64] = f2tf(rb1.z);
            Bs[ak4+3][arow+64] = f2tf(rb1.w);
        } else {
            uint4 u0 = make_uint4(f2tf(rb0.x), f2tf(rb0.y), f2tf(rb0.z), f2tf(rb0.w));
            uint4 u1 = make_uint4(f2tf(rb1.x), f2tf(rb1.y), f2tf(rb1.z), f2tf(rb1.w));
            *(uint4*)&Bs[bkr][bn4]     = u0;
            *(uint4*)&Bs[bkr+8][bn4]   = u1;
        }
        __syncthreads();

        // prefetch next tile
        if (k0 + 16 < K) {
            ra0 = *(const float4*)(Aptr + k0 + 16);
            ra1 = *(const float4*)(Aptr + (size_t)64 * K + k0 + 16);
            if (BT) {
                rb0 = *(const float4*)(Bptr + k0 + 16);
                rb1 = *(const float4*)(Bptr + (size_t)64 * K + k0 + 16);
            } else {
                rb0 = *(const float4*)(Bptr + (size_t)(k0 + 16) * N);
                rb1 = *(const float4*)(Bptr + (size_t)(k0 + 24) * N);
            }
        }

        // compute: two k8 steps
        #pragma unroll
        for (int ks = 0; ks < 2; ks++) {
            const int kb = ks * 8;
            unsigned a[4][4], b[4][2];
            #pragma unroll
            for (int mt = 0; mt < 4; mt++) {
                int r = m0 + mt * 16 + lr;
                a[mt][0] = As[kb + lq][r];
                a[mt][1] = As[kb + lq][r + 8];
                a[mt][2] = As[kb + 4 + lq][r];
                a[mt][3] = As[kb + 4 + lq][r + 8];
            }
            #pragma unroll
            for (int nt = 0; nt < 4; nt++) {
                int cn = n0 + nt * 8 + lr;
                b[nt][0] = Bs[kb + lq][cn];
                b[nt][1] = Bs[kb + 4 + lq][cn];
            }
            #pragma unroll
            for (int mt = 0; mt < 4; mt++)
                #pragma unroll
                for (int nt = 0; nt < 4; nt++)
                    mma_tf32(c[mt][nt], a[mt], b[nt]);
        }
        __syncthreads();
    }

    // epilogue
    #pragma unroll
    for (int mt = 0; mt < 4; mt++) {
        int r0g = row0 + m0 + mt * 16 + lr;
        int r1g = r0g + 8;
        float g0 = (EPI == 3) ? gate[r0g] : 0.f;
        float g1 = (EPI == 3) ? gate[r1g] : 0.f;
        #pragma unroll
        for (int nt = 0; nt < 4; nt++) {
            int cg = col0 + n0 + nt * 8 + 2 * lq;
            float* p0 = &C[(size_t)r0g * N + cg];
            float* p1 = &C[(size_t)r1g * N + cg];
            float v0 = c[mt][nt][0], v1 = c[mt][nt][1];
            float v2 = c[mt][nt][2], v3 = c[mt][nt][3];
            if (EPI == 0) {
                p0[0] = v0; p0[1] = v1; p1[0] = v2; p1[1] = v3;
            } else if (EPI == 1) {
                p0[0] += v0; p0[1] += v1; p1[0] += v2; p1[1] += v3;
            } else if (EPI == 2) {
                p0[0] = v0 / (1.f + __expf(-v0));
                p0[1] = v1 / (1.f + __expf(-v1));
                p1[0] = v2 / (1.f + __expf(-v2));
                p1[1] = v3 / (1.f + __expf(-v3));
            } else {
                p0[0] += g0 * v0; p0[1] += g0 * v1;
                p1[0] += g1 * v2; p1[1] += g1 * v3;
            }
        }
    }
}

// ---------------------------------------------------------------------------
// RoPE (NeoX-style), applied in place to q and k inside g_qkv
// ---------------------------------------------------------------------------
__global__ void rope_kernel(float* __restrict__ qkv)
{
    int n = blockIdx.x;           // token
    int t = n & (TT-1);
    for (int p = threadIdx.x; p < 1024; p += 256) {
        int which = p >> 9;       // 0=q, 1=k
        int rem = p & 511;
        int h = rem >> 5;
        int i = rem & 31;
        float inv = powf(10000.f, -(float)i / 32.f);
        float ang = (float)t * inv;
        float s, c;
        sincosf(ang, &s, &c);
        size_t base = (size_t)n*3072 + (size_t)which*1024 + h*64 + i;
        float u1 = qkv[base], u2 = qkv[base+32];
        qkv[base]    = u1*c - u2*s;
        qkv[base+32] = u2*c + u1*s;
    }
}

// ---------------------------------------------------------------------------
// Flash attention, causal. grid(32 qblocks, 32 bh), 128 threads.
// BQ=64 queries, key tiles of 32. Thread pair (2q,2q+1) owns one query row.
// ---------------------------------------------------------------------------
__global__ void flash_attn_kernel(const float* __restrict__ qkv,
                                  float* __restrict__ out)
{
    __shared__ float Qs[64][65];
    __shared__ float Ks[32][65];
    __shared__ float Vs[32][65];
    __shared__ float Ps[64][33];
    int qb = blockIdx.x;
    int bh = blockIdx.y;
    int b = bh >> 4, h = bh & 15;
    int tid = threadIdx.x;
    int qr = tid >> 1, half = tid & 1;
    int q0 = qb * 64;

    for (int i = tid; i < 64*64; i += 128) {
        int r = i >> 6, d = i & 63;
        Qs[r][d] = qkv[(size_t)(b*TT + q0 + r)*3072 + h*64 + d];
    }
    float m = -1e30f, l = 0.f;
    float o[32];
    #pragma unroll
    for (int i = 0; i < 32; i++) o[i] = 0.f;
    int qg = q0 + qr;
    int ntiles = 2 * (qb + 1);

    for (int kb = 0; kb < ntiles; kb++) {
        __syncthreads();
        for (int i = tid; i < 32*64; i += 128) {
            int r = i >> 6, d = i & 63;
            size_t base = (size_t)(b*TT + kb*32 + r)*3072 + h*64 + d;
            Ks[r][d] = qkv[base + 1024];
            Vs[r][d] = qkv[base + 2048];
        }
        __syncthreads();

        float s[16];
        #pragma unroll
        for (int j = 0; j < 16; j++) s[j] = 0.f;
        int c0 = half * 16;
        #pragma unroll
        for (int d0 = 0; d0 < 64; d0 += 8) {
            float q[8];
            #pragma unroll
            for (int dd = 0; dd < 8; dd++) q[dd] = Qs[qr][d0+dd];
            #pragma unroll
            for (int j = 0; j < 16; j++)
                #pragma unroll
                for (int dd = 0; dd < 8; dd++)
                    s[j] += q[dd] * Ks[c0+j][d0+dd];
        }
        float mymax = -1e30f;
        #pragma unroll
        for (int j = 0; j < 16; j++) {
            int kg = kb*32 + c0 + j;
            s[j] = (kg <= qg) ? s[j]*0.125f : -1e30f;
            mymax = fmaxf(mymax, s[j]);
        }
        float om = __shfl_xor_sync(0xffffffffu, mymax, 1);
        float m_new = fmaxf(m, fmaxf(mymax, om));
        float corr = __expf(m - m_new);
        float rs = 0.f;
        #pragma unroll
        for (int j = 0; j < 16; j++) {
            float p = __expf(s[j] - m_new);
            s[j] = p; rs += p;
        }
        rs += __shfl_xor_sync(0xffffffffu, rs, 1);
        l = l*corr + rs;
        #pragma unroll
        for (int i = 0; i < 32; i++) o[i] *= corr;
        #pragma unroll
        for (int j = 0; j < 16; j++) Ps[qr][c0+j] = s[j];
        m = m_new;
        __syncthreads();
        #pragma unroll
        for (int j = 0; j < 32; j++) {
            float p = Ps[qr][j];
            #pragma unroll
            for (int i = 0; i < 32; i++)
                o[i] += p * Vs[j][half*32 + i];
        }
    }
    float inv = 1.f / l;
    #pragma unroll
    for (int i = 0; i < 32; i++)
        out[(size_t)(b*TT + qg)*DD + h*64 + half*32 + i] = o[i]*inv;
}

// ---------------------------------------------------------------------------
// Router logits: block per token (128 thr, 4 warps x 4 experts)
// ---------------------------------------------------------------------------
__global__ void router_kernel(const float* __restrict__ xn,
                              const float* __restrict__ rw,
                              float* __restrict__ logits)
{
    int n = blockIdx.x;
    int warp = threadIdx.x >> 5, lane = threadIdx.x & 31;
    const float* xp = xn + (size_t)n*DD;
    for (int j = 0; j < 4; j++) {
        int e = warp*4 + j;
        const float* wp = rw + (size_t)e*DD;
        float s = 0.f;
        for (int i = lane; i < DD; i += 32) s += xp[i]*wp[i];
        #pragma unroll
        for (int off = 16; off; off >>= 1) s += __shfl_xor_sync(0xffffffffu, s, off);
        if (lane == 0) logits[n*EE + e] = s;
    }
}

// ---------------------------------------------------------------------------
// Softmax over 16 experts + top-2 (ties: lowest index, matching lax.top_k)
// ---------------------------------------------------------------------------
__global__ void top2_kernel(const float* __restrict__ logits,
                            float* __restrict__ probs,
                            int* __restrict__ topi, float* __restrict__ topw)
{
    int n = blockIdx.x*blockDim.x + threadIdx.x;
    if (n >= NTOK) return;
    float l[EE];
    float mx = -1e30f;
    #pragma unroll
    for (int e = 0; e < EE; e++) { l[e] = logits[n*EE+e]; mx = fmaxf(mx, l[e]); }
    float sum = 0.f;
    #pragma unroll
    for (int e = 0; e < EE; e++) { l[e] = __expf(l[e]-mx); sum += l[e]; }
    float inv = 1.f/sum;
    #pragma unroll
    for (int e = 0; e < EE; e++) { l[e] *= inv; probs[n*EE+e] = l[e]; }
    int i0 = 0; float p0 = l[0];
    #pragma unroll
    for (int e = 1; e < EE; e++) if (l[e] > p0) { p0 = l[e]; i0 = e; }
    int i1 = (i0 == 0) ? 1 : 0; float p1 = l[i1];
    #pragma unroll
    for (int e = 0; e < EE; e++) if (e != i0 && l[e] > p1) { p1 = l[e]; i1 = e; }
    float ws = p0 + p1;
    topi[n*2]   = i0; topi[n*2+1] = i1;
    topw[n*2]   = p0/ws; topw[n*2+1] = p1/ws;
}

// ---------------------------------------------------------------------------
// Deterministic pmean reduction (16 blocks, fixed tree)
// ---------------------------------------------------------------------------
__global__ void pmean_kernel(const float* __restrict__ probs, float* __restrict__ pmean)
{
    int e = blockIdx.x, tid = threadIdx.x;
    float s = 0.f;
    for (int t = tid; t < NTOK; t += 256) s += probs[t*EE + e];
    __shared__ float red[256];
    red[tid] = s;
    __syncthreads();
    for (int k = 128; k; k >>= 1) {
        if (tid < k) red[tid] += red[tid+k];
        __syncthreads();
    }
    if (tid == 0) pmean[e] = red[0] / (float)NTOK;
}

// ---------------------------------------------------------------------------
// Capacity position assignment: 16 blocks (one per expert), ballot scan over
// the flat assignment list in order (deterministic, matches cumsum).
// ---------------------------------------------------------------------------
__global__ void assign_kernel(const int* __restrict__ topi,
                              const float* __restrict__ topw,
                              int* __restrict__ slot, int* __restrict__ keep,
                              float* __restrict__ wcomb, int* __restrict__ counts)
{
    int e = blockIdx.x;
    int tid = threadIdx.x;            // 256
    int lane = tid & 31, warp = tid >> 5;
    __shared__ int warpsum[8];
    int running = 0;
    for (int base = 0; base < NFLAT; base += 256) {
        int i = base + tid;
        int match = (topi[i] == e) ? 1 : 0;
        unsigned mask = __ballot_sync(0xffffffffu, match);
        if (lane == 0) warpsum[warp] = __popc(mask);
        __syncthreads();
        int wbase = 0, tot = 0;
        #pragma unroll
        for (int w = 0; w < 8; w++) {
            int c = warpsum[w];
            if (w < warp) wbase += c;
            tot += c;
        }
        if (match) {
            int pos = running + wbase + __popc(mask & ((1u << lane) - 1u));
            int kp = (pos < CAP) ? 1 : 0;
            slot[i]  = (pos < CAP-1) ? pos : (CAP-1);
            keep[i]  = kp;
            wcomb[i] = kp ? topw[i] : 0.f;
        }
        running += tot;
        __syncthreads();
    }
    if (tid == 0) counts[e] = running;
}

// ---------------------------------------------------------------------------
// Scatter tokens into expert buffers (each kept (e,slot) unique)
// ---------------------------------------------------------------------------
__global__ void scatter_kernel(const int* __restrict__ topi,
                               const int* __restrict__ slot,
                               const int* __restrict__ keep,
                               const float* __restrict__ xn,
                               float* __restrict__ buf)
{
    int i = blockIdx.x;
    if (!keep[i]) return;
    int e = topi[i], s = slot[i], tok = i >> 1;
    const float4* src = (const float4*)(xn + (size_t)tok*DD);
    float4* dst = (float4*)(buf + ((size_t)e*CAP + s)*DD);
    dst[threadIdx.x] = src[threadIdx.x];
}

// ---------------------------------------------------------------------------
// Gather expert outputs + residual into x
// ---------------------------------------------------------------------------
__global__ void gather_kernel(const int* __restrict__ topi,
                              const int* __restrict__ slot,
                              const float* __restrict__ wcomb,
                              const float* __restrict__ yb,
                              float* __restrict__ x)
{
    int n = blockIdx.x;
    int t4 = threadIdx.x;
    float4* xp = (float4*)(x + (size_t)n*DD);
    float4 a = xp[t4];
    #pragma unroll
    for (int k = 0; k < 2; k++) {
        int i = n*2 + k;
        float w = wcomb[i];
        if (w != 0.f) {
            int e = topi[i], s = slot[i];
            const float4* yp = (const float4*)(yb + ((size_t)e*CAP + s)*DD);
            float4 yv = yp[t4];
            a.x += w*yv.x; a.y += w*yv.y; a.z += w*yv.z; a.w += w*yv.w;
        }
    }
    xp[t4] = a;
}

// ---------------------------------------------------------------------------
// aux = E * sum(frac * pmean); written at d_out[B*T*D]
// ---------------------------------------------------------------------------
__global__ void aux_kernel(const int* __restrict__ counts,
                           const float* __restrict__ pmean,
                           float* __restrict__ out, int out_size)
{
    if (threadIdx.x == 0 && out_size > NTOK*DD) {
        float s = 0.f;
        for (int e = 0; e < EE; e++)
            s += ((float)counts[e] / (float)NTOK) * pmean[e];
        out[NTOK*DD] = (float)EE * s;
    }
}

// ---------------------------------------------------------------------------
// ToU gate: sigmoid(xn . gw + gb) per token
// ---------------------------------------------------------------------------
__global__ void gate_kernel(const float* __restrict__ xn,
                            const float* __restrict__ gw,
                            const float* __restrict__ gb,
                            float* __restrict__ gate)
{
    int n = blockIdx.x, tid = threadIdx.x;
    const float4* xp = (const float4*)(xn + (size_t)n*DD);
    const float4* wp = (const float4*)gw;
    float4 xv = xp[tid], wv = wp[tid];
    float s = xv.x*wv.x + xv.y*wv.y + xv.z*wv.z + xv.w*wv.w;
    __shared__ float red[256];
    red[tid] = s;
    __syncthreads();
    for (int k = 128; k; k >>= 1) {
        if (tid < k) red[tid] += red[tid+k];
        __syncthreads();
    }
    if (tid == 0) gate[n] = 1.f / (1.f + __expf(-(red[0] + gb[0])));
}

// ---------------------------------------------------------------------------
// Softmax over 512 primitives (scale 1/16 folded in), in place
// ---------------------------------------------------------------------------
__global__ void softmax512_kernel(float* __restrict__ tl)
{
    int n = blockIdx.x, tid = threadIdx.x;
    float* row = tl + (size_t)n*NPRIM;
    float v0 = row[tid]       * 0.0625f;
    float v1 = row[tid + 256] * 0.0625f;
    __shared__ float red[256];
    red[tid] = fmaxf(v0, v1);
    __syncthreads();
    for (int s = 128; s; s >>= 1) {
        if (tid < s) red[tid] = fmaxf(red[tid], red[tid+s]);
        __syncthreads();
    }
    float mx = red[0];
    __syncthreads();
    v0 = __expf(v0 - mx); v1 = __expf(v1 - mx);
    red[tid] = v0 + v1;
    __syncthreads();
    for (int s = 128; s; s >>= 1) {
        if (tid < s) red[tid] += red[tid+s];
        __syncthreads();
    }
    float inv = 1.f / red[0];
    row[tid] = v0*inv; row[tid+256] = v1*inv;
}

// ---------------------------------------------------------------------------
// Host launch
// ---------------------------------------------------------------------------
extern "C" void kernel_launch(void* const* d_in, const int* in_sizes, int n_in,
                              void* d_out, int out_size)
{
    const float* x          = (const float*)d_in[0];
    const float* tou_embeds = (const float*)d_in[1];
    const float* norm1_w    = (const float*)d_in[2];
    const float* qkv_w      = (const float*)d_in[3];
    const float* attn_o_w   = (const float*)d_in[4];
    const float* norm2_w    = (const float*)d_in[5];
    const float* router_w   = (const float*)d_in[6];
    const float* moe_w1     = (const float*)d_in[7];
    const float* moe_w2     = (const float*)d_in[8];
    const float* norm3_w    = (const float*)d_in[9];
    const float* tou_q_w    = (const float*)d_in[10];
    const float* tou_k_w    = (const float*)d_in[11];
    const float* tou_v_w    = (const float*)d_in[12];
    const float* tou_o_w    = (const float*)d_in[13];
    const float* tou_gate_w = (const float*)d_in[14];
    const float* tou_gate_b = (const float*)d_in[15];

    float *gx, *gxn, *gqkv, *gattn, *glogits, *gprobs, *gtopw, *gwcomb,
          *gpmean, *gbuf, *gh, *gyb, *gtq, *gtk, *gtv, *gtl, *gtout, *ggate;
    int *gtopi, *gslot, *gkeep, *gcounts;
    cudaGetSymbolAddress((void**)&gx, g_x);
    cudaGetSymbolAddress((void**)&gxn, g_xn);
    cudaGetSymbolAddress((void**)&gqkv, g_qkv);
    cudaGetSymbolAddress((void**)&gattn, g_attn);
    cudaGetSymbolAddress((void**)&glogits, g_logits);
    cudaGetSymbolAddress((void**)&gprobs, g_probs);
    cudaGetSymbolAddress((void**)&gtopi, g_topi);
    cudaGetSymbolAddress((void**)&gtopw, g_topw);
    cudaGetSymbolAddress((void**)&gslot, g_slot);
    cudaGetSymbolAddress((void**)&gkeep, g_keep);
    cudaGetSymbolAddress((void**)&gwcomb, g_wcomb);
    cudaGetSymbolAddress((void**)&gcounts, g_counts);
    cudaGetSymbolAddress((void**)&gpmean, g_pmean);
    cudaGetSymbolAddress((void**)&gbuf, g_buf);
    cudaGetSymbolAddress((void**)&gh, g_h);
    cudaGetSymbolAddress((void**)&gyb, g_yb);
    cudaGetSymbolAddress((void**)&gtq, g_tq);
    cudaGetSymbolAddress((void**)&gtk, g_tk);
    cudaGetSymbolAddress((void**)&gtv, g_tv);
    cudaGetSymbolAddress((void**)&gtl, g_tl);
    cudaGetSymbolAddress((void**)&gtout, g_tout);
    cudaGetSymbolAddress((void**)&ggate, g_gate);

    // residual stream
    cudaMemcpyAsync(gx, x, (size_t)NTOK*DD*sizeof(float), cudaMemcpyDeviceToDevice);

    // ---- Block 1: RoPE attention ----
    rmsnorm_kernel<<<NTOK, 256>>>(x, norm1_w, gxn);
    gemm128<true,0><<<dim3(3*DD/128, NTOK/128, 1), 256>>>(gxn, qkv_w, gqkv,
        NTOK, 3*DD, DD, 0, 0, 0, nullptr);
    rope_kernel<<<NTOK, 256>>>(gqkv);
    flash_attn_kernel<<<dim3(TT/64, BB*HH), 128>>>(gqkv, gattn);
    gemm128<true,1><<<dim3(DD/128, NTOK/128, 1), 256>>>(gattn, attn_o_w, gx,
        NTOK, DD, DD, 0, 0, 0, nullptr);

    // ---- Block 2: MoE ----
    rmsnorm_kernel<<<NTOK, 256>>>(gx, norm2_w, gxn);
    router_kernel<<<NTOK, 128>>>(gxn, router_w, glogits);
    top2_kernel<<<NTOK/128, 128>>>(glogits, gprobs, gtopi, gtopw);
    pmean_kernel<<<EE, 256>>>(gprobs, gpmean);
    assign_kernel<<<EE, 256>>>(gtopi, gtopw, gslot, gkeep, gwcomb, gcounts);
    cudaMemsetAsync(gbuf, 0, (size_t)EE*CAP*DD*sizeof(float));
    scatter_kernel<<<NFLAT, 256>>>(gtopi, gslot, gkeep, gxn, gbuf);
    gemm128<false,2><<<dim3(FF/128, CAP/128, EE), 256>>>(gbuf, moe_w1, gh,
        CAP, FF, DD, (long long)CAP*DD, (long long)DD*FF, (long long)CAP*FF, nullptr);
    gemm128<false,0><<<dim3(DD/128, CAP/128, EE), 256>>>(gh, moe_w2, gyb,
        CAP, DD, FF, (long long)CAP*FF, (long long)FF*DD, (long long)CAP*DD, nullptr);
    gather_kernel<<<NTOK, 256>>>(gtopi, gslot, gwcomb, gyb, gx);
    aux_kernel<<<1, 32>>>(gcounts, gpmean, (float*)d_out, out_size);

    // ---- Block 3: ToU cross-attention ----
    rmsnorm_kernel<<<NTOK, 256>>>(gx, norm3_w, gxn);
    gemm128<true,0><<<dim3(DP/128, NTOK/128, 1), 256>>>(gxn, tou_q_w, gtq,
        NTOK, DP, DD, 0, 0, 0, nullptr);
    gemm128<true,0><<<dim3(DP/128, NPRIM/128, 1), 256>>>(tou_embeds, tou_k_w, gtk,
        NPRIM, DP, DP, 0, 0, 0, nullptr);
    gemm128<true,0><<<dim3(DP/128, NPRIM/128, 1), 256>>>(tou_embeds, tou_v_w, gtv,
        NPRIM, DP, DP, 0, 0, 0, nullptr);
    gemm128<true,0><<<dim3(NPRIM/128, NTOK/128, 1), 256>>>(gtq, gtk, gtl,
        NTOK, NPRIM, DP, 0, 0, 0, nullptr);
    softmax512_kernel<<<NTOK, 256>>>(gtl);
    gemm128<false,0><<<dim3(DP/128, NTOK/128, 1), 256>>>(gtl, gtv, gtout,
        NTOK, DP, NPRIM, 0, 0, 0, nullptr);
    gate_kernel<<<NTOK, 256>>>(gxn, tou_gate_w, tou_gate_b, ggate);
    gemm128<true,3><<<dim3(DD/128, NTOK/128, 1), 256>>>(gtout, tou_o_w, gx,
        NTOK, DD, DP, 0, 0, 0, ggate);

    // output
    cudaMemcpyAsync(d_out, gx, (size_t)NTOK*DD*sizeof(float), cudaMemcpyDeviceToDevice);
}

// round 3
// speedup vs baseline: 2.8382x; 1.4471x over previous
#include <cuda_runtime.h>
#include <cuda_bf16.h>
#include <math.h>

// ---------------------------------------------------------------------------
// Problem constants
// ---------------------------------------------------------------------------
#define BB 2
#define TT 2048
#define DD 1024
#define HH 16
#define DH 64
#define NTOK (BB*TT)            // 4096
#define EE 16
#define KK 2
#define FF 2048
#define CAP 640
#define DP 256
#define NPRIM 512
#define NFLAT (NTOK*KK)         // 8192

// ---------------------------------------------------------------------------
// Scratch (device globals; no allocation allowed)
// ---------------------------------------------------------------------------
__device__ float g_x[NTOK*DD];
__device__ float g_xn[NTOK*DD];
__device__ float g_qkv[NTOK*3*DD];
__device__ float g_attn[NTOK*DD];
__device__ float g_logits[NTOK*EE];
__device__ float g_probs[NTOK*EE];
__device__ int   g_topi[NFLAT];
__device__ float g_topw[NFLAT];
__device__ int   g_slot[NFLAT];
__device__ int   g_keep[NFLAT];
__device__ float g_wcomb[NFLAT];
__device__ int   g_counts[EE];
__device__ float g_pmean[EE];
__device__ float g_buf[EE*CAP*DD];
__device__ float g_h[EE*CAP*FF];
__device__ float g_yb[EE*CAP*DD];
__device__ float g_tq[NTOK*DP];
__device__ float g_tk[NPRIM*DP];
__device__ float g_tv[NPRIM*DP];
__device__ float g_tl[NTOK*NPRIM];
__device__ float g_tout[NTOK*DP];
__device__ float g_gate[NTOK];

// ---------------------------------------------------------------------------
// TF32 helpers
// ---------------------------------------------------------------------------
__device__ __forceinline__ unsigned f2tf(float x)
{
    unsigned r;
    asm("cvt.rna.tf32.f32 %0, %1;" : "=r"(r) : "f"(x));
    return r;
}

__device__ __forceinline__ void mma_tf32(float c[4], const unsigned a[4], const unsigned b[2])
{
    asm volatile(
        "mma.sync.aligned.m16n8k8.row.col.f32.tf32.tf32.f32 "
        "{%0,%1,%2,%3},{%4,%5,%6,%7},{%8,%9},{%0,%1,%2,%3};"
        : "+f"(c[0]), "+f"(c[1]), "+f"(c[2]), "+f"(c[3])
        : "r"(a[0]), "r"(a[1]), "r"(a[2]), "r"(a[3]),
          "r"(b[0]), "r"(b[1]));
}

// ---------------------------------------------------------------------------
// RMSNorm: one block per token, 256 threads, float4
// ---------------------------------------------------------------------------
__global__ void rmsnorm_kernel(const float* __restrict__ x,
                               const float* __restrict__ w,
                               float* __restrict__ out)
{
    int n = blockIdx.x;
    int tid = threadIdx.x;
    const float4* xp = (const float4*)(x + (size_t)n*DD);
    float4 xv = xp[tid];
    float ss = xv.x*xv.x + xv.y*xv.y + xv.z*xv.z + xv.w*xv.w;
    __shared__ float red[256];
    red[tid] = ss;
    __syncthreads();
    for (int s = 128; s; s >>= 1) {
        if (tid < s) red[tid] += red[tid+s];
        __syncthreads();
    }
    float scale = rsqrtf(red[0] / (float)DD + 1e-6f);
    const float4* wp = (const float4*)w;
    float4 wv = wp[tid];
    float4* op = (float4*)(out + (size_t)n*DD);
    op[tid] = make_float4(xv.x*scale*wv.x, xv.y*scale*wv.y,
                          xv.z*scale*wv.z, xv.w*scale*wv.w);
}

// ---------------------------------------------------------------------------
// TF32 tensor-core GEMM, C[M,N] = A[M,K] * op(B)   (same as R1)
// ---------------------------------------------------------------------------
#define SM_STRIDE 136

template<bool BT, int EPI>
__global__ __launch_bounds__(256, 2)
void gemm128(const float* __restrict__ A, const float* __restrict__ Bm,
             float* __restrict__ C, int M, int N, int K,
             long long sA, long long sB, long long sC,
             const float* __restrict__ gate)
{
    A  += blockIdx.z * sA;
    Bm += blockIdx.z * sB;
    C  += blockIdx.z * sC;
    __shared__ unsigned As[16][SM_STRIDE];
    __shared__ unsigned Bs[16][SM_STRIDE];

    const int tid  = threadIdx.x;
    const int lane = tid & 31;
    const int warp = tid >> 5;
    const int lr   = lane >> 2;
    const int lq   = lane & 3;
    const int wm   = warp & 1, wn = warp >> 1;
    const int m0   = wm * 64, n0 = wn * 32;
    const int row0 = blockIdx.y * 128, col0 = blockIdx.x * 128;

    const int arow = tid >> 2;
    const int ak4  = (tid & 3) * 4;
    const int bkr  = tid >> 5;
    const int bn4  = (tid & 31) * 4;

    const float* Aptr = A + (size_t)(row0 + arow) * K + ak4;
    const float* Bptr = BT ? (Bm + (size_t)(col0 + arow) * K + ak4)
                           : (Bm + (size_t)bkr * N + col0 + bn4);

    float4 ra0, ra1, rb0, rb1;
    ra0 = *(const float4*)(Aptr);
    ra1 = *(const float4*)(Aptr + (size_t)64 * K);
    if (BT) {
        rb0 = *(const float4*)(Bptr);
        rb1 = *(const float4*)(Bptr + (size_t)64 * K);
    } else {
        rb0 = *(const float4*)(Bptr);
        rb1 = *(const float4*)(Bptr + (size_t)8 * N);
    }

    float c[4][4][4];
    #pragma unroll
    for (int mt = 0; mt < 4; mt++)
        #pragma unroll
        for (int nt = 0; nt < 4; nt++)
            #pragma unroll
            for (int i = 0; i < 4; i++) c[mt][nt][i] = 0.f;

    for (int k0 = 0; k0 < K; k0 += 16) {
        As[ak4+0][arow]    = f2tf(ra0.x);
        As[ak4+1][arow]    = f2tf(ra0.y);
        As[ak4+2][arow]    = f2tf(ra0.z);
        As[ak4+3][arow]    = f2tf(ra0.w);
        As[ak4+0][arow+64] = f2tf(ra1.x);
        As[ak4+1][arow+64] = f2tf(ra1.y);
        As[ak4+2][arow+64] = f2tf(ra1.z);
        As[ak4+3][arow+64] = f2tf(ra1.w);
        if (BT) {
            Bs[ak4+0][arow]    = f2tf(rb0.x);
            Bs[ak4+1][arow]    = f2tf(rb0.y);
            Bs[ak4+2][arow]    = f2tf(rb0.z);
            Bs[ak4+3][arow]    = f2tf(rb0.w);
            Bs[ak4+0][arow+64] = f2tf(rb1.x);
            Bs[ak4+1][arow+64] = f2tf(rb1.y);
            Bs[ak4+2][arow+64] = f2tf(rb1.z);
            Bs[ak4+3][arow+64] = f2tf(rb1.w);
        } else {
            uint4 u0 = make_uint4(f2tf(rb0.x), f2tf(rb0.y), f2tf(rb0.z), f2tf(rb0.w));
            uint4 u1 = make_uint4(f2tf(rb1.x), f2tf(rb1.y), f2tf(rb1.z), f2tf(rb1.w));
            *(uint4*)&Bs[bkr][bn4]     = u0;
            *(uint4*)&Bs[bkr+8][bn4]   = u1;
        }
        __syncthreads();

        if (k0 + 16 < K) {
            ra0 = *(const float4*)(Aptr + k0 + 16);
            ra1 = *(const float4*)(Aptr + (size_t)64 * K + k0 + 16);
            if (BT) {
                rb0 = *(const float4*)(Bptr + k0 + 16);
                rb1 = *(const float4*)(Bptr + (size_t)64 * K + k0 + 16);
            } else {
                rb0 = *(const float4*)(Bptr + (size_t)(k0 + 16) * N);
                rb1 = *(const float4*)(Bptr + (size_t)(k0 + 24) * N);
            }
        }

        #pragma unroll
        for (int ks = 0; ks < 2; ks++) {
            const int kb = ks * 8;
            unsigned a[4][4], b[4][2];
            #pragma unroll
            for (int mt = 0; mt < 4; mt++) {
                int r = m0 + mt * 16 + lr;
                a[mt][0] = As[kb + lq][r];
                a[mt][1] = As[kb + lq][r + 8];
                a[mt][2] = As[kb + 4 + lq][r];
                a[mt][3] = As[kb + 4 + lq][r + 8];
            }
            #pragma unroll
            for (int nt = 0; nt < 4; nt++) {
                int cn = n0 + nt * 8 + lr;
                b[nt][0] = Bs[kb + lq][cn];
                b[nt][1] = Bs[kb + 4 + lq][cn];
            }
            #pragma unroll
            for (int mt = 0; mt < 4; mt++)
                #pragma unroll
                for (int nt = 0; nt < 4; nt++)
                    mma_tf32(c[mt][nt], a[mt], b[nt]);
        }
        __syncthreads();
    }

    #pragma unroll
    for (int mt = 0; mt < 4; mt++) {
        int r0g = row0 + m0 + mt * 16 + lr;
        int r1g = r0g + 8;
        float g0 = (EPI == 3) ? gate[r0g] : 0.f;
        float g1 = (EPI == 3) ? gate[r1g] : 0.f;
        #pragma unroll
        for (int nt = 0; nt < 4; nt++) {
            int cg = col0 + n0 + nt * 8 + 2 * lq;
            float* p0 = &C[(size_t)r0g * N + cg];
            float* p1 = &C[(size_t)r1g * N + cg];
            float v0 = c[mt][nt][0], v1 = c[mt][nt][1];
            float v2 = c[mt][nt][2], v3 = c[mt][nt][3];
            if (EPI == 0) {
                p0[0] = v0; p0[1] = v1; p1[0] = v2; p1[1] = v3;
            } else if (EPI == 1) {
                p0[0] += v0; p0[1] += v1; p1[0] += v2; p1[1] += v3;
            } else if (EPI == 2) {
                p0[0] = v0 / (1.f + __expf(-v0));
                p0[1] = v1 / (1.f + __expf(-v1));
                p1[0] = v2 / (1.f + __expf(-v2));
                p1[1] = v3 / (1.f + __expf(-v3));
            } else {
                p0[0] += g0 * v0; p0[1] += g0 * v1;
                p1[0] += g1 * v2; p1[1] += g1 * v3;
            }
        }
    }
}

// ---------------------------------------------------------------------------
// RoPE (NeoX-style), applied in place to q and k inside g_qkv
// ---------------------------------------------------------------------------
__global__ void rope_kernel(float* __restrict__ qkv)
{
    int n = blockIdx.x;
    int t = n & (TT-1);
    for (int p = threadIdx.x; p < 1024; p += 256) {
        int which = p >> 9;
        int rem = p & 511;
        int h = rem >> 5;
        int i = rem & 31;
        float inv = powf(10000.f, -(float)i / 32.f);
        float ang = (float)t * inv;
        float s, c;
        sincosf(ang, &s, &c);
        size_t base = (size_t)n*3072 + (size_t)which*1024 + h*64 + i;
        float u1 = qkv[base], u2 = qkv[base+32];
        qkv[base]    = u1*c - u2*s;
        qkv[base+32] = u2*c + u1*s;
    }
}

// ---------------------------------------------------------------------------
// Tensor-core flash attention, causal. TF32 m16n8k8.
// grid(32 qblocks, 32 bh), 128 threads (4 warps), BQ=64 (16 rows/warp), BK=32.
// S = Q K^T via MMA; online softmax on fragments; P through smem; PV via MMA
// with V staged transposed.
// ---------------------------------------------------------------------------
#define QS_STR 68
#define VS_STR 36
#define PS_STR 36

__global__ __launch_bounds__(128)
void flash_attn_tc(const float* __restrict__ qkv, float* __restrict__ out)
{
    __shared__ unsigned Qs[64][QS_STR];
    __shared__ unsigned Ks[32][QS_STR];
    __shared__ unsigned Vts[64][VS_STR];   // [dh][key]
    __shared__ unsigned Ps[64][PS_STR];

    const int qb = blockIdx.x, bh = blockIdx.y;
    const int b = bh >> 4, h = bh & 15;
    const int tid = threadIdx.x, lane = tid & 31, warp = tid >> 5;
    const int lr = lane >> 2, lq = lane & 3;
    const int m0 = warp * 16;
    const int q0 = qb * 64;

    // load Q (fold in 1/sqrt(dh) = 0.125)
    for (int i = tid; i < 64*64; i += 128) {
        int r = i >> 6, d = i & 63;
        Qs[r][d] = f2tf(qkv[(size_t)(b*TT + q0 + r)*3072 + h*64 + d] * 0.125f);
    }

    float mrow0 = -1e30f, mrow1 = -1e30f;
    float lrow0 = 0.f,    lrow1 = 0.f;
    float o[8][4];
    #pragma unroll
    for (int nt = 0; nt < 8; nt++)
        #pragma unroll
        for (int i = 0; i < 4; i++) o[nt][i] = 0.f;

    const int rg0 = q0 + m0 + lr, rg1 = rg0 + 8;
    const int ntiles = 2*qb + 2;

    for (int kb = 0; kb < ntiles; kb++) {
        __syncthreads();
        for (int i = tid; i < 32*64; i += 128) {
            int r = i >> 6, d = i & 63;
            size_t base = (size_t)(b*TT + kb*32 + r)*3072 + h*64 + d;
            Ks[r][d]  = f2tf(qkv[base + 1024]);
            Vts[d][r] = f2tf(qkv[base + 2048]);
        }
        __syncthreads();

        // ---- S = Q K^T ----
        float s[4][4];
        #pragma unroll
        for (int nt = 0; nt < 4; nt++)
            #pragma unroll
            for (int i = 0; i < 4; i++) s[nt][i] = 0.f;
        #pragma unroll
        for (int kk = 0; kk < 8; kk++) {
            unsigned a[4];
            a[0] = Qs[m0+lr][kk*8+lq];
            a[1] = Qs[m0+lr+8][kk*8+lq];
            a[2] = Qs[m0+lr][kk*8+lq+4];
            a[3] = Qs[m0+lr+8][kk*8+lq+4];
            #pragma unroll
            for (int nt = 0; nt < 4; nt++) {
                unsigned bf[2] = { Ks[nt*8+lr][kk*8+lq], Ks[nt*8+lr][kk*8+lq+4] };
                mma_tf32(s[nt], a, bf);
            }
        }

        // ---- causal mask (only last two tiles can clip) ----
        if (kb >= 2*qb) {
            #pragma unroll
            for (int nt = 0; nt < 4; nt++) {
                int c0 = kb*32 + nt*8 + 2*lq;
                if (c0   > rg0) s[nt][0] = -1e30f;
                if (c0+1 > rg0) s[nt][1] = -1e30f;
                if (c0   > rg1) s[nt][2] = -1e30f;
                if (c0+1 > rg1) s[nt][3] = -1e30f;
            }
        }

        // ---- online softmax (rows spread over quad lanes) ----
        float mx0 = -1e30f, mx1 = -1e30f;
        #pragma unroll
        for (int nt = 0; nt < 4; nt++) {
            mx0 = fmaxf(mx0, fmaxf(s[nt][0], s[nt][1]));
            mx1 = fmaxf(mx1, fmaxf(s[nt][2], s[nt][3]));
        }
        mx0 = fmaxf(mx0, __shfl_xor_sync(0xffffffffu, mx0, 1));
        mx0 = fmaxf(mx0, __shfl_xor_sync(0xffffffffu, mx0, 2));
        mx1 = fmaxf(mx1, __shfl_xor_sync(0xffffffffu, mx1, 1));
        mx1 = fmaxf(mx1, __shfl_xor_sync(0xffffffffu, mx1, 2));
        float mn0 = fmaxf(mrow0, mx0), mn1 = fmaxf(mrow1, mx1);
        float corr0 = __expf(mrow0 - mn0), corr1 = __expf(mrow1 - mn1);
        float sum0 = 0.f, sum1 = 0.f;
        #pragma unroll
        for (int nt = 0; nt < 4; nt++) {
            s[nt][0] = __expf(s[nt][0] - mn0);
            s[nt][1] = __expf(s[nt][1] - mn0);
            s[nt][2] = __expf(s[nt][2] - mn1);
            s[nt][3] = __expf(s[nt][3] - mn1);
            sum0 += s[nt][0] + s[nt][1];
            sum1 += s[nt][2] + s[nt][3];
        }
        sum0 += __shfl_xor_sync(0xffffffffu, sum0, 1);
        sum0 += __shfl_xor_sync(0xffffffffu, sum0, 2);
        sum1 += __shfl_xor_sync(0xffffffffu, sum1, 1);
        sum1 += __shfl_xor_sync(0xffffffffu, sum1, 2);
        lrow0 = lrow0*corr0 + sum0;
        lrow1 = lrow1*corr1 + sum1;
        mrow0 = mn0; mrow1 = mn1;
        #pragma unroll
        for (int nt = 0; nt < 8; nt++) {
            o[nt][0] *= corr0; o[nt][1] *= corr0;
            o[nt][2] *= corr1; o[nt][3] *= corr1;
        }

        // ---- P -> smem (re-fragment as MMA A operand) ----
        #pragma unroll
        for (int nt = 0; nt < 4; nt++) {
            Ps[m0+lr][nt*8+2*lq]     = f2tf(s[nt][0]);
            Ps[m0+lr][nt*8+2*lq+1]   = f2tf(s[nt][1]);
            Ps[m0+lr+8][nt*8+2*lq]   = f2tf(s[nt][2]);
            Ps[m0+lr+8][nt*8+2*lq+1] = f2tf(s[nt][3]);
        }
        __syncwarp();

        // ---- O += P V ----
        #pragma unroll
        for (int ks = 0; ks < 4; ks++) {
            unsigned a[4];
            a[0] = Ps[m0+lr][ks*8+lq];
            a[1] = Ps[m0+lr+8][ks*8+lq];
            a[2] = Ps[m0+lr][ks*8+lq+4];
            a[3] = Ps[m0+lr+8][ks*8+lq+4];
            #pragma unroll
            for (int nt = 0; nt < 8; nt++) {
                unsigned bf[2] = { Vts[nt*8+lr][ks*8+lq], Vts[nt*8+lr][ks*8+lq+4] };
                mma_tf32(o[nt], a, bf);
            }
        }
    }

    float inv0 = 1.f / lrow0, inv1 = 1.f / lrow1;
    #pragma unroll
    for (int nt = 0; nt < 8; nt++) {
        int cg = h*64 + nt*8 + 2*lq;
        size_t base0 = (size_t)(b*TT + rg0)*DD + cg;
        size_t base1 = (size_t)(b*TT + rg1)*DD + cg;
        out[base0]   = o[nt][0]*inv0;
        out[base0+1] = o[nt][1]*inv0;
        out[base1]   = o[nt][2]*inv1;
        out[base1+1] = o[nt][3]*inv1;
    }
}

// ---------------------------------------------------------------------------
// Router logits: block per token (128 thr, 4 warps x 4 experts)
// ---------------------------------------------------------------------------
__global__ void router_kernel(const float* __restrict__ xn,
                              const float* __restrict__ rw,
                              float* __restrict__ logits)
{
    int n = blockIdx.x;
    int warp = threadIdx.x >> 5, lane = threadIdx.x & 31;
    const float* xp = xn + (size_t)n*DD;
    for (int j = 0; j < 4; j++) {
        int e = warp*4 + j;
        const float* wp = rw + (size_t)e*DD;
        float s = 0.f;
        for (int i = lane; i < DD; i += 32) s += xp[i]*wp[i];
        #pragma unroll
        for (int off = 16; off; off >>= 1) s += __shfl_xor_sync(0xffffffffu, s, off);
        if (lane == 0) logits[n*EE + e] = s;
    }
}

// ---------------------------------------------------------------------------
// Softmax over 16 experts + top-2
// ---------------------------------------------------------------------------
__global__ void top2_kernel(const float* __restrict__ logits,
                            float* __restrict__ probs,
                            int* __restrict__ topi, float* __restrict__ topw)
{
    int n = blockIdx.x*blockDim.x + threadIdx.x;
    if (n >= NTOK) return;
    float l[EE];
    float mx = -1e30f;
    #pragma unroll
    for (int e = 0; e < EE; e++) { l[e] = logits[n*EE+e]; mx = fmaxf(mx, l[e]); }
    float sum = 0.f;
    #pragma unroll
    for (int e = 0; e < EE; e++) { l[e] = __expf(l[e]-mx); sum += l[e]; }
    float inv = 1.f/sum;
    #pragma unroll
    for (int e = 0; e < EE; e++) { l[e] *= inv; probs[n*EE+e] = l[e]; }
    int i0 = 0; float p0 = l[0];
    #pragma unroll
    for (int e = 1; e < EE; e++) if (l[e] > p0) { p0 = l[e]; i0 = e; }
    int i1 = (i0 == 0) ? 1 : 0; float p1 = l[i1];
    #pragma unroll
    for (int e = 0; e < EE; e++) if (e != i0 && l[e] > p1) { p1 = l[e]; i1 = e; }
    float ws = p0 + p1;
    topi[n*2]   = i0; topi[n*2+1] = i1;
    topw[n*2]   = p0/ws; topw[n*2+1] = p1/ws;
}

// ---------------------------------------------------------------------------
// Deterministic pmean reduction (16 blocks, fixed tree)
// ---------------------------------------------------------------------------
__global__ void pmean_kernel(const float* __restrict__ probs, float* __restrict__ pmean)
{
    int e = blockIdx.x, tid = threadIdx.x;
    float s = 0.f;
    for (int t = tid; t < NTOK; t += 256) s += probs[t*EE + e];
    __shared__ float red[256];
    red[tid] = s;
    __syncthreads();
    for (int k = 128; k; k >>= 1) {
        if (tid < k) red[tid] += red[tid+k];
        __syncthreads();
    }
    if (tid == 0) pmean[e] = red[0] / (float)NTOK;
}

// ---------------------------------------------------------------------------
// Capacity position assignment
// ---------------------------------------------------------------------------
__global__ void assign_kernel(const int* __restrict__ topi,
                              const float* __restrict__ topw,
                              int* __restrict__ slot, int* __restrict__ keep,
                              float* __restrict__ wcomb, int* __restrict__ counts)
{
    int e = blockIdx.x;
    int tid = threadIdx.x;
    int lane = tid & 31, warp = tid >> 5;
    __shared__ int warpsum[8];
    int running = 0;
    for (int base = 0; base < NFLAT; base += 256) {
        int i = base + tid;
        int match = (topi[i] == e) ? 1 : 0;
        unsigned mask = __ballot_sync(0xffffffffu, match);
        if (lane == 0) warpsum[warp] = __popc(mask);
        __syncthreads();
        int wbase = 0, tot = 0;
        #pragma unroll
        for (int w = 0; w < 8; w++) {
            int c = warpsum[w];
            if (w < warp) wbase += c;
            tot += c;
        }
        if (match) {
            int pos = running + wbase + __popc(mask & ((1u << lane) - 1u));
            int kp = (pos < CAP) ? 1 : 0;
            slot[i]  = (pos < CAP-1) ? pos : (CAP-1);
            keep[i]  = kp;
            wcomb[i] = kp ? topw[i] : 0.f;
        }
        running += tot;
        __syncthreads();
    }
    if (tid == 0) counts[e] = running;
}

// ---------------------------------------------------------------------------
// Scatter tokens into expert buffers
// ---------------------------------------------------------------------------
__global__ void scatter_kernel(const int* __restrict__ topi,
                               const int* __restrict__ slot,
                               const int* __restrict__ keep,
                               const float* __restrict__ xn,
                               float* __restrict__ buf)
{
    int i = blockIdx.x;
    if (!keep[i]) return;
    int e = topi[i], s = slot[i], tok = i >> 1;
    const float4* src = (const float4*)(xn + (size_t)tok*DD);
    float4* dst = (float4*)(buf + ((size_t)e*CAP + s)*DD);
    dst[threadIdx.x] = src[threadIdx.x];
}

// ---------------------------------------------------------------------------
// Gather expert outputs + residual into x
// ---------------------------------------------------------------------------
__global__ void gather_kernel(const int* __restrict__ topi,
                              const int* __restrict__ slot,
                              const float* __restrict__ wcomb,
                              const float* __restrict__ yb,
                              float* __restrict__ x)
{
    int n = blockIdx.x;
    int t4 = threadIdx.x;
    float4* xp = (float4*)(x + (size_t)n*DD);
    float4 a = xp[t4];
    #pragma unroll
    for (int k = 0; k < 2; k++) {
        int i = n*2 + k;
        float w = wcomb[i];
        if (w != 0.f) {
            int e = topi[i], s = slot[i];
            const float4* yp = (const float4*)(yb + ((size_t)e*CAP + s)*DD);
            float4 yv = yp[t4];
            a.x += w*yv.x; a.y += w*yv.y; a.z += w*yv.z; a.w += w*yv.w;
        }
    }
    xp[t4] = a;
}

// ---------------------------------------------------------------------------
// aux = E * sum(frac * pmean); written at d_out[B*T*D]
// ---------------------------------------------------------------------------
__global__ void aux_kernel(const int* __restrict__ counts,
                           const float* __restrict__ pmean,
                           float* __restrict__ out, int out_size)
{
    if (threadIdx.x == 0 && out_size > NTOK*DD) {
        float s = 0.f;
        for (int e = 0; e < EE; e++)
            s += ((float)counts[e] / (float)NTOK) * pmean[e];
        out[NTOK*DD] = (float)EE * s;
    }
}

// ---------------------------------------------------------------------------
// ToU gate: sigmoid(xn . gw + gb) per token
// ---------------------------------------------------------------------------
__global__ void gate_kernel(const float* __restrict__ xn,
                            const float* __restrict__ gw,
                            const float* __restrict__ gb,
                            float* __restrict__ gate)
{
    int n = blockIdx.x, tid = threadIdx.x;
    const float4* xp = (const float4*)(xn + (size_t)n*DD);
    const float4* wp = (const float4*)gw;
    float4 xv = xp[tid], wv = wp[tid];
    float s = xv.x*wv.x + xv.y*wv.y + xv.z*wv.z + xv.w*wv.w;
    __shared__ float red[256];
    red[tid] = s;
    __syncthreads();
    for (int k = 128; k; k >>= 1) {
        if (tid < k) red[tid] += red[tid+k];
        __syncthreads();
    }
    if (tid == 0) gate[n] = 1.f / (1.f + __expf(-(red[0] + gb[0])));
}

// ---------------------------------------------------------------------------
// Softmax over 512 primitives (scale 1/16 folded in), in place
// ---------------------------------------------------------------------------
__global__ void softmax512_kernel(float* __restrict__ tl)
{
    int n = blockIdx.x, tid = threadIdx.x;
    float* row = tl + (size_t)n*NPRIM;
    float v0 = row[tid]       * 0.0625f;
    float v1 = row[tid + 256] * 0.0625f;
    __shared__ float red[256];
    red[tid] = fmaxf(v0, v1);
    __syncthreads();
    for (int s = 128; s; s >>= 1) {
        if (tid < s) red[tid] = fmaxf(red[tid], red[tid+s]);
        __syncthreads();
    }
    float mx = red[0];
    __syncthreads();
    v0 = __expf(v0 - mx); v1 = __expf(v1 - mx);
    red[tid] = v0 + v1;
    __syncthreads();
    for (int s = 128; s; s >>= 1) {
        if (tid < s) red[tid] += red[tid+s];
        __syncthreads();
    }
    float inv = 1.f / red[0];
    row[tid] = v0*inv; row[tid+256] = v1*inv;
}

// ---------------------------------------------------------------------------
// Host launch
// ---------------------------------------------------------------------------
extern "C" void kernel_launch(void* const* d_in, const int* in_sizes, int n_in,
                              void* d_out, int out_size)
{
    const float* x          = (const float*)d_in[0];
    const float* tou_embeds = (const float*)d_in[1];
    const float* norm1_w    = (const float*)d_in[2];
    const float* qkv_w      = (const float*)d_in[3];
    const float* attn_o_w   = (const float*)d_in[4];
    const float* norm2_w    = (const float*)d_in[5];
    const float* router_w   = (const float*)d_in[6];
    const float* moe_w1     = (const float*)d_in[7];
    const float* moe_w2     = (const float*)d_in[8];
    const float* norm3_w    = (const float*)d_in[9];
    const float* tou_q_w    = (const float*)d_in[10];
    const float* tou_k_w    = (const float*)d_in[11];
    const float* tou_v_w    = (const float*)d_in[12];
    const float* tou_o_w    = (const float*)d_in[13];
    const float* tou_gate_w = (const float*)d_in[14];
    const float* tou_gate_b = (const float*)d_in[15];

    float *gx, *gxn, *gqkv, *gattn, *glogits, *gprobs, *gtopw, *gwcomb,
          *gpmean, *gbuf, *gh, *gyb, *gtq, *gtk, *gtv, *gtl, *gtout, *ggate;
    int *gtopi, *gslot, *gkeep, *gcounts;
    cudaGetSymbolAddress((void**)&gx, g_x);
    cudaGetSymbolAddress((void**)&gxn, g_xn);
    cudaGetSymbolAddress((void**)&gqkv, g_qkv);
    cudaGetSymbolAddress((void**)&gattn, g_attn);
    cudaGetSymbolAddress((void**)&glogits, g_logits);
    cudaGetSymbolAddress((void**)&gprobs, g_probs);
    cudaGetSymbolAddress((void**)&gtopi, g_topi);
    cudaGetSymbolAddress((void**)&gtopw, g_topw);
    cudaGetSymbolAddress((void**)&gslot, g_slot);
    cudaGetSymbolAddress((void**)&gkeep, g_keep);
    cudaGetSymbolAddress((void**)&gwcomb, g_wcomb);
    cudaGetSymbolAddress((void**)&gcounts, g_counts);
    cudaGetSymbolAddress((void**)&gpmean, g_pmean);
    cudaGetSymbolAddress((void**)&gbuf, g_buf);
    cudaGetSymbolAddress((void**)&gh, g_h);
    cudaGetSymbolAddress((void**)&gyb, g_yb);
    cudaGetSymbolAddress((void**)&gtq, g_tq);
    cudaGetSymbolAddress((void**)&gtk, g_tk);
    cudaGetSymbolAddress((void**)&gtv, g_tv);
    cudaGetSymbolAddress((void**)&gtl, g_tl);
    cudaGetSymbolAddress((void**)&gtout, g_tout);
    cudaGetSymbolAddress((void**)&ggate, g_gate);

    // residual stream
    cudaMemcpyAsync(gx, x, (size_t)NTOK*DD*sizeof(float), cudaMemcpyDeviceToDevice);

    // ---- Block 1: RoPE attention ----
    rmsnorm_kernel<<<NTOK, 256>>>(x, norm1_w, gxn);
    gemm128<true,0><<<dim3(3*DD/128, NTOK/128, 1), 256>>>(gxn, qkv_w, gqkv,
        NTOK, 3*DD, DD, 0, 0, 0, nullptr);
    rope_kernel<<<NTOK, 256>>>(gqkv);
    flash_attn_tc<<<dim3(TT/64, BB*HH), 128>>>(gqkv, gattn);
    gemm128<true,1><<<dim3(DD/128, NTOK/128, 1), 256>>>(gattn, attn_o_w, gx,
        NTOK, DD, DD, 0, 0, 0, nullptr);

    // ---- Block 2: MoE ----
    rmsnorm_kernel<<<NTOK, 256>>>(gx, norm2_w, gxn);
    router_kernel<<<NTOK, 128>>>(gxn, router_w, glogits);
    top2_kernel<<<NTOK/128, 128>>>(glogits, gprobs, gtopi, gtopw);
    pmean_kernel<<<EE, 256>>>(gprobs, gpmean);
    assign_kernel<<<EE, 256>>>(gtopi, gtopw, gslot, gkeep, gwcomb, gcounts);
    cudaMemsetAsync(gbuf, 0, (size_t)EE*CAP*DD*sizeof(float));
    scatter_kernel<<<NFLAT, 256>>>(gtopi, gslot, gkeep, gxn, gbuf);
    gemm128<false,2><<<dim3(FF/128, CAP/128, EE), 256>>>(gbuf, moe_w1, gh,
        CAP, FF, DD, (long long)CAP*DD, (long long)DD*FF, (long long)CAP*FF, nullptr);
    gemm128<false,0><<<dim3(DD/128, CAP/128, EE), 256>>>(gh, moe_w2, gyb,
        CAP, DD, FF, (long long)CAP*FF, (long long)FF*DD, (long long)CAP*DD, nullptr);
    gather_kernel<<<NTOK, 256>>>(gtopi, gslot, gwcomb, gyb, gx);
    aux_kernel<<<1, 32>>>(gcounts, gpmean, (float*)d_out, out_size);

    // ---- Block 3: ToU cross-attention ----
    rmsnorm_kernel<<<NTOK, 256>>>(gx, norm3_w, gxn);
    gemm128<true,0><<<dim3(DP/128, NTOK/128, 1), 256>>>(gxn, tou_q_w, gtq,
        NTOK, DP, DD, 0, 0, 0, nullptr);
    gemm128<true,0><<<dim3(DP/128, NPRIM/128, 1), 256>>>(tou_embeds, tou_k_w, gtk,
        NPRIM, DP, DP, 0, 0, 0, nullptr);
    gemm128<true,0><<<dim3(DP/128, NPRIM/128, 1), 256>>>(tou_embeds, tou_v_w, gtv,
        NPRIM, DP, DP, 0, 0, 0, nullptr);
    gemm128<true,0><<<dim3(NPRIM/128, NTOK/128, 1), 256>>>(gtq, gtk, gtl,
        NTOK, NPRIM, DP, 0, 0, 0, nullptr);
    softmax512_kernel<<<NTOK, 256>>>(gtl);
    gemm128<false,0><<<dim3(DP/128, NTOK/128, 1), 256>>>(gtl, gtv, gtout,
        NTOK, DP, NPRIM, 0, 0, 0, nullptr);
    gate_kernel<<<NTOK, 256>>>(gxn, tou_gate_w, tou_gate_b, ggate);
    gemm128<true,3><<<dim3(DD/128, NTOK/128, 1), 256>>>(gtout, tou_o_w, gx,
        NTOK, DD, DP, 0, 0, 0, ggate);

    // output
    cudaMemcpyAsync(d_out, gx, (size_t)NTOK*DD*sizeof(float), cudaMemcpyDeviceToDevice);
}

// round 4
// speedup vs baseline: 3.5080x; 1.2360x over previous
#include <cuda_runtime.h>
#include <cuda_bf16.h>
#include <math.h>

// ---------------------------------------------------------------------------
// Problem constants
// ---------------------------------------------------------------------------
#define BB 2
#define TT 2048
#define DD 1024
#define HH 16
#define DH 64
#define NTOK (BB*TT)            // 4096
#define EE 16
#define KK 2
#define FF 2048
#define CAP 640
#define DP 256
#define NPRIM 512
#define NFLAT (NTOK*KK)         // 8192

// ---------------------------------------------------------------------------
// Scratch (device globals; no allocation allowed)
// ---------------------------------------------------------------------------
__device__ float g_x[NTOK*DD];
__device__ float g_xn[NTOK*DD];
__device__ float g_qkv[NTOK*3*DD];
__device__ float g_attn[NTOK*DD];
__device__ float g_logits[NTOK*EE];
__device__ float g_probs[NTOK*EE];
__device__ int   g_topi[NFLAT];
__device__ float g_topw[NFLAT];
__device__ int   g_slot[NFLAT];
__device__ int   g_keep[NFLAT];
__device__ float g_wcomb[NFLAT];
__device__ int   g_counts[EE];
__device__ float g_pmean[EE];
__device__ float g_buf[EE*CAP*DD];
__device__ float g_h[EE*CAP*FF];
__device__ float g_yb[EE*CAP*DD];
__device__ float g_tq[NTOK*DP];
__device__ float g_tk[NPRIM*DP];
__device__ float g_tv[NPRIM*DP];
__device__ float g_tl[NTOK*NPRIM];
__device__ float g_tout[NTOK*DP];
__device__ float g_gate[NTOK];
__device__ float g_ropec[TT*32];
__device__ float g_ropes[TT*32];

// ---------------------------------------------------------------------------
// TF32 helpers
// ---------------------------------------------------------------------------
__device__ __forceinline__ unsigned f2tf(float x)
{
    unsigned r;
    asm("cvt.rna.tf32.f32 %0, %1;" : "=r"(r) : "f"(x));
    return r;
}

__device__ __forceinline__ void mma_tf32(float c[4], const unsigned a[4], const unsigned b[2])
{
    asm volatile(
        "mma.sync.aligned.m16n8k8.row.col.f32.tf32.tf32.f32 "
        "{%0,%1,%2,%3},{%4,%5,%6,%7},{%8,%9},{%0,%1,%2,%3};"
        : "+f"(c[0]), "+f"(c[1]), "+f"(c[2]), "+f"(c[3])
        : "r"(a[0]), "r"(a[1]), "r"(a[2]), "r"(a[3]),
          "r"(b[0]), "r"(b[1]));
}

__device__ __forceinline__ void cp16(void* smem_dst, const void* gptr)
{
    unsigned saddr = (unsigned)__cvta_generic_to_shared(smem_dst);
    asm volatile("cp.async.cg.shared.global [%0], [%1], 16;\n"
                 :: "r"(saddr), "l"(gptr));
}
__device__ __forceinline__ void cp_commit()  { asm volatile("cp.async.commit_group;\n"); }
__device__ __forceinline__ void cp_wait1()   { asm volatile("cp.async.wait_group 1;\n"); }
__device__ __forceinline__ void cp_wait0()   { asm volatile("cp.async.wait_group 0;\n"); }

// ---------------------------------------------------------------------------
// RMSNorm: one block per token, 256 threads, float4
// ---------------------------------------------------------------------------
__global__ void rmsnorm_kernel(const float* __restrict__ x,
                               const float* __restrict__ w,
                               float* __restrict__ out)
{
    int n = blockIdx.x;
    int tid = threadIdx.x;
    const float4* xp = (const float4*)(x + (size_t)n*DD);
    float4 xv = xp[tid];
    float ss = xv.x*xv.x + xv.y*xv.y + xv.z*xv.z + xv.w*xv.w;
    __shared__ float red[256];
    red[tid] = ss;
    __syncthreads();
    for (int s = 128; s; s >>= 1) {
        if (tid < s) red[tid] += red[tid+s];
        __syncthreads();
    }
    float scale = rsqrtf(red[0] / (float)DD + 1e-6f);
    const float4* wp = (const float4*)w;
    float4 wv = wp[tid];
    float4* op = (float4*)(out + (size_t)n*DD);
    op[tid] = make_float4(xv.x*scale*wv.x, xv.y*scale*wv.y,
                          xv.z*scale*wv.z, xv.w*scale*wv.w);
}

// ---------------------------------------------------------------------------
// TF32 tensor-core GEMM with cp.async double buffering.
//   C[M,N] = A[M,K] * op(B)
//   BT=true : B stored [N,K] row-major (use B^T)
//   BT=false: B stored [K,N] row-major
// EPI: 0=store, 1=C+=, 2=silu store, 3=C += gate[row]*v
// Tiles: block 128x128, BK=16; 8 warps, warp tile 64x32 via m16n8k8.
// Smem A/B(T): row-major [128][20] (stride 20 => conflict-free frags);
// B(KN): [16][136]. Raw fp32 bits fed to tf32 MMA (HW truncates).
// ---------------------------------------------------------------------------
#define AS_STR 20
#define BF_STR 136

template<bool BT, int EPI>
__global__ __launch_bounds__(256, 2)
void gemm128(const float* __restrict__ A, const float* __restrict__ Bm,
             float* __restrict__ C, int M, int N, int K,
             long long sA, long long sB, long long sC,
             const float* __restrict__ gate)
{
    A  += blockIdx.z * sA;
    Bm += blockIdx.z * sB;
    C  += blockIdx.z * sC;

    __shared__ unsigned As[2][128][AS_STR];
    __shared__ unsigned Bs[2][128][AS_STR];     // BT=true layout [n][k]
    __shared__ unsigned Bf[2][16][BF_STR];      // BT=false layout [k][n]

    const int tid  = threadIdx.x;
    const int lane = tid & 31;
    const int warp = tid >> 5;
    const int lr   = lane >> 2;
    const int lq   = lane & 3;
    const int wm   = warp & 1, wn = warp >> 1;
    const int m0   = wm * 64, n0 = wn * 32;
    const int row0 = blockIdx.y * 128, col0 = blockIdx.x * 128;

    // chunk decomposition (each thread: 2 chunks of A, 2 of B)
    const int c0i = tid, c1i = tid + 256;
    const int ar0 = c0i >> 2, ac0 = (c0i & 3) * 4;
    const int ar1 = c1i >> 2, ac1 = (c1i & 3) * 4;
    const int fk0 = c0i >> 5, fn0 = (c0i & 31) * 4;
    const int fk1 = c1i >> 5, fn1 = (c1i & 31) * 4;

    const int nIter = K >> 4;

    // ---- issue stage 0 ----
    {
        cp16(&As[0][ar0][ac0], A + (size_t)(row0 + ar0) * K + ac0);
        cp16(&As[0][ar1][ac1], A + (size_t)(row0 + ar1) * K + ac1);
        if (BT) {
            cp16(&Bs[0][ar0][ac0], Bm + (size_t)(col0 + ar0) * K + ac0);
            cp16(&Bs[0][ar1][ac1], Bm + (size_t)(col0 + ar1) * K + ac1);
        } else {
            cp16(&Bf[0][fk0][fn0], Bm + (size_t)fk0 * N + col0 + fn0);
            cp16(&Bf[0][fk1][fn1], Bm + (size_t)fk1 * N + col0 + fn1);
        }
        cp_commit();
    }

    float c[4][4][4];
    #pragma unroll
    for (int mt = 0; mt < 4; mt++)
        #pragma unroll
        for (int nt = 0; nt < 4; nt++)
            #pragma unroll
            for (int i = 0; i < 4; i++) c[mt][nt][i] = 0.f;

    int st = 0;
    for (int it = 0; it < nIter; it++) {
        if (it + 1 < nIter) {
            const int k0 = (it + 1) << 4;
            const int ns = st ^ 1;
            cp16(&As[ns][ar0][ac0], A + (size_t)(row0 + ar0) * K + k0 + ac0);
            cp16(&As[ns][ar1][ac1], A + (size_t)(row0 + ar1) * K + k0 + ac1);
            if (BT) {
                cp16(&Bs[ns][ar0][ac0], Bm + (size_t)(col0 + ar0) * K + k0 + ac0);
                cp16(&Bs[ns][ar1][ac1], Bm + (size_t)(col0 + ar1) * K + k0 + ac1);
            } else {
                cp16(&Bf[ns][fk0][fn0], Bm + (size_t)(k0 + fk0) * N + col0 + fn0);
                cp16(&Bf[ns][fk1][fn1], Bm + (size_t)(k0 + fk1) * N + col0 + fn1);
            }
            cp_commit();
            cp_wait1();
        } else {
            cp_wait0();
        }
        __syncthreads();

        #pragma unroll
        for (int ks = 0; ks < 2; ks++) {
            const int kb = ks * 8;
            unsigned a[4][4], b[4][2];
            #pragma unroll
            for (int mt = 0; mt < 4; mt++) {
                int r = m0 + mt * 16 + lr;
                a[mt][0] = As[st][r][kb + lq];
                a[mt][1] = As[st][r + 8][kb + lq];
                a[mt][2] = As[st][r][kb + 4 + lq];
                a[mt][3] = As[st][r + 8][kb + 4 + lq];
            }
            #pragma unroll
            for (int nt = 0; nt < 4; nt++) {
                int cn = n0 + nt * 8 + lr;
                if (BT) {
                    b[nt][0] = Bs[st][cn][kb + lq];
                    b[nt][1] = Bs[st][cn][kb + 4 + lq];
                } else {
                    b[nt][0] = Bf[st][kb + lq][cn];
                    b[nt][1] = Bf[st][kb + 4 + lq][cn];
                }
            }
            #pragma unroll
            for (int mt = 0; mt < 4; mt++)
                #pragma unroll
                for (int nt = 0; nt < 4; nt++)
                    mma_tf32(c[mt][nt], a[mt], b[nt]);
        }
        __syncthreads();
        st ^= 1;
    }

    // epilogue
    #pragma unroll
    for (int mt = 0; mt < 4; mt++) {
        int r0g = row0 + m0 + mt * 16 + lr;
        int r1g = r0g + 8;
        float g0 = (EPI == 3) ? gate[r0g] : 0.f;
        float g1 = (EPI == 3) ? gate[r1g] : 0.f;
        #pragma unroll
        for (int nt = 0; nt < 4; nt++) {
            int cg = col0 + n0 + nt * 8 + 2 * lq;
            float* p0 = &C[(size_t)r0g * N + cg];
            float* p1 = &C[(size_t)r1g * N + cg];
            float v0 = c[mt][nt][0], v1 = c[mt][nt][1];
            float v2 = c[mt][nt][2], v3 = c[mt][nt][3];
            if (EPI == 0) {
                p0[0] = v0; p0[1] = v1; p1[0] = v2; p1[1] = v3;
            } else if (EPI == 1) {
                p0[0] += v0; p0[1] += v1; p1[0] += v2; p1[1] += v3;
            } else if (EPI == 2) {
                p0[0] = v0 / (1.f + __expf(-v0));
                p0[1] = v1 / (1.f + __expf(-v1));
                p1[0] = v2 / (1.f + __expf(-v2));
                p1[1] = v3 / (1.f + __expf(-v3));
            } else {
                p0[0] += g0 * v0; p0[1] += g0 * v1;
                p1[0] += g1 * v2; p1[1] += g1 * v3;
            }
        }
    }
}

// ---------------------------------------------------------------------------
// RoPE table + apply
// ---------------------------------------------------------------------------
__global__ void rope_table_kernel()
{
    int idx = blockIdx.x * 256 + threadIdx.x;     // TT*32 total
    int t = idx >> 5, i = idx & 31;
    float inv = powf(10000.f, -(float)i / 32.f);
    float s, c;
    sincosf((float)t * inv, &s, &c);
    g_ropec[idx] = c;
    g_ropes[idx] = s;
}

__global__ void rope_kernel(float* __restrict__ qkv)
{
    int n = blockIdx.x;
    int t = n & (TT-1);
    for (int p = threadIdx.x; p < 1024; p += 256) {
        int which = p >> 9;
        int rem = p & 511;
        int h = rem >> 5;
        int i = rem & 31;
        float c = g_ropec[t*32 + i];
        float s = g_ropes[t*32 + i];
        size_t base = (size_t)n*3072 + (size_t)which*1024 + h*64 + i;
        float u1 = qkv[base], u2 = qkv[base+32];
        qkv[base]    = u1*c - u2*s;
        qkv[base+32] = u2*c + u1*s;
    }
}

// ---------------------------------------------------------------------------
// Tensor-core flash attention (unchanged from R2)
// ---------------------------------------------------------------------------
#define QS_STR 68
#define VS_STR 36
#define PS_STR 36

__global__ __launch_bounds__(128)
void flash_attn_tc(const float* __restrict__ qkv, float* __restrict__ out)
{
    __shared__ unsigned Qs[64][QS_STR];
    __shared__ unsigned Ks[32][QS_STR];
    __shared__ unsigned Vts[64][VS_STR];
    __shared__ unsigned Ps[64][PS_STR];

    const int qb = blockIdx.x, bh = blockIdx.y;
    const int b = bh >> 4, h = bh & 15;
    const int tid = threadIdx.x, lane = tid & 31, warp = tid >> 5;
    const int lr = lane >> 2, lq = lane & 3;
    const int m0 = warp * 16;
    const int q0 = qb * 64;

    for (int i = tid; i < 64*64; i += 128) {
        int r = i >> 6, d = i & 63;
        Qs[r][d] = f2tf(qkv[(size_t)(b*TT + q0 + r)*3072 + h*64 + d] * 0.125f);
    }

    float mrow0 = -1e30f, mrow1 = -1e30f;
    float lrow0 = 0.f,    lrow1 = 0.f;
    float o[8][4];
    #pragma unroll
    for (int nt = 0; nt < 8; nt++)
        #pragma unroll
        for (int i = 0; i < 4; i++) o[nt][i] = 0.f;

    const int rg0 = q0 + m0 + lr, rg1 = rg0 + 8;
    const int ntiles = 2*qb + 2;

    for (int kb = 0; kb < ntiles; kb++) {
        __syncthreads();
        for (int i = tid; i < 32*64; i += 128) {
            int r = i >> 6, d = i & 63;
            size_t base = (size_t)(b*TT + kb*32 + r)*3072 + h*64 + d;
            Ks[r][d]  = f2tf(qkv[base + 1024]);
            Vts[d][r] = f2tf(qkv[base + 2048]);
        }
        __syncthreads();

        float s[4][4];
        #pragma unroll
        for (int nt = 0; nt < 4; nt++)
            #pragma unroll
            for (int i = 0; i < 4; i++) s[nt][i] = 0.f;
        #pragma unroll
        for (int kk = 0; kk < 8; kk++) {
            unsigned a[4];
            a[0] = Qs[m0+lr][kk*8+lq];
            a[1] = Qs[m0+lr+8][kk*8+lq];
            a[2] = Qs[m0+lr][kk*8+lq+4];
            a[3] = Qs[m0+lr+8][kk*8+lq+4];
            #pragma unroll
            for (int nt = 0; nt < 4; nt++) {
                unsigned bf[2] = { Ks[nt*8+lr][kk*8+lq], Ks[nt*8+lr][kk*8+lq+4] };
                mma_tf32(s[nt], a, bf);
            }
        }

        if (kb >= 2*qb) {
            #pragma unroll
            for (int nt = 0; nt < 4; nt++) {
                int c0 = kb*32 + nt*8 + 2*lq;
                if (c0   > rg0) s[nt][0] = -1e30f;
                if (c0+1 > rg0) s[nt][1] = -1e30f;
                if (c0   > rg1) s[nt][2] = -1e30f;
                if (c0+1 > rg1) s[nt][3] = -1e30f;
            }
        }

        float mx0 = -1e30f, mx1 = -1e30f;
        #pragma unroll
        for (int nt = 0; nt < 4; nt++) {
            mx0 = fmaxf(mx0, fmaxf(s[nt][0], s[nt][1]));
            mx1 = fmaxf(mx1, fmaxf(s[nt][2], s[nt][3]));
        }
        mx0 = fmaxf(mx0, __shfl_xor_sync(0xffffffffu, mx0, 1));
        mx0 = fmaxf(mx0, __shfl_xor_sync(0xffffffffu, mx0, 2));
        mx1 = fmaxf(mx1, __shfl_xor_sync(0xffffffffu, mx1, 1));
        mx1 = fmaxf(mx1, __shfl_xor_sync(0xffffffffu, mx1, 2));
        float mn0 = fmaxf(mrow0, mx0), mn1 = fmaxf(mrow1, mx1);
        float corr0 = __expf(mrow0 - mn0), corr1 = __expf(mrow1 - mn1);
        float sum0 = 0.f, sum1 = 0.f;
        #pragma unroll
        for (int nt = 0; nt < 4; nt++) {
            s[nt][0] = __expf(s[nt][0] - mn0);
            s[nt][1] = __expf(s[nt][1] - mn0);
            s[nt][2] = __expf(s[nt][2] - mn1);
            s[nt][3] = __expf(s[nt][3] - mn1);
            sum0 += s[nt][0] + s[nt][1];
            sum1 += s[nt][2] + s[nt][3];
        }
        sum0 += __shfl_xor_sync(0xffffffffu, sum0, 1);
        sum0 += __shfl_xor_sync(0xffffffffu, sum0, 2);
        sum1 += __shfl_xor_sync(0xffffffffu, sum1, 1);
        sum1 += __shfl_xor_sync(0xffffffffu, sum1, 2);
        lrow0 = lrow0*corr0 + sum0;
        lrow1 = lrow1*corr1 + sum1;
        mrow0 = mn0; mrow1 = mn1;
        #pragma unroll
        for (int nt = 0; nt < 8; nt++) {
            o[nt][0] *= corr0; o[nt][1] *= corr0;
            o[nt][2] *= corr1; o[nt][3] *= corr1;
        }

        #pragma unroll
        for (int nt = 0; nt < 4; nt++) {
            Ps[m0+lr][nt*8+2*lq]     = f2tf(s[nt][0]);
            Ps[m0+lr][nt*8+2*lq+1]   = f2tf(s[nt][1]);
            Ps[m0+lr+8][nt*8+2*lq]   = f2tf(s[nt][2]);
            Ps[m0+lr+8][nt*8+2*lq+1] = f2tf(s[nt][3]);
        }
        __syncwarp();

        #pragma unroll
        for (int ks = 0; ks < 4; ks++) {
            unsigned a[4];
            a[0] = Ps[m0+lr][ks*8+lq];
            a[1] = Ps[m0+lr+8][ks*8+lq];
            a[2] = Ps[m0+lr][ks*8+lq+4];
            a[3] = Ps[m0+lr+8][ks*8+lq+4];
            #pragma unroll
            for (int nt = 0; nt < 8; nt++) {
                unsigned bf[2] = { Vts[nt*8+lr][ks*8+lq], Vts[nt*8+lr][ks*8+lq+4] };
                mma_tf32(o[nt], a, bf);
            }
        }
    }

    float inv0 = 1.f / lrow0, inv1 = 1.f / lrow1;
    #pragma unroll
    for (int nt = 0; nt < 8; nt++) {
        int cg = h*64 + nt*8 + 2*lq;
        size_t base0 = (size_t)(b*TT + rg0)*DD + cg;
        size_t base1 = (size_t)(b*TT + rg1)*DD + cg;
        out[base0]   = o[nt][0]*inv0;
        out[base0+1] = o[nt][1]*inv0;
        out[base1]   = o[nt][2]*inv1;
        out[base1+1] = o[nt][3]*inv1;
    }
}

// ---------------------------------------------------------------------------
// Router logits: block per token (128 thr, 4 warps x 4 experts)
// ---------------------------------------------------------------------------
__global__ void router_kernel(const float* __restrict__ xn,
                              const float* __restrict__ rw,
                              float* __restrict__ logits)
{
    int n = blockIdx.x;
    int warp = threadIdx.x >> 5, lane = threadIdx.x & 31;
    const float* xp = xn + (size_t)n*DD;
    for (int j = 0; j < 4; j++) {
        int e = warp*4 + j;
        const float* wp = rw + (size_t)e*DD;
        float s = 0.f;
        for (int i = lane; i < DD; i += 32) s += xp[i]*wp[i];
        #pragma unroll
        for (int off = 16; off; off >>= 1) s += __shfl_xor_sync(0xffffffffu, s, off);
        if (lane == 0) logits[n*EE + e] = s;
    }
}

// ---------------------------------------------------------------------------
// Softmax over 16 experts + top-2
// ---------------------------------------------------------------------------
__global__ void top2_kernel(const float* __restrict__ logits,
                            float* __restrict__ probs,
                            int* __restrict__ topi, float* __restrict__ topw)
{
    int n = blockIdx.x*blockDim.x + threadIdx.x;
    if (n >= NTOK) return;
    float l[EE];
    float mx = -1e30f;
    #pragma unroll
    for (int e = 0; e < EE; e++) { l[e] = logits[n*EE+e]; mx = fmaxf(mx, l[e]); }
    float sum = 0.f;
    #pragma unroll
    for (int e = 0; e < EE; e++) { l[e] = __expf(l[e]-mx); sum += l[e]; }
    float inv = 1.f/sum;
    #pragma unroll
    for (int e = 0; e < EE; e++) { l[e] *= inv; probs[n*EE+e] = l[e]; }
    int i0 = 0; float p0 = l[0];
    #pragma unroll
    for (int e = 1; e < EE; e++) if (l[e] > p0) { p0 = l[e]; i0 = e; }
    int i1 = (i0 == 0) ? 1 : 0; float p1 = l[i1];
    #pragma unroll
    for (int e = 0; e < EE; e++) if (e != i0 && l[e] > p1) { p1 = l[e]; i1 = e; }
    float ws = p0 + p1;
    topi[n*2]   = i0; topi[n*2+1] = i1;
    topw[n*2]   = p0/ws; topw[n*2+1] = p1/ws;
}

// ---------------------------------------------------------------------------
// Deterministic pmean reduction (16 blocks, fixed tree)
// ---------------------------------------------------------------------------
__global__ void pmean_kernel(const float* __restrict__ probs, float* __restrict__ pmean)
{
    int e = blockIdx.x, tid = threadIdx.x;
    float s = 0.f;
    for (int t = tid; t < NTOK; t += 256) s += probs[t*EE + e];
    __shared__ float red[256];
    red[tid] = s;
    __syncthreads();
    for (int k = 128; k; k >>= 1) {
        if (tid < k) red[tid] += red[tid+k];
        __syncthreads();
    }
    if (tid == 0) pmean[e] = red[0] / (float)NTOK;
}

// ---------------------------------------------------------------------------
// Capacity position assignment
// ---------------------------------------------------------------------------
__global__ void assign_kernel(const int* __restrict__ topi,
                              const float* __restrict__ topw,
                              int* __restrict__ slot, int* __restrict__ keep,
                              float* __restrict__ wcomb, int* __restrict__ counts)
{
    int e = blockIdx.x;
    int tid = threadIdx.x;
    int lane = tid & 31, warp = tid >> 5;
    __shared__ int warpsum[8];
    int running = 0;
    for (int base = 0; base < NFLAT; base += 256) {
        int i = base + tid;
        int match = (topi[i] == e) ? 1 : 0;
        unsigned mask = __ballot_sync(0xffffffffu, match);
        if (lane == 0) warpsum[warp] = __popc(mask);
        __syncthreads();
        int wbase = 0, tot = 0;
        #pragma unroll
        for (int w = 0; w < 8; w++) {
            int c = warpsum[w];
            if (w < warp) wbase += c;
            tot += c;
        }
        if (match) {
            int pos = running + wbase + __popc(mask & ((1u << lane) - 1u));
            int kp = (pos < CAP) ? 1 : 0;
            slot[i]  = (pos < CAP-1) ? pos : (CAP-1);
            keep[i]  = kp;
            wcomb[i] = kp ? topw[i] : 0.f;
        }
        running += tot;
        __syncthreads();
    }
    if (tid == 0) counts[e] = running;
}

// ---------------------------------------------------------------------------
// Scatter tokens into expert buffers
// ---------------------------------------------------------------------------
__global__ void scatter_kernel(const int* __restrict__ topi,
                               const int* __restrict__ slot,
                               const int* __restrict__ keep,
                               const float* __restrict__ xn,
                               float* __restrict__ buf)
{
    int i = blockIdx.x;
    if (!keep[i]) return;
    int e = topi[i], s = slot[i], tok = i >> 1;
    const float4* src = (const float4*)(xn + (size_t)tok*DD);
    float4* dst = (float4*)(buf + ((size_t)e*CAP + s)*DD);
    dst[threadIdx.x] = src[threadIdx.x];
}

// ---------------------------------------------------------------------------
// Gather expert outputs + residual into x
// ---------------------------------------------------------------------------
__global__ void gather_kernel(const int* __restrict__ topi,
                              const int* __restrict__ slot,
                              const float* __restrict__ wcomb,
                              const float* __restrict__ yb,
                              float* __restrict__ x)
{
    int n = blockIdx.x;
    int t4 = threadIdx.x;
    float4* xp = (float4*)(x + (size_t)n*DD);
    float4 a = xp[t4];
    #pragma unroll
    for (int k = 0; k < 2; k++) {
        int i = n*2 + k;
        float w = wcomb[i];
        if (w != 0.f) {
            int e = topi[i], s = slot[i];
            const float4* yp = (const float4*)(yb + ((size_t)e*CAP + s)*DD);
            float4 yv = yp[t4];
            a.x += w*yv.x; a.y += w*yv.y; a.z += w*yv.z; a.w += w*yv.w;
        }
    }
    xp[t4] = a;
}

// ---------------------------------------------------------------------------
// aux = E * sum(frac * pmean); written at d_out[B*T*D]
// ---------------------------------------------------------------------------
__global__ void aux_kernel(const int* __restrict__ counts,
                           const float* __restrict__ pmean,
                           float* __restrict__ out, int out_size)
{
    if (threadIdx.x == 0 && out_size > NTOK*DD) {
        float s = 0.f;
        for (int e = 0; e < EE; e++)
            s += ((float)counts[e] / (float)NTOK) * pmean[e];
        out[NTOK*DD] = (float)EE * s;
    }
}

// ---------------------------------------------------------------------------
// ToU gate: sigmoid(xn . gw + gb) per token
// ---------------------------------------------------------------------------
__global__ void gate_kernel(const float* __restrict__ xn,
                            const float* __restrict__ gw,
                            const float* __restrict__ gb,
                            float* __restrict__ gate)
{
    int n = blockIdx.x, tid = threadIdx.x;
    const float4* xp = (const float4*)(xn + (size_t)n*DD);
    const float4* wp = (const float4*)gw;
    float4 xv = xp[tid], wv = wp[tid];
    float s = xv.x*wv.x + xv.y*wv.y + xv.z*wv.z + xv.w*wv.w;
    __shared__ float red[256];
    red[tid] = s;
    __syncthreads();
    for (int k = 128; k; k >>= 1) {
        if (tid < k) red[tid] += red[tid+k];
        __syncthreads();
    }
    if (tid == 0) gate[n] = 1.f / (1.f + __expf(-(red[0] + gb[0])));
}

// ---------------------------------------------------------------------------
// Softmax over 512 primitives (scale 1/16 folded in), in place
// ---------------------------------------------------------------------------
__global__ void softmax512_kernel(float* __restrict__ tl)
{
    int n = blockIdx.x, tid = threadIdx.x;
    float* row = tl + (size_t)n*NPRIM;
    float v0 = row[tid]       * 0.0625f;
    float v1 = row[tid + 256] * 0.0625f;
    __shared__ float red[256];
    red[tid] = fmaxf(v0, v1);
    __syncthreads();
    for (int s = 128; s; s >>= 1) {
        if (tid < s) red[tid] = fmaxf(red[tid], red[tid+s]);
        __syncthreads();
    }
    float mx = red[0];
    __syncthreads();
    v0 = __expf(v0 - mx); v1 = __expf(v1 - mx);
    red[tid] = v0 + v1;
    __syncthreads();
    for (int s = 128; s; s >>= 1) {
        if (tid < s) red[tid] += red[tid+s];
        __syncthreads();
    }
    float inv = 1.f / red[0];
    row[tid] = v0*inv; row[tid+256] = v1*inv;
}

// ---------------------------------------------------------------------------
// Host launch
// ---------------------------------------------------------------------------
extern "C" void kernel_launch(void* const* d_in, const int* in_sizes, int n_in,
                              void* d_out, int out_size)
{
    const float* x          = (const float*)d_in[0];
    const float* tou_embeds = (const float*)d_in[1];
    const float* norm1_w    = (const float*)d_in[2];
    const float* qkv_w      = (const float*)d_in[3];
    const float* attn_o_w   = (const float*)d_in[4];
    const float* norm2_w    = (const float*)d_in[5];
    const float* router_w   = (const float*)d_in[6];
    const float* moe_w1     = (const float*)d_in[7];
    const float* moe_w2     = (const float*)d_in[8];
    const float* norm3_w    = (const float*)d_in[9];
    const float* tou_q_w    = (const float*)d_in[10];
    const float* tou_k_w    = (const float*)d_in[11];
    const float* tou_v_w    = (const float*)d_in[12];
    const float* tou_o_w    = (const float*)d_in[13];
    const float* tou_gate_w = (const float*)d_in[14];
    const float* tou_gate_b = (const float*)d_in[15];

    float *gx, *gxn, *gqkv, *gattn, *glogits, *gprobs, *gtopw, *gwcomb,
          *gpmean, *gbuf, *gh, *gyb, *gtq, *gtk, *gtv, *gtl, *gtout, *ggate;
    int *gtopi, *gslot, *gkeep, *gcounts;
    cudaGetSymbolAddress((void**)&gx, g_x);
    cudaGetSymbolAddress((void**)&gxn, g_xn);
    cudaGetSymbolAddress((void**)&gqkv, g_qkv);
    cudaGetSymbolAddress((void**)&gattn, g_attn);
    cudaGetSymbolAddress((void**)&glogits, g_logits);
    cudaGetSymbolAddress((void**)&gprobs, g_probs);
    cudaGetSymbolAddress((void**)&gtopi, g_topi);
    cudaGetSymbolAddress((void**)&gtopw, g_topw);
    cudaGetSymbolAddress((void**)&gslot, g_slot);
    cudaGetSymbolAddress((void**)&gkeep, g_keep);
    cudaGetSymbolAddress((void**)&gwcomb, g_wcomb);
    cudaGetSymbolAddress((void**)&gcounts, g_counts);
    cudaGetSymbolAddress((void**)&gpmean, g_pmean);
    cudaGetSymbolAddress((void**)&gbuf, g_buf);
    cudaGetSymbolAddress((void**)&gh, g_h);
    cudaGetSymbolAddress((void**)&gyb, g_yb);
    cudaGetSymbolAddress((void**)&gtq, g_tq);
    cudaGetSymbolAddress((void**)&gtk, g_tk);
    cudaGetSymbolAddress((void**)&gtv, g_tv);
    cudaGetSymbolAddress((void**)&gtl, g_tl);
    cudaGetSymbolAddress((void**)&gtout, g_tout);
    cudaGetSymbolAddress((void**)&ggate, g_gate);

    // residual stream
    cudaMemcpyAsync(gx, x, (size_t)NTOK*DD*sizeof(float), cudaMemcpyDeviceToDevice);
    rope_table_kernel<<<TT*32/256, 256>>>();

    // ---- Block 1: RoPE attention ----
    rmsnorm_kernel<<<NTOK, 256>>>(x, norm1_w, gxn);
    gemm128<true,0><<<dim3(3*DD/128, NTOK/128, 1), 256>>>(gxn, qkv_w, gqkv,
        NTOK, 3*DD, DD, 0, 0, 0, nullptr);
    rope_kernel<<<NTOK, 256>>>(gqkv);
    flash_attn_tc<<<dim3(TT/64, BB*HH), 128>>>(gqkv, gattn);
    gemm128<true,1><<<dim3(DD/128, NTOK/128, 1), 256>>>(gattn, attn_o_w, gx,
        NTOK, DD, DD, 0, 0, 0, nullptr);

    // ---- Block 2: MoE ----
    rmsnorm_kernel<<<NTOK, 256>>>(gx, norm2_w, gxn);
    router_kernel<<<NTOK, 128>>>(gxn, router_w, glogits);
    top2_kernel<<<NTOK/128, 128>>>(glogits, gprobs, gtopi, gtopw);
    pmean_kernel<<<EE, 256>>>(gprobs, gpmean);
    assign_kernel<<<EE, 256>>>(gtopi, gtopw, gslot, gkeep, gwcomb, gcounts);
    cudaMemsetAsync(gbuf, 0, (size_t)EE*CAP*DD*sizeof(float));
    scatter_kernel<<<NFLAT, 256>>>(gtopi, gslot, gkeep, gxn, gbuf);
    gemm128<false,2><<<dim3(FF/128, CAP/128, EE), 256>>>(gbuf, moe_w1, gh,
        CAP, FF, DD, (long long)CAP*DD, (long long)DD*FF, (long long)CAP*FF, nullptr);
    gemm128<false,0><<<dim3(DD/128, CAP/128, EE), 256>>>(gh, moe_w2, gyb,
        CAP, DD, FF, (long long)CAP*FF, (long long)FF*DD, (long long)CAP*DD, nullptr);
    gather_kernel<<<NTOK, 256>>>(gtopi, gslot, gwcomb, gyb, gx);
    aux_kernel<<<1, 32>>>(gcounts, gpmean, (float*)d_out, out_size);

    // ---- Block 3: ToU cross-attention ----
    rmsnorm_kernel<<<NTOK, 256>>>(gx, norm3_w, gxn);
    gemm128<true,0><<<dim3(DP/128, NTOK/128, 1), 256>>>(gxn, tou_q_w, gtq,
        NTOK, DP, DD, 0, 0, 0, nullptr);
    gemm128<true,0><<<dim3(DP/128, NPRIM/128, 1), 256>>>(tou_embeds, tou_k_w, gtk,
        NPRIM, DP, DP, 0, 0, 0, nullptr);
    gemm128<true,0><<<dim3(DP/128, NPRIM/128, 1), 256>>>(tou_embeds, tou_v_w, gtv,
        NPRIM, DP, DP, 0, 0, 0, nullptr);
    gemm128<true,0><<<dim3(NPRIM/128, NTOK/128, 1), 256>>>(gtq, gtk, gtl,
        NTOK, NPRIM, DP, 0, 0, 0, nullptr);
    softmax512_kernel<<<NTOK, 256>>>(gtl);
    gemm128<false,0><<<dim3(DP/128, NTOK/128, 1), 256>>>(gtl, gtv, gtout,
        NTOK, DP, NPRIM, 0, 0, 0, nullptr);
    gate_kernel<<<NTOK, 256>>>(gxn, tou_gate_w, tou_gate_b, ggate);
    gemm128<true,3><<<dim3(DD/128, NTOK/128, 1), 256>>>(gtout, tou_o_w, gx,
        NTOK, DD, DP, 0, 0, 0, ggate);

    // output
    cudaMemcpyAsync(d_out, gx, (size_t)NTOK*DD*sizeof(float), cudaMemcpyDeviceToDevice);
}

// round 5
// speedup vs baseline: 3.6853x; 1.0505x over previous
#include <cuda_runtime.h>
#include <cuda_bf16.h>
#include <math.h>

// ---------------------------------------------------------------------------
// Problem constants
// ---------------------------------------------------------------------------
#define BB 2
#define TT 2048
#define DD 1024
#define HH 16
#define DH 64
#define NTOK (BB*TT)            // 4096
#define EE 16
#define KK 2
#define FF 2048
#define CAP 640
#define DP 256
#define NPRIM 512
#define NFLAT (NTOK*KK)         // 8192

// ---------------------------------------------------------------------------
// Scratch (device globals; no allocation allowed)
// ---------------------------------------------------------------------------
__device__ float g_x[NTOK*DD];
__device__ float g_xn[NTOK*DD];
__device__ float g_qkv[NTOK*3*DD];
__device__ float g_attn[NTOK*DD];
__device__ float g_logits[NTOK*EE];
__device__ float g_probs[NTOK*EE];
__device__ int   g_topi[NFLAT];
__device__ float g_topw[NFLAT];
__device__ int   g_slot[NFLAT];
__device__ int   g_keep[NFLAT];
__device__ float g_wcomb[NFLAT];
__device__ int   g_counts[EE];
__device__ float g_pmean[EE];
__device__ float g_buf[EE*CAP*DD];
__device__ float g_h[EE*CAP*FF];
__device__ float g_yb[EE*CAP*DD];
__device__ float g_tq[NTOK*DP];
__device__ float g_tk[NPRIM*DP];
__device__ float g_tv[NPRIM*DP];
__device__ float g_tl[NTOK*NPRIM];
__device__ float g_tout[NTOK*DP];
__device__ float g_gate[NTOK];
__device__ float g_ropec[TT*32];
__device__ float g_ropes[TT*32];

// ---------------------------------------------------------------------------
// TF32 helpers
// ---------------------------------------------------------------------------
__device__ __forceinline__ unsigned f2tf(float x)
{
    unsigned r;
    asm("cvt.rna.tf32.f32 %0, %1;" : "=r"(r) : "f"(x));
    return r;
}

__device__ __forceinline__ void mma_tf32(float c[4], const unsigned a[4], const unsigned b[2])
{
    asm volatile(
        "mma.sync.aligned.m16n8k8.row.col.f32.tf32.tf32.f32 "
        "{%0,%1,%2,%3},{%4,%5,%6,%7},{%8,%9},{%0,%1,%2,%3};"
        : "+f"(c[0]), "+f"(c[1]), "+f"(c[2]), "+f"(c[3])
        : "r"(a[0]), "r"(a[1]), "r"(a[2]), "r"(a[3]),
          "r"(b[0]), "r"(b[1]));
}

__device__ __forceinline__ void cp16(void* smem_dst, const void* gptr)
{
    unsigned saddr = (unsigned)__cvta_generic_to_shared(smem_dst);
    asm volatile("cp.async.cg.shared.global [%0], [%1], 16;\n"
                 :: "r"(saddr), "l"(gptr));
}
__device__ __forceinline__ void cp_commit()  { asm volatile("cp.async.commit_group;\n"); }
__device__ __forceinline__ void cp_wait2()   { asm volatile("cp.async.wait_group 2;\n"); }
__device__ __forceinline__ void cp_wait1()   { asm volatile("cp.async.wait_group 1;\n"); }
__device__ __forceinline__ void cp_wait0()   { asm volatile("cp.async.wait_group 0;\n"); }

// ---------------------------------------------------------------------------
// RMSNorm: one block per token, 256 threads, float4
// ---------------------------------------------------------------------------
__global__ void rmsnorm_kernel(const float* __restrict__ x,
                               const float* __restrict__ w,
                               float* __restrict__ out)
{
    int n = blockIdx.x;
    int tid = threadIdx.x;
    const float4* xp = (const float4*)(x + (size_t)n*DD);
    float4 xv = xp[tid];
    float ss = xv.x*xv.x + xv.y*xv.y + xv.z*xv.z + xv.w*xv.w;
    __shared__ float red[256];
    red[tid] = ss;
    __syncthreads();
    for (int s = 128; s; s >>= 1) {
        if (tid < s) red[tid] += red[tid+s];
        __syncthreads();
    }
    float scale = rsqrtf(red[0] / (float)DD + 1e-6f);
    const float4* wp = (const float4*)w;
    float4 wv = wp[tid];
    float4* op = (float4*)(out + (size_t)n*DD);
    op[tid] = make_float4(xv.x*scale*wv.x, xv.y*scale*wv.y,
                          xv.z*scale*wv.z, xv.w*scale*wv.w);
}

// ---------------------------------------------------------------------------
// TF32 tensor-core GEMM: 4-stage cp.async pipeline, ONE barrier/iteration.
//   C[M,N] = A[M,K] * op(B)
//   BT=true : B stored [N,K] row-major; BT=false: [K,N] row-major
// EPI: 0=store, 1=C+=, 2=silu store, 3=C += gate[row]*v
// Dynamic smem: As[4][128][20] + (Bs[4][128][20] | Bf[4][16][136])
// ---------------------------------------------------------------------------
#define AS_STR 20
#define BF_STR 136
#define NSTG 4
#define AS_TILE (128*AS_STR)          // words per A stage
#define BF_TILE (16*BF_STR)           // words per Bf stage

template<bool BT, int EPI>
__global__ __launch_bounds__(256, 2)
void gemm128(const float* __restrict__ A, const float* __restrict__ Bm,
             float* __restrict__ C, int M, int N, int K,
             long long sA, long long sB, long long sC,
             const float* __restrict__ gate)
{
    A  += blockIdx.z * sA;
    Bm += blockIdx.z * sB;
    C  += blockIdx.z * sC;

    extern __shared__ unsigned smem_dyn[];
    unsigned* AsP = smem_dyn;                       // [NSTG][128][AS_STR]
    unsigned* BsP = smem_dyn + NSTG*AS_TILE;        // BT : [NSTG][128][AS_STR]
    unsigned* BfP = smem_dyn + NSTG*AS_TILE;        // !BT: [NSTG][16][BF_STR]

    const int tid  = threadIdx.x;
    const int lane = tid & 31;
    const int warp = tid >> 5;
    const int lr   = lane >> 2;
    const int lq   = lane & 3;
    const int wm   = warp & 1, wn = warp >> 1;
    const int m0   = wm * 64, n0 = wn * 32;
    const int row0 = blockIdx.y * 128, col0 = blockIdx.x * 128;

    // chunk decomposition (each thread: 2 chunks of A, 2 of B)
    const int c0i = tid, c1i = tid + 256;
    const int ar0 = c0i >> 2, ac0 = (c0i & 3) * 4;
    const int ar1 = c1i >> 2, ac1 = (c1i & 3) * 4;
    const int fk0 = c0i >> 5, fn0 = (c0i & 31) * 4;
    const int fk1 = c1i >> 5, fn1 = (c1i & 31) * 4;

    const int nIter = K >> 4;

    // issue one stage's loads + commit
    auto issue = [&](int stg, int k0) {
        cp16(&AsP[stg*AS_TILE + ar0*AS_STR + ac0], A + (size_t)(row0 + ar0) * K + k0 + ac0);
        cp16(&AsP[stg*AS_TILE + ar1*AS_STR + ac1], A + (size_t)(row0 + ar1) * K + k0 + ac1);
        if constexpr (BT) {
            cp16(&BsP[stg*AS_TILE + ar0*AS_STR + ac0], Bm + (size_t)(col0 + ar0) * K + k0 + ac0);
            cp16(&BsP[stg*AS_TILE + ar1*AS_STR + ac1], Bm + (size_t)(col0 + ar1) * K + k0 + ac1);
        } else {
            cp16(&BfP[stg*BF_TILE + fk0*BF_STR + fn0], Bm + (size_t)(k0 + fk0) * N + col0 + fn0);
            cp16(&BfP[stg*BF_TILE + fk1*BF_STR + fn1], Bm + (size_t)(k0 + fk1) * N + col0 + fn1);
        }
        cp_commit();
    };

    // prologue: 3 stages in flight
    issue(0, 0);
    if (nIter > 1) issue(1, 16);
    if (nIter > 2) issue(2, 32);

    float c[4][4][4];
    #pragma unroll
    for (int mt = 0; mt < 4; mt++)
        #pragma unroll
        for (int nt = 0; nt < 4; nt++)
            #pragma unroll
            for (int i = 0; i < 4; i++) c[mt][nt][i] = 0.f;

    for (int it = 0; it < nIter; it++) {
        // pending groups: it .. min(it+2, nIter-1); need group `it` done
        if (it + 2 < nIter)      cp_wait2();
        else if (it + 1 < nIter) cp_wait1();
        else                     cp_wait0();
        __syncthreads();

        if (it + 3 < nIter) issue((it + 3) & 3, (it + 3) << 4);

        const int st = it & 3;
        const unsigned* Asb = AsP + st * AS_TILE;
        const unsigned* Bsb = BsP + st * AS_TILE;
        const unsigned* Bfb = BfP + st * BF_TILE;

        #pragma unroll
        for (int ks = 0; ks < 2; ks++) {
            const int kb = ks * 8;
            unsigned a[4][4], b[4][2];
            #pragma unroll
            for (int mt = 0; mt < 4; mt++) {
                int r = m0 + mt * 16 + lr;
                a[mt][0] = Asb[r*AS_STR + kb + lq];
                a[mt][1] = Asb[(r+8)*AS_STR + kb + lq];
                a[mt][2] = Asb[r*AS_STR + kb + 4 + lq];
                a[mt][3] = Asb[(r+8)*AS_STR + kb + 4 + lq];
            }
            #pragma unroll
            for (int nt = 0; nt < 4; nt++) {
                int cn = n0 + nt * 8 + lr;
                if constexpr (BT) {
                    b[nt][0] = Bsb[cn*AS_STR + kb + lq];
                    b[nt][1] = Bsb[cn*AS_STR + kb + 4 + lq];
                } else {
                    b[nt][0] = Bfb[(kb+lq)*BF_STR + cn];
                    b[nt][1] = Bfb[(kb+4+lq)*BF_STR + cn];
                }
            }
            #pragma unroll
            for (int mt = 0; mt < 4; mt++)
                #pragma unroll
                for (int nt = 0; nt < 4; nt++)
                    mma_tf32(c[mt][nt], a[mt], b[nt]);
        }
    }

    // epilogue (float2 stores)
    #pragma unroll
    for (int mt = 0; mt < 4; mt++) {
        int r0g = row0 + m0 + mt * 16 + lr;
        int r1g = r0g + 8;
        float g0 = (EPI == 3) ? gate[r0g] : 0.f;
        float g1 = (EPI == 3) ? gate[r1g] : 0.f;
        #pragma unroll
        for (int nt = 0; nt < 4; nt++) {
            int cg = col0 + n0 + nt * 8 + 2 * lq;
            float2* p0 = (float2*)&C[(size_t)r0g * N + cg];
            float2* p1 = (float2*)&C[(size_t)r1g * N + cg];
            float v0 = c[mt][nt][0], v1 = c[mt][nt][1];
            float v2 = c[mt][nt][2], v3 = c[mt][nt][3];
            if (EPI == 0) {
                *p0 = make_float2(v0, v1);
                *p1 = make_float2(v2, v3);
            } else if (EPI == 1) {
                float2 o0 = *p0, o1 = *p1;
                *p0 = make_float2(o0.x + v0, o0.y + v1);
                *p1 = make_float2(o1.x + v2, o1.y + v3);
            } else if (EPI == 2) {
                *p0 = make_float2(v0 / (1.f + __expf(-v0)), v1 / (1.f + __expf(-v1)));
                *p1 = make_float2(v2 / (1.f + __expf(-v2)), v3 / (1.f + __expf(-v3)));
            } else {
                float2 o0 = *p0, o1 = *p1;
                *p0 = make_float2(o0.x + g0 * v0, o0.y + g0 * v1);
                *p1 = make_float2(o1.x + g1 * v2, o1.y + g1 * v3);
            }
        }
    }
}

#define SMEM_BT ((NSTG*AS_TILE + NSTG*AS_TILE) * 4)   // 81920
#define SMEM_KN ((NSTG*AS_TILE + NSTG*BF_TILE) * 4)   // 75776

// ---------------------------------------------------------------------------
// RoPE table + apply
// ---------------------------------------------------------------------------
__global__ void rope_table_kernel()
{
    int idx = blockIdx.x * 256 + threadIdx.x;     // TT*32 total
    int t = idx >> 5, i = idx & 31;
    float inv = powf(10000.f, -(float)i / 32.f);
    float s, c;
    sincosf((float)t * inv, &s, &c);
    g_ropec[idx] = c;
    g_ropes[idx] = s;
}

__global__ void rope_kernel(float* __restrict__ qkv)
{
    int n = blockIdx.x;
    int t = n & (TT-1);
    for (int p = threadIdx.x; p < 1024; p += 256) {
        int which = p >> 9;
        int rem = p & 511;
        int h = rem >> 5;
        int i = rem & 31;
        float c = g_ropec[t*32 + i];
        float s = g_ropes[t*32 + i];
        size_t base = (size_t)n*3072 + (size_t)which*1024 + h*64 + i;
        float u1 = qkv[base], u2 = qkv[base+32];
        qkv[base]    = u1*c - u2*s;
        qkv[base+32] = u2*c + u1*s;
    }
}

// ---------------------------------------------------------------------------
// Tensor-core flash attention (unchanged)
// ---------------------------------------------------------------------------
#define QS_STR 68
#define VS_STR 36
#define PS_STR 36

__global__ __launch_bounds__(128)
void flash_attn_tc(const float* __restrict__ qkv, float* __restrict__ out)
{
    __shared__ unsigned Qs[64][QS_STR];
    __shared__ unsigned Ks[32][QS_STR];
    __shared__ unsigned Vts[64][VS_STR];
    __shared__ unsigned Ps[64][PS_STR];

    const int qb = blockIdx.x, bh = blockIdx.y;
    const int b = bh >> 4, h = bh & 15;
    const int tid = threadIdx.x, lane = tid & 31, warp = tid >> 5;
    const int lr = lane >> 2, lq = lane & 3;
    const int m0 = warp * 16;
    const int q0 = qb * 64;

    for (int i = tid; i < 64*64; i += 128) {
        int r = i >> 6, d = i & 63;
        Qs[r][d] = f2tf(qkv[(size_t)(b*TT + q0 + r)*3072 + h*64 + d] * 0.125f);
    }

    float mrow0 = -1e30f, mrow1 = -1e30f;
    float lrow0 = 0.f,    lrow1 = 0.f;
    float o[8][4];
    #pragma unroll
    for (int nt = 0; nt < 8; nt++)
        #pragma unroll
        for (int i = 0; i < 4; i++) o[nt][i] = 0.f;

    const int rg0 = q0 + m0 + lr, rg1 = rg0 + 8;
    const int ntiles = 2*qb + 2;

    for (int kb = 0; kb < ntiles; kb++) {
        __syncthreads();
        for (int i = tid; i < 32*64; i += 128) {
            int r = i >> 6, d = i & 63;
            size_t base = (size_t)(b*TT + kb*32 + r)*3072 + h*64 + d;
            Ks[r][d]  = f2tf(qkv[base + 1024]);
            Vts[d][r] = f2tf(qkv[base + 2048]);
        }
        __syncthreads();

        float s[4][4];
        #pragma unroll
        for (int nt = 0; nt < 4; nt++)
            #pragma unroll
            for (int i = 0; i < 4; i++) s[nt][i] = 0.f;
        #pragma unroll
        for (int kk = 0; kk < 8; kk++) {
            unsigned a[4];
            a[0] = Qs[m0+lr][kk*8+lq];
            a[1] = Qs[m0+lr+8][kk*8+lq];
            a[2] = Qs[m0+lr][kk*8+lq+4];
            a[3] = Qs[m0+lr+8][kk*8+lq+4];
            #pragma unroll
            for (int nt = 0; nt < 4; nt++) {
                unsigned bf[2] = { Ks[nt*8+lr][kk*8+lq], Ks[nt*8+lr][kk*8+lq+4] };
                mma_tf32(s[nt], a, bf);
            }
        }

        if (kb >= 2*qb) {
            #pragma unroll
            for (int nt = 0; nt < 4; nt++) {
                int c0 = kb*32 + nt*8 + 2*lq;
                if (c0   > rg0) s[nt][0] = -1e30f;
                if (c0+1 > rg0) s[nt][1] = -1e30f;
                if (c0   > rg1) s[nt][2] = -1e30f;
                if (c0+1 > rg1) s[nt][3] = -1e30f;
            }
        }

        float mx0 = -1e30f, mx1 = -1e30f;
        #pragma unroll
        for (int nt = 0; nt < 4; nt++) {
            mx0 = fmaxf(mx0, fmaxf(s[nt][0], s[nt][1]));
            mx1 = fmaxf(mx1, fmaxf(s[nt][2], s[nt][3]));
        }
        mx0 = fmaxf(mx0, __shfl_xor_sync(0xffffffffu, mx0, 1));
        mx0 = fmaxf(mx0, __shfl_xor_sync(0xffffffffu, mx0, 2));
        mx1 = fmaxf(mx1, __shfl_xor_sync(0xffffffffu, mx1, 1));
        mx1 = fmaxf(mx1, __shfl_xor_sync(0xffffffffu, mx1, 2));
        float mn0 = fmaxf(mrow0, mx0), mn1 = fmaxf(mrow1, mx1);
        float corr0 = __expf(mrow0 - mn0), corr1 = __expf(mrow1 - mn1);
        float sum0 = 0.f, sum1 = 0.f;
        #pragma unroll
        for (int nt = 0; nt < 4; nt++) {
            s[nt][0] = __expf(s[nt][0] - mn0);
            s[nt][1] = __expf(s[nt][1] - mn0);
            s[nt][2] = __expf(s[nt][2] - mn1);
            s[nt][3] = __expf(s[nt][3] - mn1);
            sum0 += s[nt][0] + s[nt][1];
            sum1 += s[nt][2] + s[nt][3];
        }
        sum0 += __shfl_xor_sync(0xffffffffu, sum0, 1);
        sum0 += __shfl_xor_sync(0xffffffffu, sum0, 2);
        sum1 += __shfl_xor_sync(0xffffffffu, sum1, 1);
        sum1 += __shfl_xor_sync(0xffffffffu, sum1, 2);
        lrow0 = lrow0*corr0 + sum0;
        lrow1 = lrow1*corr1 + sum1;
        mrow0 = mn0; mrow1 = mn1;
        #pragma unroll
        for (int nt = 0; nt < 8; nt++) {
            o[nt][0] *= corr0; o[nt][1] *= corr0;
            o[nt][2] *= corr1; o[nt][3] *= corr1;
        }

        #pragma unroll
        for (int nt = 0; nt < 4; nt++) {
            Ps[m0+lr][nt*8+2*lq]     = f2tf(s[nt][0]);
            Ps[m0+lr][nt*8+2*lq+1]   = f2tf(s[nt][1]);
            Ps[m0+lr+8][nt*8+2*lq]   = f2tf(s[nt][2]);
            Ps[m0+lr+8][nt*8+2*lq+1] = f2tf(s[nt][3]);
        }
        __syncwarp();

        #pragma unroll
        for (int ks = 0; ks < 4; ks++) {
            unsigned a[4];
            a[0] = Ps[m0+lr][ks*8+lq];
            a[1] = Ps[m0+lr+8][ks*8+lq];
            a[2] = Ps[m0+lr][ks*8+lq+4];
            a[3] = Ps[m0+lr+8][ks*8+lq+4];
            #pragma unroll
            for (int nt = 0; nt < 8; nt++) {
                unsigned bf[2] = { Vts[nt*8+lr][ks*8+lq], Vts[nt*8+lr][ks*8+lq+4] };
                mma_tf32(o[nt], a, bf);
            }
        }
    }

    float inv0 = 1.f / lrow0, inv1 = 1.f / lrow1;
    #pragma unroll
    for (int nt = 0; nt < 8; nt++) {
        int cg = h*64 + nt*8 + 2*lq;
        size_t base0 = (size_t)(b*TT + rg0)*DD + cg;
        size_t base1 = (size_t)(b*TT + rg1)*DD + cg;
        out[base0]   = o[nt][0]*inv0;
        out[base0+1] = o[nt][1]*inv0;
        out[base1]   = o[nt][2]*inv1;
        out[base1+1] = o[nt][3]*inv1;
    }
}

// ---------------------------------------------------------------------------
// Router logits: block per token (128 thr, 4 warps x 4 experts)
// ---------------------------------------------------------------------------
__global__ void router_kernel(const float* __restrict__ xn,
                              const float* __restrict__ rw,
                              float* __restrict__ logits)
{
    int n = blockIdx.x;
    int warp = threadIdx.x >> 5, lane = threadIdx.x & 31;
    const float* xp = xn + (size_t)n*DD;
    for (int j = 0; j < 4; j++) {
        int e = warp*4 + j;
        const float* wp = rw + (size_t)e*DD;
        float s = 0.f;
        for (int i = lane; i < DD; i += 32) s += xp[i]*wp[i];
        #pragma unroll
        for (int off = 16; off; off >>= 1) s += __shfl_xor_sync(0xffffffffu, s, off);
        if (lane == 0) logits[n*EE + e] = s;
    }
}

// ---------------------------------------------------------------------------
// Softmax over 16 experts + top-2
// ---------------------------------------------------------------------------
__global__ void top2_kernel(const float* __restrict__ logits,
                            float* __restrict__ probs,
                            int* __restrict__ topi, float* __restrict__ topw)
{
    int n = blockIdx.x*blockDim.x + threadIdx.x;
    if (n >= NTOK) return;
    float l[EE];
    float mx = -1e30f;
    #pragma unroll
    for (int e = 0; e < EE; e++) { l[e] = logits[n*EE+e]; mx = fmaxf(mx, l[e]); }
    float sum = 0.f;
    #pragma unroll
    for (int e = 0; e < EE; e++) { l[e] = __expf(l[e]-mx); sum += l[e]; }
    float inv = 1.f/sum;
    #pragma unroll
    for (int e = 0; e < EE; e++) { l[e] *= inv; probs[n*EE+e] = l[e]; }
    int i0 = 0; float p0 = l[0];
    #pragma unroll
    for (int e = 1; e < EE; e++) if (l[e] > p0) { p0 = l[e]; i0 = e; }
    int i1 = (i0 == 0) ? 1 : 0; float p1 = l[i1];
    #pragma unroll
    for (int e = 0; e < EE; e++) if (e != i0 && l[e] > p1) { p1 = l[e]; i1 = e; }
    float ws = p0 + p1;
    topi[n*2]   = i0; topi[n*2+1] = i1;
    topw[n*2]   = p0/ws; topw[n*2+1] = p1/ws;
}

// ---------------------------------------------------------------------------
// Deterministic pmean reduction (16 blocks, fixed tree)
// ---------------------------------------------------------------------------
__global__ void pmean_kernel(const float* __restrict__ probs, float* __restrict__ pmean)
{
    int e = blockIdx.x, tid = threadIdx.x;
    float s = 0.f;
    for (int t = tid; t < NTOK; t += 256) s += probs[t*EE + e];
    __shared__ float red[256];
    red[tid] = s;
    __syncthreads();
    for (int k = 128; k; k >>= 1) {
        if (tid < k) red[tid] += red[tid+k];
        __syncthreads();
    }
    if (tid == 0) pmean[e] = red[0] / (float)NTOK;
}

// ---------------------------------------------------------------------------
// Capacity position assignment
// ---------------------------------------------------------------------------
__global__ void assign_kernel(const int* __restrict__ topi,
                              const float* __restrict__ topw,
                              int* __restrict__ slot, int* __restrict__ keep,
                              float* __restrict__ wcomb, int* __restrict__ counts)
{
    int e = blockIdx.x;
    int tid = threadIdx.x;
    int lane = tid & 31, warp = tid >> 5;
    __shared__ int warpsum[8];
    int running = 0;
    for (int base = 0; base < NFLAT; base += 256) {
        int i = base + tid;
        int match = (topi[i] == e) ? 1 : 0;
        unsigned mask = __ballot_sync(0xffffffffu, match);
        if (lane == 0) warpsum[warp] = __popc(mask);
        __syncthreads();
        int wbase = 0, tot = 0;
        #pragma unroll
        for (int w = 0; w < 8; w++) {
            int c = warpsum[w];
            if (w < warp) wbase += c;
            tot += c;
        }
        if (match) {
            int pos = running + wbase + __popc(mask & ((1u << lane) - 1u));
            int kp = (pos < CAP) ? 1 : 0;
            slot[i]  = (pos < CAP-1) ? pos : (CAP-1);
            keep[i]  = kp;
            wcomb[i] = kp ? topw[i] : 0.f;
        }
        running += tot;
        __syncthreads();
    }
    if (tid == 0) counts[e] = running;
}

// ---------------------------------------------------------------------------
// Scatter tokens into expert buffers
// ---------------------------------------------------------------------------
__global__ void scatter_kernel(const int* __restrict__ topi,
                               const int* __restrict__ slot,
                               const int* __restrict__ keep,
                               const float* __restrict__ xn,
                               float* __restrict__ buf)
{
    int i = blockIdx.x;
    if (!keep[i]) return;
    int e = topi[i], s = slot[i], tok = i >> 1;
    const float4* src = (const float4*)(xn + (size_t)tok*DD);
    float4* dst = (float4*)(buf + ((size_t)e*CAP + s)*DD);
    dst[threadIdx.x] = src[threadIdx.x];
}

// ---------------------------------------------------------------------------
// Gather expert outputs + residual into x
// ---------------------------------------------------------------------------
__global__ void gather_kernel(const int* __restrict__ topi,
                              const int* __restrict__ slot,
                              const float* __restrict__ wcomb,
                              const float* __restrict__ yb,
                              float* __restrict__ x)
{
    int n = blockIdx.x;
    int t4 = threadIdx.x;
    float4* xp = (float4*)(x + (size_t)n*DD);
    float4 a = xp[t4];
    #pragma unroll
    for (int k = 0; k < 2; k++) {
        int i = n*2 + k;
        float w = wcomb[i];
        if (w != 0.f) {
            int e = topi[i], s = slot[i];
            const float4* yp = (const float4*)(yb + ((size_t)e*CAP + s)*DD);
            float4 yv = yp[t4];
            a.x += w*yv.x; a.y += w*yv.y; a.z += w*yv.z; a.w += w*yv.w;
        }
    }
    xp[t4] = a;
}

// ---------------------------------------------------------------------------
// aux = E * sum(frac * pmean); written at d_out[B*T*D]
// ---------------------------------------------------------------------------
__global__ void aux_kernel(const int* __restrict__ counts,
                           const float* __restrict__ pmean,
                           float* __restrict__ out, int out_size)
{
    if (threadIdx.x == 0 && out_size > NTOK*DD) {
        float s = 0.f;
        for (int e = 0; e < EE; e++)
            s += ((float)counts[e] / (float)NTOK) * pmean[e];
        out[NTOK*DD] = (float)EE * s;
    }
}

// ---------------------------------------------------------------------------
// ToU gate: sigmoid(xn . gw + gb) per token
// ---------------------------------------------------------------------------
__global__ void gate_kernel(const float* __restrict__ xn,
                            const float* __restrict__ gw,
                            const float* __restrict__ gb,
                            float* __restrict__ gate)
{
    int n = blockIdx.x, tid = threadIdx.x;
    const float4* xp = (const float4*)(xn + (size_t)n*DD);
    const float4* wp = (const float4*)gw;
    float4 xv = xp[tid], wv = wp[tid];
    float s = xv.x*wv.x + xv.y*wv.y + xv.z*wv.z + xv.w*wv.w;
    __shared__ float red[256];
    red[tid] = s;
    __syncthreads();
    for (int k = 128; k; k >>= 1) {
        if (tid < k) red[tid] += red[tid+k];
        __syncthreads();
    }
    if (tid == 0) gate[n] = 1.f / (1.f + __expf(-(red[0] + gb[0])));
}

// ---------------------------------------------------------------------------
// Softmax over 512 primitives (scale 1/16 folded in), in place
// ---------------------------------------------------------------------------
__global__ void softmax512_kernel(float* __restrict__ tl)
{
    int n = blockIdx.x, tid = threadIdx.x;
    float* row = tl + (size_t)n*NPRIM;
    float v0 = row[tid]       * 0.0625f;
    float v1 = row[tid + 256] * 0.0625f;
    __shared__ float red[256];
    red[tid] = fmaxf(v0, v1);
    __syncthreads();
    for (int s = 128; s; s >>= 1) {
        if (tid < s) red[tid] = fmaxf(red[tid], red[tid+s]);
        __syncthreads();
    }
    float mx = red[0];
    __syncthreads();
    v0 = __expf(v0 - mx); v1 = __expf(v1 - mx);
    red[tid] = v0 + v1;
    __syncthreads();
    for (int s = 128; s; s >>= 1) {
        if (tid < s) red[tid] += red[tid+s];
        __syncthreads();
    }
    float inv = 1.f / red[0];
    row[tid] = v0*inv; row[tid+256] = v1*inv;
}

// ---------------------------------------------------------------------------
// Host launch
// ---------------------------------------------------------------------------
extern "C" void kernel_launch(void* const* d_in, const int* in_sizes, int n_in,
                              void* d_out, int out_size)
{
    const float* x          = (const float*)d_in[0];
    const float* tou_embeds = (const float*)d_in[1];
    const float* norm1_w    = (const float*)d_in[2];
    const float* qkv_w      = (const float*)d_in[3];
    const float* attn_o_w   = (const float*)d_in[4];
    const float* norm2_w    = (const float*)d_in[5];
    const float* router_w   = (const float*)d_in[6];
    const float* moe_w1     = (const float*)d_in[7];
    const float* moe_w2     = (const float*)d_in[8];
    const float* norm3_w    = (const float*)d_in[9];
    const float* tou_q_w    = (const float*)d_in[10];
    const float* tou_k_w    = (const float*)d_in[11];
    const float* tou_v_w    = (const float*)d_in[12];
    const float* tou_o_w    = (const float*)d_in[13];
    const float* tou_gate_w = (const float*)d_in[14];
    const float* tou_gate_b = (const float*)d_in[15];

    // raise dynamic-smem limits (host-side attribute, not an allocation)
    cudaFuncSetAttribute(gemm128<true,0>,  cudaFuncAttributeMaxDynamicSharedMemorySize, SMEM_BT);
    cudaFuncSetAttribute(gemm128<true,1>,  cudaFuncAttributeMaxDynamicSharedMemorySize, SMEM_BT);
    cudaFuncSetAttribute(gemm128<true,3>,  cudaFuncAttributeMaxDynamicSharedMemorySize, SMEM_BT);
    cudaFuncSetAttribute(gemm128<false,0>, cudaFuncAttributeMaxDynamicSharedMemorySize, SMEM_KN);
    cudaFuncSetAttribute(gemm128<false,2>, cudaFuncAttributeMaxDynamicSharedMemorySize, SMEM_KN);

    float *gx, *gxn, *gqkv, *gattn, *glogits, *gprobs, *gtopw, *gwcomb,
          *gpmean, *gbuf, *gh, *gyb, *gtq, *gtk, *gtv, *gtl, *gtout, *ggate;
    int *gtopi, *gslot, *gkeep, *gcounts;
    cudaGetSymbolAddress((void**)&gx, g_x);
    cudaGetSymbolAddress((void**)&gxn, g_xn);
    cudaGetSymbolAddress((void**)&gqkv, g_qkv);
    cudaGetSymbolAddress((void**)&gattn, g_attn);
    cudaGetSymbolAddress((void**)&glogits, g_logits);
    cudaGetSymbolAddress((void**)&gprobs, g_probs);
    cudaGetSymbolAddress((void**)&gtopi, g_topi);
    cudaGetSymbolAddress((void**)&gtopw, g_topw);
    cudaGetSymbolAddress((void**)&gslot, g_slot);
    cudaGetSymbolAddress((void**)&gkeep, g_keep);
    cudaGetSymbolAddress((void**)&gwcomb, g_wcomb);
    cudaGetSymbolAddress((void**)&gcounts, g_counts);
    cudaGetSymbolAddress((void**)&gpmean, g_pmean);
    cudaGetSymbolAddress((void**)&gbuf, g_buf);
    cudaGetSymbolAddress((void**)&gh, g_h);
    cudaGetSymbolAddress((void**)&gyb, g_yb);
    cudaGetSymbolAddress((void**)&gtq, g_tq);
    cudaGetSymbolAddress((void**)&gtk, g_tk);
    cudaGetSymbolAddress((void**)&gtv, g_tv);
    cudaGetSymbolAddress((void**)&gtl, g_tl);
    cudaGetSymbolAddress((void**)&gtout, g_tout);
    cudaGetSymbolAddress((void**)&ggate, g_gate);

    // residual stream
    cudaMemcpyAsync(gx, x, (size_t)NTOK*DD*sizeof(float), cudaMemcpyDeviceToDevice);
    rope_table_kernel<<<TT*32/256, 256>>>();

    // ---- Block 1: RoPE attention ----
    rmsnorm_kernel<<<NTOK, 256>>>(x, norm1_w, gxn);
    gemm128<true,0><<<dim3(3*DD/128, NTOK/128, 1), 256, SMEM_BT>>>(gxn, qkv_w, gqkv,
        NTOK, 3*DD, DD, 0, 0, 0, nullptr);
    rope_kernel<<<NTOK, 256>>>(gqkv);
    flash_attn_tc<<<dim3(TT/64, BB*HH), 128>>>(gqkv, gattn);
    gemm128<true,1><<<dim3(DD/128, NTOK/128, 1), 256, SMEM_BT>>>(gattn, attn_o_w, gx,
        NTOK, DD, DD, 0, 0, 0, nullptr);

    // ---- Block 2: MoE ----
    rmsnorm_kernel<<<NTOK, 256>>>(gx, norm2_w, gxn);
    router_kernel<<<NTOK, 128>>>(gxn, router_w, glogits);
    top2_kernel<<<NTOK/128, 128>>>(glogits, gprobs, gtopi, gtopw);
    pmean_kernel<<<EE, 256>>>(gprobs, gpmean);
    assign_kernel<<<EE, 256>>>(gtopi, gtopw, gslot, gkeep, gwcomb, gcounts);
    cudaMemsetAsync(gbuf, 0, (size_t)EE*CAP*DD*sizeof(float));
    scatter_kernel<<<NFLAT, 256>>>(gtopi, gslot, gkeep, gxn, gbuf);
    gemm128<false,2><<<dim3(FF/128, CAP/128, EE), 256, SMEM_KN>>>(gbuf, moe_w1, gh,
        CAP, FF, DD, (long long)CAP*DD, (long long)DD*FF, (long long)CAP*FF, nullptr);
    gemm128<false,0><<<dim3(DD/128, CAP/128, EE), 256, SMEM_KN>>>(gh, moe_w2, gyb,
        CAP, DD, FF, (long long)CAP*FF, (long long)FF*DD, (long long)CAP*DD, nullptr);
    gather_kernel<<<NTOK, 256>>>(gtopi, gslot, gwcomb, gyb, gx);
    aux_kernel<<<1, 32>>>(gcounts, gpmean, (float*)d_out, out_size);

    // ---- Block 3: ToU cross-attention ----
    rmsnorm_kernel<<<NTOK, 256>>>(gx, norm3_w, gxn);
    gemm128<true,0><<<dim3(DP/128, NTOK/128, 1), 256, SMEM_BT>>>(gxn, tou_q_w, gtq,
        NTOK, DP, DD, 0, 0, 0, nullptr);
    gemm128<true,0><<<dim3(DP/128, NPRIM/128, 1), 256, SMEM_BT>>>(tou_embeds, tou_k_w, gtk,
        NPRIM, DP, DP, 0, 0, 0, nullptr);
    gemm128<true,0><<<dim3(DP/128, NPRIM/128, 1), 256, SMEM_BT>>>(tou_embeds, tou_v_w, gtv,
        NPRIM, DP, DP, 0, 0, 0, nullptr);
    gemm128<true,0><<<dim3(NPRIM/128, NTOK/128, 1), 256, SMEM_BT>>>(gtq, gtk, gtl,
        NTOK, NPRIM, DP, 0, 0, 0, nullptr);
    softmax512_kernel<<<NTOK, 256>>>(gtl);
    gemm128<false,0><<<dim3(DP/128, NTOK/128, 1), 256, SMEM_KN>>>(gtl, gtv, gtout,
        NTOK, DP, NPRIM, 0, 0, 0, nullptr);
    gate_kernel<<<NTOK, 256>>>(gxn, tou_gate_w, tou_gate_b, ggate);
    gemm128<true,3><<<dim3(DD/128, NTOK/128, 1), 256, SMEM_BT>>>(gtout, tou_o_w, gx,
        NTOK, DD, DP, 0, 0, 0, ggate);

    // output
    cudaMemcpyAsync(d_out, gx, (size_t)NTOK*DD*sizeof(float), cudaMemcpyDeviceToDevice);
}

// round 6
// speedup vs baseline: 3.8704x; 1.0502x over previous
#include <cuda_runtime.h>
#include <cuda_bf16.h>
#include <math.h>

// ---------------------------------------------------------------------------
// Problem constants
// ---------------------------------------------------------------------------
#define BB 2
#define TT 2048
#define DD 1024
#define HH 16
#define DH 64
#define NTOK (BB*TT)            // 4096
#define EE 16
#define KK 2
#define FF 2048
#define CAP 640
#define DP 256
#define NPRIM 512
#define NFLAT (NTOK*KK)         // 8192

// ---------------------------------------------------------------------------
// Scratch (device globals; no allocation allowed)
// ---------------------------------------------------------------------------
__device__ float g_x[NTOK*DD];
__device__ float g_xn[NTOK*DD];
__device__ float g_qkv[NTOK*3*DD];
__device__ float g_attn[NTOK*DD];
__device__ float g_logits[NTOK*EE];
__device__ float g_probs[NTOK*EE];
__device__ int   g_topi[NFLAT];
__device__ float g_topw[NFLAT];
__device__ int   g_slot[NFLAT];
__device__ int   g_keep[NFLAT];
__device__ float g_wcomb[NFLAT];
__device__ int   g_counts[EE];
__device__ float g_pmean[EE];
__device__ float g_buf[EE*CAP*DD];
__device__ float g_h[EE*CAP*FF];
__device__ float g_yb[EE*CAP*DD];
__device__ float g_tq[NTOK*DP];
__device__ float g_tk[NPRIM*DP];
__device__ float g_tv[NPRIM*DP];
__device__ float g_tl[NTOK*NPRIM];
__device__ float g_tout[NTOK*DP];
__device__ float g_gate[NTOK];
__device__ float g_ropec[TT*32];
__device__ float g_ropes[TT*32];

// ---------------------------------------------------------------------------
// TF32 helpers
// ---------------------------------------------------------------------------
__device__ __forceinline__ void mma_tf32(float c[4], const unsigned a[4], const unsigned b[2])
{
    asm volatile(
        "mma.sync.aligned.m16n8k8.row.col.f32.tf32.tf32.f32 "
        "{%0,%1,%2,%3},{%4,%5,%6,%7},{%8,%9},{%0,%1,%2,%3};"
        : "+f"(c[0]), "+f"(c[1]), "+f"(c[2]), "+f"(c[3])
        : "r"(a[0]), "r"(a[1]), "r"(a[2]), "r"(a[3]),
          "r"(b[0]), "r"(b[1]));
}

__device__ __forceinline__ void cp16(void* smem_dst, const void* gptr)
{
    unsigned saddr = (unsigned)__cvta_generic_to_shared(smem_dst);
    asm volatile("cp.async.cg.shared.global [%0], [%1], 16;\n"
                 :: "r"(saddr), "l"(gptr));
}
__device__ __forceinline__ void cp_commit()  { asm volatile("cp.async.commit_group;\n"); }
__device__ __forceinline__ void cp_wait2()   { asm volatile("cp.async.wait_group 2;\n"); }
__device__ __forceinline__ void cp_wait1()   { asm volatile("cp.async.wait_group 1;\n"); }
__device__ __forceinline__ void cp_wait0()   { asm volatile("cp.async.wait_group 0;\n"); }

// ---------------------------------------------------------------------------
// RMSNorm: one block per token, 256 threads, float4
// ---------------------------------------------------------------------------
__global__ void rmsnorm_kernel(const float* __restrict__ x,
                               const float* __restrict__ w,
                               float* __restrict__ out)
{
    int n = blockIdx.x;
    int tid = threadIdx.x;
    const float4* xp = (const float4*)(x + (size_t)n*DD);
    float4 xv = xp[tid];
    float ss = xv.x*xv.x + xv.y*xv.y + xv.z*xv.z + xv.w*xv.w;
    __shared__ float red[256];
    red[tid] = ss;
    __syncthreads();
    for (int s = 128; s; s >>= 1) {
        if (tid < s) red[tid] += red[tid+s];
        __syncthreads();
    }
    float scale = rsqrtf(red[0] / (float)DD + 1e-6f);
    const float4* wp = (const float4*)w;
    float4 wv = wp[tid];
    float4* op = (float4*)(out + (size_t)n*DD);
    op[tid] = make_float4(xv.x*scale*wv.x, xv.y*scale*wv.y,
                          xv.z*scale*wv.z, xv.w*scale*wv.w);
}

// ---------------------------------------------------------------------------
// TF32 tensor-core GEMM: 4-stage cp.async pipeline (unchanged from R4)
// ---------------------------------------------------------------------------
#define AS_STR 20
#define BF_STR 136
#define NSTG 4
#define AS_TILE (128*AS_STR)
#define BF_TILE (16*BF_STR)

template<bool BT, int EPI>
__global__ __launch_bounds__(256, 2)
void gemm128(const float* __restrict__ A, const float* __restrict__ Bm,
             float* __restrict__ C, int M, int N, int K,
             long long sA, long long sB, long long sC,
             const float* __restrict__ gate)
{
    A  += blockIdx.z * sA;
    Bm += blockIdx.z * sB;
    C  += blockIdx.z * sC;

    extern __shared__ unsigned smem_dyn[];
    unsigned* AsP = smem_dyn;
    unsigned* BsP = smem_dyn + NSTG*AS_TILE;
    unsigned* BfP = smem_dyn + NSTG*AS_TILE;

    const int tid  = threadIdx.x;
    const int lane = tid & 31;
    const int warp = tid >> 5;
    const int lr   = lane >> 2;
    const int lq   = lane & 3;
    const int wm   = warp & 1, wn = warp >> 1;
    const int m0   = wm * 64, n0 = wn * 32;
    const int row0 = blockIdx.y * 128, col0 = blockIdx.x * 128;

    const int c0i = tid, c1i = tid + 256;
    const int ar0 = c0i >> 2, ac0 = (c0i & 3) * 4;
    const int ar1 = c1i >> 2, ac1 = (c1i & 3) * 4;
    const int fk0 = c0i >> 5, fn0 = (c0i & 31) * 4;
    const int fk1 = c1i >> 5, fn1 = (c1i & 31) * 4;

    const int nIter = K >> 4;

    auto issue = [&](int stg, int k0) {
        cp16(&AsP[stg*AS_TILE + ar0*AS_STR + ac0], A + (size_t)(row0 + ar0) * K + k0 + ac0);
        cp16(&AsP[stg*AS_TILE + ar1*AS_STR + ac1], A + (size_t)(row0 + ar1) * K + k0 + ac1);
        if constexpr (BT) {
            cp16(&BsP[stg*AS_TILE + ar0*AS_STR + ac0], Bm + (size_t)(col0 + ar0) * K + k0 + ac0);
            cp16(&BsP[stg*AS_TILE + ar1*AS_STR + ac1], Bm + (size_t)(col0 + ar1) * K + k0 + ac1);
        } else {
            cp16(&BfP[stg*BF_TILE + fk0*BF_STR + fn0], Bm + (size_t)(k0 + fk0) * N + col0 + fn0);
            cp16(&BfP[stg*BF_TILE + fk1*BF_STR + fn1], Bm + (size_t)(k0 + fk1) * N + col0 + fn1);
        }
        cp_commit();
    };

    issue(0, 0);
    if (nIter > 1) issue(1, 16);
    if (nIter > 2) issue(2, 32);

    float c[4][4][4];
    #pragma unroll
    for (int mt = 0; mt < 4; mt++)
        #pragma unroll
        for (int nt = 0; nt < 4; nt++)
            #pragma unroll
            for (int i = 0; i < 4; i++) c[mt][nt][i] = 0.f;

    for (int it = 0; it < nIter; it++) {
        if (it + 2 < nIter)      cp_wait2();
        else if (it + 1 < nIter) cp_wait1();
        else                     cp_wait0();
        __syncthreads();

        if (it + 3 < nIter) issue((it + 3) & 3, (it + 3) << 4);

        const int st = it & 3;
        const unsigned* Asb = AsP + st * AS_TILE;
        const unsigned* Bsb = BsP + st * AS_TILE;
        const unsigned* Bfb = BfP + st * BF_TILE;

        #pragma unroll
        for (int ks = 0; ks < 2; ks++) {
            const int kb = ks * 8;
            unsigned a[4][4], b[4][2];
            #pragma unroll
            for (int mt = 0; mt < 4; mt++) {
                int r = m0 + mt * 16 + lr;
                a[mt][0] = Asb[r*AS_STR + kb + lq];
                a[mt][1] = Asb[(r+8)*AS_STR + kb + lq];
                a[mt][2] = Asb[r*AS_STR + kb + 4 + lq];
                a[mt][3] = Asb[(r+8)*AS_STR + kb + 4 + lq];
            }
            #pragma unroll
            for (int nt = 0; nt < 4; nt++) {
                int cn = n0 + nt * 8 + lr;
                if constexpr (BT) {
                    b[nt][0] = Bsb[cn*AS_STR + kb + lq];
                    b[nt][1] = Bsb[cn*AS_STR + kb + 4 + lq];
                } else {
                    b[nt][0] = Bfb[(kb+lq)*BF_STR + cn];
                    b[nt][1] = Bfb[(kb+4+lq)*BF_STR + cn];
                }
            }
            #pragma unroll
            for (int mt = 0; mt < 4; mt++)
                #pragma unroll
                for (int nt = 0; nt < 4; nt++)
                    mma_tf32(c[mt][nt], a[mt], b[nt]);
        }
    }

    #pragma unroll
    for (int mt = 0; mt < 4; mt++) {
        int r0g = row0 + m0 + mt * 16 + lr;
        int r1g = r0g + 8;
        float g0 = (EPI == 3) ? gate[r0g] : 0.f;
        float g1 = (EPI == 3) ? gate[r1g] : 0.f;
        #pragma unroll
        for (int nt = 0; nt < 4; nt++) {
            int cg = col0 + n0 + nt * 8 + 2 * lq;
            float2* p0 = (float2*)&C[(size_t)r0g * N + cg];
            float2* p1 = (float2*)&C[(size_t)r1g * N + cg];
            float v0 = c[mt][nt][0], v1 = c[mt][nt][1];
            float v2 = c[mt][nt][2], v3 = c[mt][nt][3];
            if (EPI == 0) {
                *p0 = make_float2(v0, v1);
                *p1 = make_float2(v2, v3);
            } else if (EPI == 1) {
                float2 o0 = *p0, o1 = *p1;
                *p0 = make_float2(o0.x + v0, o0.y + v1);
                *p1 = make_float2(o1.x + v2, o1.y + v3);
            } else if (EPI == 2) {
                *p0 = make_float2(v0 / (1.f + __expf(-v0)), v1 / (1.f + __expf(-v1)));
                *p1 = make_float2(v2 / (1.f + __expf(-v2)), v3 / (1.f + __expf(-v3)));
            } else {
                float2 o0 = *p0, o1 = *p1;
                *p0 = make_float2(o0.x + g0 * v0, o0.y + g0 * v1);
                *p1 = make_float2(o1.x + g1 * v2, o1.y + g1 * v3);
            }
        }
    }
}

#define SMEM_BT ((NSTG*AS_TILE + NSTG*AS_TILE) * 4)
#define SMEM_KN ((NSTG*AS_TILE + NSTG*BF_TILE) * 4)

// ---------------------------------------------------------------------------
// RoPE table + apply
// ---------------------------------------------------------------------------
__global__ void rope_table_kernel()
{
    int idx = blockIdx.x * 256 + threadIdx.x;
    int t = idx >> 5, i = idx & 31;
    float inv = powf(10000.f, -(float)i / 32.f);
    float s, c;
    sincosf((float)t * inv, &s, &c);
    g_ropec[idx] = c;
    g_ropes[idx] = s;
}

__global__ void rope_kernel(float* __restrict__ qkv)
{
    int n = blockIdx.x;
    int t = n & (TT-1);
    for (int p = threadIdx.x; p < 1024; p += 256) {
        int which = p >> 9;
        int rem = p & 511;
        int h = rem >> 5;
        int i = rem & 31;
        float c = g_ropec[t*32 + i];
        float s = g_ropes[t*32 + i];
        size_t base = (size_t)n*3072 + (size_t)which*1024 + h*64 + i;
        float u1 = qkv[base], u2 = qkv[base+32];
        qkv[base]    = u1*c - u2*s;
        qkv[base+32] = u2*c + u1*s;
    }
}

// ---------------------------------------------------------------------------
// Flash attention v2: BQ=128, 256 threads (8 warps), BK=32,
// cp.async triple-buffered K/V, V kept native [key][dh] (no transpose),
// raw fp32 bits into tf32 MMA, scale folded into post-MMA S.
// ---------------------------------------------------------------------------
#define FQ_STR 68
#define FK_STR 68
#define FV_STR 72
#define FP_STR 36
#define FQ_OFF 0
#define FK_OFF (128*FQ_STR)                       // 8704
#define FV_OFF (FK_OFF + 3*32*FK_STR)             // 15232
#define FP_OFF (FV_OFF + 3*32*FV_STR)             // 22144
#define FLASH_SMEM ((FP_OFF + 128*FP_STR) * 4)    // 107008 bytes

__global__ __launch_bounds__(256)
void flash_attn_tc(const float* __restrict__ qkv, float* __restrict__ out)
{
    extern __shared__ unsigned fsm[];
    unsigned* Qs = fsm + FQ_OFF;
    unsigned* Ks = fsm + FK_OFF;
    unsigned* Vs = fsm + FV_OFF;
    unsigned* Ps = fsm + FP_OFF;

    const int qb = blockIdx.x, bh = blockIdx.y;
    const int b = bh >> 4, h = bh & 15;
    const int tid = threadIdx.x, lane = tid & 31, warp = tid >> 5;
    const int lr = lane >> 2, lq = lane & 3;
    const int m0 = warp * 16;
    const int q0 = qb * 128;
    const int ntiles = 4*qb + 4;

    // Q: 128 rows x 16 chunks (16B) = 2048 chunks
    #pragma unroll
    for (int c = tid; c < 2048; c += 256) {
        int r = c >> 4, off = (c & 15) * 4;
        cp16(&Qs[r*FQ_STR + off], qkv + (size_t)(b*TT + q0 + r)*3072 + h*64 + off);
    }

    auto load_tile = [&](int kb, int buf) {
        unsigned* Kb = Ks + buf*(32*FK_STR);
        unsigned* Vb = Vs + buf*(32*FV_STR);
        #pragma unroll
        for (int c = tid; c < 512; c += 256) {
            int r = c >> 4, off = (c & 15) * 4;
            size_t base = (size_t)(b*TT + kb*32 + r)*3072 + h*64 + off;
            cp16(&Kb[r*FK_STR + off], qkv + base + 1024);
            cp16(&Vb[r*FV_STR + off], qkv + base + 2048);
        }
        cp_commit();
    };

    load_tile(0, 0);    // group 0 also covers the Q chunks above
    load_tile(1, 1);

    float mrow0 = -1e30f, mrow1 = -1e30f;
    float lrow0 = 0.f,    lrow1 = 0.f;
    float o[8][4];
    #pragma unroll
    for (int nt = 0; nt < 8; nt++)
        #pragma unroll
        for (int i = 0; i < 4; i++) o[nt][i] = 0.f;

    const int rg0 = q0 + m0 + lr, rg1 = rg0 + 8;

    for (int kb = 0; kb < ntiles; kb++) {
        if (kb + 1 < ntiles) cp_wait1(); else cp_wait0();
        __syncthreads();   // tile kb ready; all warps done with tile kb-1 -> its buffer free
        if (kb + 2 < ntiles) load_tile(kb + 2, (kb + 2) % 3);

        const unsigned* Kb = Ks + (kb % 3)*(32*FK_STR);
        const unsigned* Vb = Vs + (kb % 3)*(32*FV_STR);

        // ---- S = Q K^T ----
        float s[4][4];
        #pragma unroll
        for (int nt = 0; nt < 4; nt++)
            #pragma unroll
            for (int i = 0; i < 4; i++) s[nt][i] = 0.f;
        #pragma unroll
        for (int kk = 0; kk < 8; kk++) {
            unsigned a[4];
            a[0] = Qs[(m0+lr)*FQ_STR + kk*8+lq];
            a[1] = Qs[(m0+lr+8)*FQ_STR + kk*8+lq];
            a[2] = Qs[(m0+lr)*FQ_STR + kk*8+lq+4];
            a[3] = Qs[(m0+lr+8)*FQ_STR + kk*8+lq+4];
            #pragma unroll
            for (int nt = 0; nt < 4; nt++) {
                unsigned bf[2] = { Kb[(nt*8+lr)*FK_STR + kk*8+lq],
                                   Kb[(nt*8+lr)*FK_STR + kk*8+lq+4] };
                mma_tf32(s[nt], a, bf);
            }
        }

        // ---- scale + causal mask ----
        #pragma unroll
        for (int nt = 0; nt < 4; nt++)
            #pragma unroll
            for (int i = 0; i < 4; i++) s[nt][i] *= 0.125f;
        if (kb*32 + 31 > q0 + m0) {
            #pragma unroll
            for (int nt = 0; nt < 4; nt++) {
                int c0 = kb*32 + nt*8 + 2*lq;
                if (c0   > rg0) s[nt][0] = -1e30f;
                if (c0+1 > rg0) s[nt][1] = -1e30f;
                if (c0   > rg1) s[nt][2] = -1e30f;
                if (c0+1 > rg1) s[nt][3] = -1e30f;
            }
        }

        // ---- online softmax ----
        float mx0 = -1e30f, mx1 = -1e30f;
        #pragma unroll
        for (int nt = 0; nt < 4; nt++) {
            mx0 = fmaxf(mx0, fmaxf(s[nt][0], s[nt][1]));
            mx1 = fmaxf(mx1, fmaxf(s[nt][2], s[nt][3]));
        }
        mx0 = fmaxf(mx0, __shfl_xor_sync(0xffffffffu, mx0, 1));
        mx0 = fmaxf(mx0, __shfl_xor_sync(0xffffffffu, mx0, 2));
        mx1 = fmaxf(mx1, __shfl_xor_sync(0xffffffffu, mx1, 1));
        mx1 = fmaxf(mx1, __shfl_xor_sync(0xffffffffu, mx1, 2));
        float mn0 = fmaxf(mrow0, mx0), mn1 = fmaxf(mrow1, mx1);
        float corr0 = __expf(mrow0 - mn0), corr1 = __expf(mrow1 - mn1);
        float sum0 = 0.f, sum1 = 0.f;
        #pragma unroll
        for (int nt = 0; nt < 4; nt++) {
            s[nt][0] = __expf(s[nt][0] - mn0);
            s[nt][1] = __expf(s[nt][1] - mn0);
            s[nt][2] = __expf(s[nt][2] - mn1);
            s[nt][3] = __expf(s[nt][3] - mn1);
            sum0 += s[nt][0] + s[nt][1];
            sum1 += s[nt][2] + s[nt][3];
        }
        sum0 += __shfl_xor_sync(0xffffffffu, sum0, 1);
        sum0 += __shfl_xor_sync(0xffffffffu, sum0, 2);
        sum1 += __shfl_xor_sync(0xffffffffu, sum1, 1);
        sum1 += __shfl_xor_sync(0xffffffffu, sum1, 2);
        lrow0 = lrow0*corr0 + sum0;
        lrow1 = lrow1*corr1 + sum1;
        mrow0 = mn0; mrow1 = mn1;
        #pragma unroll
        for (int nt = 0; nt < 8; nt++) {
            o[nt][0] *= corr0; o[nt][1] *= corr0;
            o[nt][2] *= corr1; o[nt][3] *= corr1;
        }

        // ---- P -> smem (warp-private rows) ----
        #pragma unroll
        for (int nt = 0; nt < 4; nt++) {
            Ps[(m0+lr)*FP_STR + nt*8+2*lq]     = __float_as_uint(s[nt][0]);
            Ps[(m0+lr)*FP_STR + nt*8+2*lq+1]   = __float_as_uint(s[nt][1]);
            Ps[(m0+lr+8)*FP_STR + nt*8+2*lq]   = __float_as_uint(s[nt][2]);
            Ps[(m0+lr+8)*FP_STR + nt*8+2*lq+1] = __float_as_uint(s[nt][3]);
        }
        __syncwarp();

        // ---- O += P V  (V native [key][dh] = col-major B) ----
        #pragma unroll
        for (int ks = 0; ks < 4; ks++) {
            unsigned a[4];
            a[0] = Ps[(m0+lr)*FP_STR + ks*8+lq];
            a[1] = Ps[(m0+lr+8)*FP_STR + ks*8+lq];
            a[2] = Ps[(m0+lr)*FP_STR + ks*8+lq+4];
            a[3] = Ps[(m0+lr+8)*FP_STR + ks*8+lq+4];
            #pragma unroll
            for (int nt = 0; nt < 8; nt++) {
                unsigned bf[2] = { Vb[(ks*8+lq)*FV_STR + nt*8+lr],
                                   Vb[(ks*8+4+lq)*FV_STR + nt*8+lr] };
                mma_tf32(o[nt], a, bf);
            }
        }
    }

    float inv0 = 1.f / lrow0, inv1 = 1.f / lrow1;
    #pragma unroll
    for (int nt = 0; nt < 8; nt++) {
        int cg = h*64 + nt*8 + 2*lq;
        size_t base0 = (size_t)(b*TT + rg0)*DD + cg;
        size_t base1 = (size_t)(b*TT + rg1)*DD + cg;
        out[base0]   = o[nt][0]*inv0;
        out[base0+1] = o[nt][1]*inv0;
        out[base1]   = o[nt][2]*inv1;
        out[base1+1] = o[nt][3]*inv1;
    }
}

// ---------------------------------------------------------------------------
// Router logits: block per token (128 thr, 4 warps x 4 experts)
// ---------------------------------------------------------------------------
__global__ void router_kernel(const float* __restrict__ xn,
                              const float* __restrict__ rw,
                              float* __restrict__ logits)
{
    int n = blockIdx.x;
    int warp = threadIdx.x >> 5, lane = threadIdx.x & 31;
    const float* xp = xn + (size_t)n*DD;
    for (int j = 0; j < 4; j++) {
        int e = warp*4 + j;
        const float* wp = rw + (size_t)e*DD;
        float s = 0.f;
        for (int i = lane; i < DD; i += 32) s += xp[i]*wp[i];
        #pragma unroll
        for (int off = 16; off; off >>= 1) s += __shfl_xor_sync(0xffffffffu, s, off);
        if (lane == 0) logits[n*EE + e] = s;
    }
}

// ---------------------------------------------------------------------------
// Softmax over 16 experts + top-2
// ---------------------------------------------------------------------------
__global__ void top2_kernel(const float* __restrict__ logits,
                            float* __restrict__ probs,
                            int* __restrict__ topi, float* __restrict__ topw)
{
    int n = blockIdx.x*blockDim.x + threadIdx.x;
    if (n >= NTOK) return;
    float l[EE];
    float mx = -1e30f;
    #pragma unroll
    for (int e = 0; e < EE; e++) { l[e] = logits[n*EE+e]; mx = fmaxf(mx, l[e]); }
    float sum = 0.f;
    #pragma unroll
    for (int e = 0; e < EE; e++) { l[e] = __expf(l[e]-mx); sum += l[e]; }
    float inv = 1.f/sum;
    #pragma unroll
    for (int e = 0; e < EE; e++) { l[e] *= inv; probs[n*EE+e] = l[e]; }
    int i0 = 0; float p0 = l[0];
    #pragma unroll
    for (int e = 1; e < EE; e++) if (l[e] > p0) { p0 = l[e]; i0 = e; }
    int i1 = (i0 == 0) ? 1 : 0; float p1 = l[i1];
    #pragma unroll
    for (int e = 0; e < EE; e++) if (e != i0 && l[e] > p1) { p1 = l[e]; i1 = e; }
    float ws = p0 + p1;
    topi[n*2]   = i0; topi[n*2+1] = i1;
    topw[n*2]   = p0/ws; topw[n*2+1] = p1/ws;
}

// ---------------------------------------------------------------------------
// Deterministic pmean reduction (16 blocks, fixed tree)
// ---------------------------------------------------------------------------
__global__ void pmean_kernel(const float* __restrict__ probs, float* __restrict__ pmean)
{
    int e = blockIdx.x, tid = threadIdx.x;
    float s = 0.f;
    for (int t = tid; t < NTOK; t += 256) s += probs[t*EE + e];
    __shared__ float red[256];
    red[tid] = s;
    __syncthreads();
    for (int k = 128; k; k >>= 1) {
        if (tid < k) red[tid] += red[tid+k];
        __syncthreads();
    }
    if (tid == 0) pmean[e] = red[0] / (float)NTOK;
}

// ---------------------------------------------------------------------------
// Capacity position assignment
// ---------------------------------------------------------------------------
__global__ void assign_kernel(const int* __restrict__ topi,
                              const float* __restrict__ topw,
                              int* __restrict__ slot, int* __restrict__ keep,
                              float* __restrict__ wcomb, int* __restrict__ counts)
{
    int e = blockIdx.x;
    int tid = threadIdx.x;
    int lane = tid & 31, warp = tid >> 5;
    __shared__ int warpsum[8];
    int running = 0;
    for (int base = 0; base < NFLAT; base += 256) {
        int i = base + tid;
        int match = (topi[i] == e) ? 1 : 0;
        unsigned mask = __ballot_sync(0xffffffffu, match);
        if (lane == 0) warpsum[warp] = __popc(mask);
        __syncthreads();
        int wbase = 0, tot = 0;
        #pragma unroll
        for (int w = 0; w < 8; w++) {
            int c = warpsum[w];
            if (w < warp) wbase += c;
            tot += c;
        }
        if (match) {
            int pos = running + wbase + __popc(mask & ((1u << lane) - 1u));
            int kp = (pos < CAP) ? 1 : 0;
            slot[i]  = (pos < CAP-1) ? pos : (CAP-1);
            keep[i]  = kp;
            wcomb[i] = kp ? topw[i] : 0.f;
        }
        running += tot;
        __syncthreads();
    }
    if (tid == 0) counts[e] = running;
}

// ---------------------------------------------------------------------------
// Scatter tokens into expert buffers
// ---------------------------------------------------------------------------
__global__ void scatter_kernel(const int* __restrict__ topi,
                               const int* __restrict__ slot,
                               const int* __restrict__ keep,
                               const float* __restrict__ xn,
                               float* __restrict__ buf)
{
    int i = blockIdx.x;
    if (!keep[i]) return;
    int e = topi[i], s = slot[i], tok = i >> 1;
    const float4* src = (const float4*)(xn + (size_t)tok*DD);
    float4* dst = (float4*)(buf + ((size_t)e*CAP + s)*DD);
    dst[threadIdx.x] = src[threadIdx.x];
}

// ---------------------------------------------------------------------------
// Gather expert outputs + residual into x
// ---------------------------------------------------------------------------
__global__ void gather_kernel(const int* __restrict__ topi,
                              const int* __restrict__ slot,
                              const float* __restrict__ wcomb,
                              const float* __restrict__ yb,
                              float* __restrict__ x)
{
    int n = blockIdx.x;
    int t4 = threadIdx.x;
    float4* xp = (float4*)(x + (size_t)n*DD);
    float4 a = xp[t4];
    #pragma unroll
    for (int k = 0; k < 2; k++) {
        int i = n*2 + k;
        float w = wcomb[i];
        if (w != 0.f) {
            int e = topi[i], s = slot[i];
            const float4* yp = (const float4*)(yb + ((size_t)e*CAP + s)*DD);
            float4 yv = yp[t4];
            a.x += w*yv.x; a.y += w*yv.y; a.z += w*yv.z; a.w += w*yv.w;
        }
    }
    xp[t4] = a;
}

// ---------------------------------------------------------------------------
// aux = E * sum(frac * pmean); written at d_out[B*T*D]
// ---------------------------------------------------------------------------
__global__ void aux_kernel(const int* __restrict__ counts,
                           const float* __restrict__ pmean,
                           float* __restrict__ out, int out_size)
{
    if (threadIdx.x == 0 && out_size > NTOK*DD) {
        float s = 0.f;
        for (int e = 0; e < EE; e++)
            s += ((float)counts[e] / (float)NTOK) * pmean[e];
        out[NTOK*DD] = (float)EE * s;
    }
}

// ---------------------------------------------------------------------------
// ToU gate: sigmoid(xn . gw + gb) per token
// ---------------------------------------------------------------------------
__global__ void gate_kernel(const float* __restrict__ xn,
                            const float* __restrict__ gw,
                            const float* __restrict__ gb,
                            float* __restrict__ gate)
{
    int n = blockIdx.x, tid = threadIdx.x;
    const float4* xp = (const float4*)(xn + (size_t)n*DD);
    const float4* wp = (const float4*)gw;
    float4 xv = xp[tid], wv = wp[tid];
    float s = xv.x*wv.x + xv.y*wv.y + xv.z*wv.z + xv.w*wv.w;
    __shared__ float red[256];
    red[tid] = s;
    __syncthreads();
    for (int k = 128; k; k >>= 1) {
        if (tid < k) red[tid] += red[tid+k];
        __syncthreads();
    }
    if (tid == 0) gate[n] = 1.f / (1.f + __expf(-(red[0] + gb[0])));
}

// ---------------------------------------------------------------------------
// Softmax over 512 primitives (scale 1/16 folded in), in place
// ---------------------------------------------------------------------------
__global__ void softmax512_kernel(float* __restrict__ tl)
{
    int n = blockIdx.x, tid = threadIdx.x;
    float* row = tl + (size_t)n*NPRIM;
    float v0 = row[tid]       * 0.0625f;
    float v1 = row[tid + 256] * 0.0625f;
    __shared__ float red[256];
    red[tid] = fmaxf(v0, v1);
    __syncthreads();
    for (int s = 128; s; s >>= 1) {
        if (tid < s) red[tid] = fmaxf(red[tid], red[tid+s]);
        __syncthreads();
    }
    float mx = red[0];
    __syncthreads();
    v0 = __expf(v0 - mx); v1 = __expf(v1 - mx);
    red[tid] = v0 + v1;
    __syncthreads();
    for (int s = 128; s; s >>= 1) {
        if (tid < s) red[tid] += red[tid+s];
        __syncthreads();
    }
    float inv = 1.f / red[0];
    row[tid] = v0*inv; row[tid+256] = v1*inv;
}

// ---------------------------------------------------------------------------
// Host launch
// ---------------------------------------------------------------------------
extern "C" void kernel_launch(void* const* d_in, const int* in_sizes, int n_in,
                              void* d_out, int out_size)
{
    const float* x          = (const float*)d_in[0];
    const float* tou_embeds = (const float*)d_in[1];
    const float* norm1_w    = (const float*)d_in[2];
    const float* qkv_w      = (const float*)d_in[3];
    const float* attn_o_w   = (const float*)d_in[4];
    const float* norm2_w    = (const float*)d_in[5];
    const float* router_w   = (const float*)d_in[6];
    const float* moe_w1     = (const float*)d_in[7];
    const float* moe_w2     = (const float*)d_in[8];
    const float* norm3_w    = (const float*)d_in[9];
    const float* tou_q_w    = (const float*)d_in[10];
    const float* tou_k_w    = (const float*)d_in[11];
    const float* tou_v_w    = (const float*)d_in[12];
    const float* tou_o_w    = (const float*)d_in[13];
    const float* tou_gate_w = (const float*)d_in[14];
    const float* tou_gate_b = (const float*)d_in[15];

    cudaFuncSetAttribute(gemm128<true,0>,  cudaFuncAttributeMaxDynamicSharedMemorySize, SMEM_BT);
    cudaFuncSetAttribute(gemm128<true,1>,  cudaFuncAttributeMaxDynamicSharedMemorySize, SMEM_BT);
    cudaFuncSetAttribute(gemm128<true,3>,  cudaFuncAttributeMaxDynamicSharedMemorySize, SMEM_BT);
    cudaFuncSetAttribute(gemm128<false,0>, cudaFuncAttributeMaxDynamicSharedMemorySize, SMEM_KN);
    cudaFuncSetAttribute(gemm128<false,2>, cudaFuncAttributeMaxDynamicSharedMemorySize, SMEM_KN);
    cudaFuncSetAttribute(flash_attn_tc,    cudaFuncAttributeMaxDynamicSharedMemorySize, FLASH_SMEM);

    float *gx, *gxn, *gqkv, *gattn, *glogits, *gprobs, *gtopw, *gwcomb,
          *gpmean, *gbuf, *gh, *gyb, *gtq, *gtk, *gtv, *gtl, *gtout, *ggate;
    int *gtopi, *gslot, *gkeep, *gcounts;
    cudaGetSymbolAddress((void**)&gx, g_x);
    cudaGetSymbolAddress((void**)&gxn, g_xn);
    cudaGetSymbolAddress((void**)&gqkv, g_qkv);
    cudaGetSymbolAddress((void**)&gattn, g_attn);
    cudaGetSymbolAddress((void**)&glogits, g_logits);
    cudaGetSymbolAddress((void**)&gprobs, g_probs);
    cudaGetSymbolAddress((void**)&gtopi, g_topi);
    cudaGetSymbolAddress((void**)&gtopw, g_topw);
    cudaGetSymbolAddress((void**)&gslot, g_slot);
    cudaGetSymbolAddress((void**)&gkeep, g_keep);
    cudaGetSymbolAddress((void**)&gwcomb, g_wcomb);
    cudaGetSymbolAddress((void**)&gcounts, g_counts);
    cudaGetSymbolAddress((void**)&gpmean, g_pmean);
    cudaGetSymbolAddress((void**)&gbuf, g_buf);
    cudaGetSymbolAddress((void**)&gh, g_h);
    cudaGetSymbolAddress((void**)&gyb, g_yb);
    cudaGetSymbolAddress((void**)&gtq, g_tq);
    cudaGetSymbolAddress((void**)&gtk, g_tk);
    cudaGetSymbolAddress((void**)&gtv, g_tv);
    cudaGetSymbolAddress((void**)&gtl, g_tl);
    cudaGetSymbolAddress((void**)&gtout, g_tout);
    cudaGetSymbolAddress((void**)&ggate, g_gate);

    // residual stream
    cudaMemcpyAsync(gx, x, (size_t)NTOK*DD*sizeof(float), cudaMemcpyDeviceToDevice);
    rope_table_kernel<<<TT*32/256, 256>>>();

    // ---- Block 1: RoPE attention ----
    rmsnorm_kernel<<<NTOK, 256>>>(x, norm1_w, gxn);
    gemm128<true,0><<<dim3(3*DD/128, NTOK/128, 1), 256, SMEM_BT>>>(gxn, qkv_w, gqkv,
        NTOK, 3*DD, DD, 0, 0, 0, nullptr);
    rope_kernel<<<NTOK, 256>>>(gqkv);
    flash_attn_tc<<<dim3(TT/128, BB*HH), 256, FLASH_SMEM>>>(gqkv, gattn);
    gemm128<true,1><<<dim3(DD/128, NTOK/128, 1), 256, SMEM_BT>>>(gattn, attn_o_w, gx,
        NTOK, DD, DD, 0, 0, 0, nullptr);

    // ---- Block 2: MoE ----
    rmsnorm_kernel<<<NTOK, 256>>>(gx, norm2_w, gxn);
    router_kernel<<<NTOK, 128>>>(gxn, router_w, glogits);
    top2_kernel<<<NTOK/128, 128>>>(glogits, gprobs, gtopi, gtopw);
    pmean_kernel<<<EE, 256>>>(gprobs, gpmean);
    assign_kernel<<<EE, 256>>>(gtopi, gtopw, gslot, gkeep, gwcomb, gcounts);
    cudaMemsetAsync(gbuf, 0, (size_t)EE*CAP*DD*sizeof(float));
    scatter_kernel<<<NFLAT, 256>>>(gtopi, gslot, gkeep, gxn, gbuf);
    gemm128<false,2><<<dim3(FF/128, CAP/128, EE), 256, SMEM_KN>>>(gbuf, moe_w1, gh,
        CAP, FF, DD, (long long)CAP*DD, (long long)DD*FF, (long long)CAP*FF, nullptr);
    gemm128<false,0><<<dim3(DD/128, CAP/128, EE), 256, SMEM_KN>>>(gh, moe_w2, gyb,
        CAP, DD, FF, (long long)CAP*FF, (long long)FF*DD, (long long)CAP*DD, nullptr);
    gather_kernel<<<NTOK, 256>>>(gtopi, gslot, gwcomb, gyb, gx);
    aux_kernel<<<1, 32>>>(gcounts, gpmean, (float*)d_out, out_size);

    // ---- Block 3: ToU cross-attention ----
    rmsnorm_kernel<<<NTOK, 256>>>(gx, norm3_w, gxn);
    gemm128<true,0><<<dim3(DP/128, NTOK/128, 1), 256, SMEM_BT>>>(gxn, tou_q_w, gtq,
        NTOK, DP, DD, 0, 0, 0, nullptr);
    gemm128<true,0><<<dim3(DP/128, NPRIM/128, 1), 256, SMEM_BT>>>(tou_embeds, tou_k_w, gtk,
        NPRIM, DP, DP, 0, 0, 0, nullptr);
    gemm128<true,0><<<dim3(DP/128, NPRIM/128, 1), 256, SMEM_BT>>>(tou_embeds, tou_v_w, gtv,
        NPRIM, DP, DP, 0, 0, 0, nullptr);
    gemm128<true,0><<<dim3(NPRIM/128, NTOK/128, 1), 256, SMEM_BT>>>(gtq, gtk, gtl,
        NTOK, NPRIM, DP, 0, 0, 0, nullptr);
    softmax512_kernel<<<NTOK, 256>>>(gtl);
    gemm128<false,0><<<dim3(DP/128, NTOK/128, 1), 256, SMEM_KN>>>(gtl, gtv, gtout,
        NTOK, DP, NPRIM, 0, 0, 0, nullptr);
    gate_kernel<<<NTOK, 256>>>(gxn, tou_gate_w, tou_gate_b, ggate);
    gemm128<true,3><<<dim3(DD/128, NTOK/128, 1), 256, SMEM_BT>>>(gtout, tou_o_w, gx,
        NTOK, DD, DP, 0, 0, 0, ggate);

    // output
    cudaMemcpyAsync(d_out, gx, (size_t)NTOK*DD*sizeof(float), cudaMemcpyDeviceToDevice);
}

// round 7
// speedup vs baseline: 3.8868x; 1.0042x over previous
#include <cuda_runtime.h>
#include <cuda_bf16.h>
#include <math.h>

// ---------------------------------------------------------------------------
// Problem constants
// ---------------------------------------------------------------------------
#define BB 2
#define TT 2048
#define DD 1024
#define HH 16
#define DH 64
#define NTOK (BB*TT)            // 4096
#define EE 16
#define KK 2
#define FF 2048
#define CAP 640
#define DP 256
#define NPRIM 512
#define NFLAT (NTOK*KK)         // 8192

// ---------------------------------------------------------------------------
// Scratch (device globals; no allocation allowed)
// ---------------------------------------------------------------------------
__device__ float g_x[NTOK*DD];
__device__ float g_xn[NTOK*DD];
__device__ float g_qkv[NTOK*3*DD];
__device__ float g_attn[NTOK*DD];
__device__ float g_logits[NTOK*EE];
__device__ float g_probs[NTOK*EE];
__device__ int   g_topi[NFLAT];
__device__ float g_topw[NFLAT];
__device__ int   g_slot[NFLAT];
__device__ int   g_keep[NFLAT];
__device__ float g_wcomb[NFLAT];
__device__ int   g_counts[EE];
__device__ float g_pmean[EE];
__device__ float g_buf[EE*CAP*DD];
__device__ float g_h[EE*CAP*FF];
__device__ float g_yb[EE*CAP*DD];
__device__ float g_tq[NTOK*DP];
__device__ float g_tk[NPRIM*DP];
__device__ float g_tv[NPRIM*DP];
__device__ float g_tl[NTOK*NPRIM];
__device__ float g_tout[NTOK*DP];
__device__ float g_gate[NTOK];
__device__ float g_ropec[TT*32];
__device__ float g_ropes[TT*32];

// ---------------------------------------------------------------------------
// Streams / events for graph fork-join (host resources, created once)
// ---------------------------------------------------------------------------
static cudaStream_t s1, s2;
static cudaEvent_t ev_root, ev_tab, ev_s1, ev_s2, ev_top2, ev_pm, ev_n3, ev_gate;
namespace {
struct InitOnce {
    InitOnce() {
        cudaStreamCreateWithFlags(&s1, cudaStreamNonBlocking);
        cudaStreamCreateWithFlags(&s2, cudaStreamNonBlocking);
        cudaEventCreateWithFlags(&ev_root, cudaEventDisableTiming);
        cudaEventCreateWithFlags(&ev_tab,  cudaEventDisableTiming);
        cudaEventCreateWithFlags(&ev_s1,   cudaEventDisableTiming);
        cudaEventCreateWithFlags(&ev_s2,   cudaEventDisableTiming);
        cudaEventCreateWithFlags(&ev_top2, cudaEventDisableTiming);
        cudaEventCreateWithFlags(&ev_pm,   cudaEventDisableTiming);
        cudaEventCreateWithFlags(&ev_n3,   cudaEventDisableTiming);
        cudaEventCreateWithFlags(&ev_gate, cudaEventDisableTiming);
    }
};
static InitOnce init_once_;
}

// ---------------------------------------------------------------------------
// TF32 helpers
// ---------------------------------------------------------------------------
__device__ __forceinline__ void mma_tf32(float c[4], const unsigned a[4], const unsigned b[2])
{
    asm volatile(
        "mma.sync.aligned.m16n8k8.row.col.f32.tf32.tf32.f32 "
        "{%0,%1,%2,%3},{%4,%5,%6,%7},{%8,%9},{%0,%1,%2,%3};"
        : "+f"(c[0]), "+f"(c[1]), "+f"(c[2]), "+f"(c[3])
        : "r"(a[0]), "r"(a[1]), "r"(a[2]), "r"(a[3]),
          "r"(b[0]), "r"(b[1]));
}

__device__ __forceinline__ void cp16(void* smem_dst, const void* gptr)
{
    unsigned saddr = (unsigned)__cvta_generic_to_shared(smem_dst);
    asm volatile("cp.async.cg.shared.global [%0], [%1], 16;\n"
                 :: "r"(saddr), "l"(gptr));
}
__device__ __forceinline__ void cp_commit()  { asm volatile("cp.async.commit_group;\n"); }
__device__ __forceinline__ void cp_wait2()   { asm volatile("cp.async.wait_group 2;\n"); }
__device__ __forceinline__ void cp_wait1()   { asm volatile("cp.async.wait_group 1;\n"); }
__device__ __forceinline__ void cp_wait0()   { asm volatile("cp.async.wait_group 0;\n"); }

// ---------------------------------------------------------------------------
// RMSNorm: one block per token, 256 threads, float4
// ---------------------------------------------------------------------------
__global__ void rmsnorm_kernel(const float* __restrict__ x,
                               const float* __restrict__ w,
                               float* __restrict__ out)
{
    int n = blockIdx.x;
    int tid = threadIdx.x;
    const float4* xp = (const float4*)(x + (size_t)n*DD);
    float4 xv = xp[tid];
    float ss = xv.x*xv.x + xv.y*xv.y + xv.z*xv.z + xv.w*xv.w;
    __shared__ float red[256];
    red[tid] = ss;
    __syncthreads();
    for (int s = 128; s; s >>= 1) {
        if (tid < s) red[tid] += red[tid+s];
        __syncthreads();
    }
    float scale = rsqrtf(red[0] / (float)DD + 1e-6f);
    const float4* wp = (const float4*)w;
    float4 wv = wp[tid];
    float4* op = (float4*)(out + (size_t)n*DD);
    op[tid] = make_float4(xv.x*scale*wv.x, xv.y*scale*wv.y,
                          xv.z*scale*wv.z, xv.w*scale*wv.w);
}

// ---------------------------------------------------------------------------
// TF32 tensor-core GEMM: 4-stage cp.async pipeline.
// EPI: 0=store, 1=C+=, 2=silu store, 3=C+=gate*v,
//      4=C=Xin+v (residual store), 5=C=Xin+gate*v (gated residual store)
// ---------------------------------------------------------------------------
#define AS_STR 20
#define BF_STR 136
#define NSTG 4
#define AS_TILE (128*AS_STR)
#define BF_TILE (16*BF_STR)

template<bool BT, int EPI>
__global__ __launch_bounds__(256, 2)
void gemm128(const float* __restrict__ A, const float* __restrict__ Bm,
             float* __restrict__ C, int M, int N, int K,
             long long sA, long long sB, long long sC,
             const float* __restrict__ gate, const float* __restrict__ Xin)
{
    A  += blockIdx.z * sA;
    Bm += blockIdx.z * sB;
    C  += blockIdx.z * sC;

    extern __shared__ unsigned smem_dyn[];
    unsigned* AsP = smem_dyn;
    unsigned* BsP = smem_dyn + NSTG*AS_TILE;
    unsigned* BfP = smem_dyn + NSTG*AS_TILE;

    const int tid  = threadIdx.x;
    const int lane = tid & 31;
    const int warp = tid >> 5;
    const int lr   = lane >> 2;
    const int lq   = lane & 3;
    const int wm   = warp & 1, wn = warp >> 1;
    const int m0   = wm * 64, n0 = wn * 32;
    const int row0 = blockIdx.y * 128, col0 = blockIdx.x * 128;

    const int c0i = tid, c1i = tid + 256;
    const int ar0 = c0i >> 2, ac0 = (c0i & 3) * 4;
    const int ar1 = c1i >> 2, ac1 = (c1i & 3) * 4;
    const int fk0 = c0i >> 5, fn0 = (c0i & 31) * 4;
    const int fk1 = c1i >> 5, fn1 = (c1i & 31) * 4;

    const int nIter = K >> 4;

    auto issue = [&](int stg, int k0) {
        cp16(&AsP[stg*AS_TILE + ar0*AS_STR + ac0], A + (size_t)(row0 + ar0) * K + k0 + ac0);
        cp16(&AsP[stg*AS_TILE + ar1*AS_STR + ac1], A + (size_t)(row0 + ar1) * K + k0 + ac1);
        if constexpr (BT) {
            cp16(&BsP[stg*AS_TILE + ar0*AS_STR + ac0], Bm + (size_t)(col0 + ar0) * K + k0 + ac0);
            cp16(&BsP[stg*AS_TILE + ar1*AS_STR + ac1], Bm + (size_t)(col0 + ar1) * K + k0 + ac1);
        } else {
            cp16(&BfP[stg*BF_TILE + fk0*BF_STR + fn0], Bm + (size_t)(k0 + fk0) * N + col0 + fn0);
            cp16(&BfP[stg*BF_TILE + fk1*BF_STR + fn1], Bm + (size_t)(k0 + fk1) * N + col0 + fn1);
        }
        cp_commit();
    };

    issue(0, 0);
    if (nIter > 1) issue(1, 16);
    if (nIter > 2) issue(2, 32);

    float c[4][4][4];
    #pragma unroll
    for (int mt = 0; mt < 4; mt++)
        #pragma unroll
        for (int nt = 0; nt < 4; nt++)
            #pragma unroll
            for (int i = 0; i < 4; i++) c[mt][nt][i] = 0.f;

    for (int it = 0; it < nIter; it++) {
        if (it + 2 < nIter)      cp_wait2();
        else if (it + 1 < nIter) cp_wait1();
        else                     cp_wait0();
        __syncthreads();

        if (it + 3 < nIter) issue((it + 3) & 3, (it + 3) << 4);

        const int st = it & 3;
        const unsigned* Asb = AsP + st * AS_TILE;
        const unsigned* Bsb = BsP + st * AS_TILE;
        const unsigned* Bfb = BfP + st * BF_TILE;

        #pragma unroll
        for (int ks = 0; ks < 2; ks++) {
            const int kb = ks * 8;
            unsigned a[4][4], b[4][2];
            #pragma unroll
            for (int mt = 0; mt < 4; mt++) {
                int r = m0 + mt * 16 + lr;
                a[mt][0] = Asb[r*AS_STR + kb + lq];
                a[mt][1] = Asb[(r+8)*AS_STR + kb + lq];
                a[mt][2] = Asb[r*AS_STR + kb + 4 + lq];
                a[mt][3] = Asb[(r+8)*AS_STR + kb + 4 + lq];
            }
            #pragma unroll
            for (int nt = 0; nt < 4; nt++) {
                int cn = n0 + nt * 8 + lr;
                if constexpr (BT) {
                    b[nt][0] = Bsb[cn*AS_STR + kb + lq];
                    b[nt][1] = Bsb[cn*AS_STR + kb + 4 + lq];
                } else {
                    b[nt][0] = Bfb[(kb+lq)*BF_STR + cn];
                    b[nt][1] = Bfb[(kb+4+lq)*BF_STR + cn];
                }
            }
            #pragma unroll
            for (int mt = 0; mt < 4; mt++)
                #pragma unroll
                for (int nt = 0; nt < 4; nt++)
                    mma_tf32(c[mt][nt], a[mt], b[nt]);
        }
    }

    #pragma unroll
    for (int mt = 0; mt < 4; mt++) {
        int r0g = row0 + m0 + mt * 16 + lr;
        int r1g = r0g + 8;
        float g0 = (EPI == 3 || EPI == 5) ? gate[r0g] : 0.f;
        float g1 = (EPI == 3 || EPI == 5) ? gate[r1g] : 0.f;
        #pragma unroll
        for (int nt = 0; nt < 4; nt++) {
            int cg = col0 + n0 + nt * 8 + 2 * lq;
            size_t i0 = (size_t)r0g * N + cg;
            size_t i1 = (size_t)r1g * N + cg;
            float2* p0 = (float2*)&C[i0];
            float2* p1 = (float2*)&C[i1];
            float v0 = c[mt][nt][0], v1 = c[mt][nt][1];
            float v2 = c[mt][nt][2], v3 = c[mt][nt][3];
            if (EPI == 0) {
                *p0 = make_float2(v0, v1);
                *p1 = make_float2(v2, v3);
            } else if (EPI == 1) {
                float2 o0 = *p0, o1 = *p1;
                *p0 = make_float2(o0.x + v0, o0.y + v1);
                *p1 = make_float2(o1.x + v2, o1.y + v3);
            } else if (EPI == 2) {
                *p0 = make_float2(v0 / (1.f + __expf(-v0)), v1 / (1.f + __expf(-v1)));
                *p1 = make_float2(v2 / (1.f + __expf(-v2)), v3 / (1.f + __expf(-v3)));
            } else if (EPI == 3) {
                float2 o0 = *p0, o1 = *p1;
                *p0 = make_float2(o0.x + g0 * v0, o0.y + g0 * v1);
                *p1 = make_float2(o1.x + g1 * v2, o1.y + g1 * v3);
            } else if (EPI == 4) {
                float2 x0 = *(const float2*)&Xin[i0];
                float2 x1 = *(const float2*)&Xin[i1];
                *p0 = make_float2(x0.x + v0, x0.y + v1);
                *p1 = make_float2(x1.x + v2, x1.y + v3);
            } else {
                float2 x0 = *(const float2*)&Xin[i0];
                float2 x1 = *(const float2*)&Xin[i1];
                *p0 = make_float2(x0.x + g0 * v0, x0.y + g0 * v1);
                *p1 = make_float2(x1.x + g1 * v2, x1.y + g1 * v3);
            }
        }
    }
}

#define SMEM_BT ((NSTG*AS_TILE + NSTG*AS_TILE) * 4)
#define SMEM_KN ((NSTG*AS_TILE + NSTG*BF_TILE) * 4)

// ---------------------------------------------------------------------------
// RoPE table + apply
// ---------------------------------------------------------------------------
__global__ void rope_table_kernel()
{
    int idx = blockIdx.x * 256 + threadIdx.x;
    int t = idx >> 5, i = idx & 31;
    float inv = powf(10000.f, -(float)i / 32.f);
    float s, c;
    sincosf((float)t * inv, &s, &c);
    g_ropec[idx] = c;
    g_ropes[idx] = s;
}

__global__ void rope_kernel(float* __restrict__ qkv)
{
    int n = blockIdx.x;
    int t = n & (TT-1);
    for (int p = threadIdx.x; p < 1024; p += 256) {
        int which = p >> 9;
        int rem = p & 511;
        int h = rem >> 5;
        int i = rem & 31;
        float c = g_ropec[t*32 + i];
        float s = g_ropes[t*32 + i];
        size_t base = (size_t)n*3072 + (size_t)which*1024 + h*64 + i;
        float u1 = qkv[base], u2 = qkv[base+32];
        qkv[base]    = u1*c - u2*s;
        qkv[base+32] = u2*c + u1*s;
    }
}

// ---------------------------------------------------------------------------
// Flash attention v2 (unchanged from R5)
// ---------------------------------------------------------------------------
#define FQ_STR 68
#define FK_STR 68
#define FV_STR 72
#define FP_STR 36
#define FQ_OFF 0
#define FK_OFF (128*FQ_STR)
#define FV_OFF (FK_OFF + 3*32*FK_STR)
#define FP_OFF (FV_OFF + 3*32*FV_STR)
#define FLASH_SMEM ((FP_OFF + 128*FP_STR) * 4)

__global__ __launch_bounds__(256)
void flash_attn_tc(const float* __restrict__ qkv, float* __restrict__ out)
{
    extern __shared__ unsigned fsm[];
    unsigned* Qs = fsm + FQ_OFF;
    unsigned* Ks = fsm + FK_OFF;
    unsigned* Vs = fsm + FV_OFF;
    unsigned* Ps = fsm + FP_OFF;

    const int qb = blockIdx.x, bh = blockIdx.y;
    const int b = bh >> 4, h = bh & 15;
    const int tid = threadIdx.x, lane = tid & 31, warp = tid >> 5;
    const int lr = lane >> 2, lq = lane & 3;
    const int m0 = warp * 16;
    const int q0 = qb * 128;
    const int ntiles = 4*qb + 4;

    #pragma unroll
    for (int c = tid; c < 2048; c += 256) {
        int r = c >> 4, off = (c & 15) * 4;
        cp16(&Qs[r*FQ_STR + off], qkv + (size_t)(b*TT + q0 + r)*3072 + h*64 + off);
    }

    auto load_tile = [&](int kb, int buf) {
        unsigned* Kb = Ks + buf*(32*FK_STR);
        unsigned* Vb = Vs + buf*(32*FV_STR);
        #pragma unroll
        for (int c = tid; c < 512; c += 256) {
            int r = c >> 4, off = (c & 15) * 4;
            size_t base = (size_t)(b*TT + kb*32 + r)*3072 + h*64 + off;
            cp16(&Kb[r*FK_STR + off], qkv + base + 1024);
            cp16(&Vb[r*FV_STR + off], qkv + base + 2048);
        }
        cp_commit();
    };

    load_tile(0, 0);
    load_tile(1, 1);

    float mrow0 = -1e30f, mrow1 = -1e30f;
    float lrow0 = 0.f,    lrow1 = 0.f;
    float o[8][4];
    #pragma unroll
    for (int nt = 0; nt < 8; nt++)
        #pragma unroll
        for (int i = 0; i < 4; i++) o[nt][i] = 0.f;

    const int rg0 = q0 + m0 + lr, rg1 = rg0 + 8;

    for (int kb = 0; kb < ntiles; kb++) {
        if (kb + 1 < ntiles) cp_wait1(); else cp_wait0();
        __syncthreads();
        if (kb + 2 < ntiles) load_tile(kb + 2, (kb + 2) % 3);

        const unsigned* Kb = Ks + (kb % 3)*(32*FK_STR);
        const unsigned* Vb = Vs + (kb % 3)*(32*FV_STR);

        float s[4][4];
        #pragma unroll
        for (int nt = 0; nt < 4; nt++)
            #pragma unroll
            for (int i = 0; i < 4; i++) s[nt][i] = 0.f;
        #pragma unroll
        for (int kk = 0; kk < 8; kk++) {
            unsigned a[4];
            a[0] = Qs[(m0+lr)*FQ_STR + kk*8+lq];
            a[1] = Qs[(m0+lr+8)*FQ_STR + kk*8+lq];
            a[2] = Qs[(m0+lr)*FQ_STR + kk*8+lq+4];
            a[3] = Qs[(m0+lr+8)*FQ_STR + kk*8+lq+4];
            #pragma unroll
            for (int nt = 0; nt < 4; nt++) {
                unsigned bf[2] = { Kb[(nt*8+lr)*FK_STR + kk*8+lq],
                                   Kb[(nt*8+lr)*FK_STR + kk*8+lq+4] };
                mma_tf32(s[nt], a, bf);
            }
        }

        #pragma unroll
        for (int nt = 0; nt < 4; nt++)
            #pragma unroll
            for (int i = 0; i < 4; i++) s[nt][i] *= 0.125f;
        if (kb*32 + 31 > q0 + m0) {
            #pragma unroll
            for (int nt = 0; nt < 4; nt++) {
                int c0 = kb*32 + nt*8 + 2*lq;
                if (c0   > rg0) s[nt][0] = -1e30f;
                if (c0+1 > rg0) s[nt][1] = -1e30f;
                if (c0   > rg1) s[nt][2] = -1e30f;
                if (c0+1 > rg1) s[nt][3] = -1e30f;
            }
        }

        float mx0 = -1e30f, mx1 = -1e30f;
        #pragma unroll
        for (int nt = 0; nt < 4; nt++) {
            mx0 = fmaxf(mx0, fmaxf(s[nt][0], s[nt][1]));
            mx1 = fmaxf(mx1, fmaxf(s[nt][2], s[nt][3]));
        }
        mx0 = fmaxf(mx0, __shfl_xor_sync(0xffffffffu, mx0, 1));
        mx0 = fmaxf(mx0, __shfl_xor_sync(0xffffffffu, mx0, 2));
        mx1 = fmaxf(mx1, __shfl_xor_sync(0xffffffffu, mx1, 1));
        mx1 = fmaxf(mx1, __shfl_xor_sync(0xffffffffu, mx1, 2));
        float mn0 = fmaxf(mrow0, mx0), mn1 = fmaxf(mrow1, mx1);
        float corr0 = __expf(mrow0 - mn0), corr1 = __expf(mrow1 - mn1);
        float sum0 = 0.f, sum1 = 0.f;
        #pragma unroll
        for (int nt = 0; nt < 4; nt++) {
            s[nt][0] = __expf(s[nt][0] - mn0);
            s[nt][1] = __expf(s[nt][1] - mn0);
            s[nt][2] = __expf(s[nt][2] - mn1);
            s[nt][3] = __expf(s[nt][3] - mn1);
            sum0 += s[nt][0] + s[nt][1];
            sum1 += s[nt][2] + s[nt][3];
        }
        sum0 += __shfl_xor_sync(0xffffffffu, sum0, 1);
        sum0 += __shfl_xor_sync(0xffffffffu, sum0, 2);
        sum1 += __shfl_xor_sync(0xffffffffu, sum1, 1);
        sum1 += __shfl_xor_sync(0xffffffffu, sum1, 2);
        lrow0 = lrow0*corr0 + sum0;
        lrow1 = lrow1*corr1 + sum1;
        mrow0 = mn0; mrow1 = mn1;
        #pragma unroll
        for (int nt = 0; nt < 8; nt++) {
            o[nt][0] *= corr0; o[nt][1] *= corr0;
            o[nt][2] *= corr1; o[nt][3] *= corr1;
        }

        #pragma unroll
        for (int nt = 0; nt < 4; nt++) {
            Ps[(m0+lr)*FP_STR + nt*8+2*lq]     = __float_as_uint(s[nt][0]);
            Ps[(m0+lr)*FP_STR + nt*8+2*lq+1]   = __float_as_uint(s[nt][1]);
            Ps[(m0+lr+8)*FP_STR + nt*8+2*lq]   = __float_as_uint(s[nt][2]);
            Ps[(m0+lr+8)*FP_STR + nt*8+2*lq+1] = __float_as_uint(s[nt][3]);
        }
        __syncwarp();

        #pragma unroll
        for (int ks = 0; ks < 4; ks++) {
            unsigned a[4];
            a[0] = Ps[(m0+lr)*FP_STR + ks*8+lq];
            a[1] = Ps[(m0+lr+8)*FP_STR + ks*8+lq];
            a[2] = Ps[(m0+lr)*FP_STR + ks*8+lq+4];
            a[3] = Ps[(m0+lr+8)*FP_STR + ks*8+lq+4];
            #pragma unroll
            for (int nt = 0; nt < 8; nt++) {
                unsigned bf[2] = { Vb[(ks*8+lq)*FV_STR + nt*8+lr],
                                   Vb[(ks*8+4+lq)*FV_STR + nt*8+lr] };
                mma_tf32(o[nt], a, bf);
            }
        }
    }

    float inv0 = 1.f / lrow0, inv1 = 1.f / lrow1;
    #pragma unroll
    for (int nt = 0; nt < 8; nt++) {
        int cg = h*64 + nt*8 + 2*lq;
        size_t base0 = (size_t)(b*TT + rg0)*DD + cg;
        size_t base1 = (size_t)(b*TT + rg1)*DD + cg;
        out[base0]   = o[nt][0]*inv0;
        out[base0+1] = o[nt][1]*inv0;
        out[base1]   = o[nt][2]*inv1;
        out[base1+1] = o[nt][3]*inv1;
    }
}

// ---------------------------------------------------------------------------
// Router logits
// ---------------------------------------------------------------------------
__global__ void router_kernel(const float* __restrict__ xn,
                              const float* __restrict__ rw,
                              float* __restrict__ logits)
{
    int n = blockIdx.x;
    int warp = threadIdx.x >> 5, lane = threadIdx.x & 31;
    const float* xp = xn + (size_t)n*DD;
    for (int j = 0; j < 4; j++) {
        int e = warp*4 + j;
        const float* wp = rw + (size_t)e*DD;
        float s = 0.f;
        for (int i = lane; i < DD; i += 32) s += xp[i]*wp[i];
        #pragma unroll
        for (int off = 16; off; off >>= 1) s += __shfl_xor_sync(0xffffffffu, s, off);
        if (lane == 0) logits[n*EE + e] = s;
    }
}

// ---------------------------------------------------------------------------
// Softmax over 16 experts + top-2
// ---------------------------------------------------------------------------
__global__ void top2_kernel(const float* __restrict__ logits,
                            float* __restrict__ probs,
                            int* __restrict__ topi, float* __restrict__ topw)
{
    int n = blockIdx.x*blockDim.x + threadIdx.x;
    if (n >= NTOK) return;
    float l[EE];
    float mx = -1e30f;
    #pragma unroll
    for (int e = 0; e < EE; e++) { l[e] = logits[n*EE+e]; mx = fmaxf(mx, l[e]); }
    float sum = 0.f;
    #pragma unroll
    for (int e = 0; e < EE; e++) { l[e] = __expf(l[e]-mx); sum += l[e]; }
    float inv = 1.f/sum;
    #pragma unroll
    for (int e = 0; e < EE; e++) { l[e] *= inv; probs[n*EE+e] = l[e]; }
    int i0 = 0; float p0 = l[0];
    #pragma unroll
    for (int e = 1; e < EE; e++) if (l[e] > p0) { p0 = l[e]; i0 = e; }
    int i1 = (i0 == 0) ? 1 : 0; float p1 = l[i1];
    #pragma unroll
    for (int e = 0; e < EE; e++) if (e != i0 && l[e] > p1) { p1 = l[e]; i1 = e; }
    float ws = p0 + p1;
    topi[n*2]   = i0; topi[n*2+1] = i1;
    topw[n*2]   = p0/ws; topw[n*2+1] = p1/ws;
}

// ---------------------------------------------------------------------------
// Deterministic pmean reduction
// ---------------------------------------------------------------------------
__global__ void pmean_kernel(const float* __restrict__ probs, float* __restrict__ pmean)
{
    int e = blockIdx.x, tid = threadIdx.x;
    float s = 0.f;
    for (int t = tid; t < NTOK; t += 256) s += probs[t*EE + e];
    __shared__ float red[256];
    red[tid] = s;
    __syncthreads();
    for (int k = 128; k; k >>= 1) {
        if (tid < k) red[tid] += red[tid+k];
        __syncthreads();
    }
    if (tid == 0) pmean[e] = red[0] / (float)NTOK;
}

// ---------------------------------------------------------------------------
// Capacity position assignment
// ---------------------------------------------------------------------------
__global__ void assign_kernel(const int* __restrict__ topi,
                              const float* __restrict__ topw,
                              int* __restrict__ slot, int* __restrict__ keep,
                              float* __restrict__ wcomb, int* __restrict__ counts)
{
    int e = blockIdx.x;
    int tid = threadIdx.x;
    int lane = tid & 31, warp = tid >> 5;
    __shared__ int warpsum[8];
    int running = 0;
    for (int base = 0; base < NFLAT; base += 256) {
        int i = base + tid;
        int match = (topi[i] == e) ? 1 : 0;
        unsigned mask = __ballot_sync(0xffffffffu, match);
        if (lane == 0) warpsum[warp] = __popc(mask);
        __syncthreads();
        int wbase = 0, tot = 0;
        #pragma unroll
        for (int w = 0; w < 8; w++) {
            int c = warpsum[w];
            if (w < warp) wbase += c;
            tot += c;
        }
        if (match) {
            int pos = running + wbase + __popc(mask & ((1u << lane) - 1u));
            int kp = (pos < CAP) ? 1 : 0;
            slot[i]  = (pos < CAP-1) ? pos : (CAP-1);
            keep[i]  = kp;
            wcomb[i] = kp ? topw[i] : 0.f;
        }
        running += tot;
        __syncthreads();
    }
    if (tid == 0) counts[e] = running;
}

// ---------------------------------------------------------------------------
// Scatter / gather / aux / gate / softmax512
// ---------------------------------------------------------------------------
__global__ void scatter_kernel(const int* __restrict__ topi,
                               const int* __restrict__ slot,
                               const int* __restrict__ keep,
                               const float* __restrict__ xn,
                               float* __restrict__ buf)
{
    int i = blockIdx.x;
    if (!keep[i]) return;
    int e = topi[i], s = slot[i], tok = i >> 1;
    const float4* src = (const float4*)(xn + (size_t)tok*DD);
    float4* dst = (float4*)(buf + ((size_t)e*CAP + s)*DD);
    dst[threadIdx.x] = src[threadIdx.x];
}

__global__ void gather_kernel(const int* __restrict__ topi,
                              const int* __restrict__ slot,
                              const float* __restrict__ wcomb,
                              const float* __restrict__ yb,
                              float* __restrict__ x)
{
    int n = blockIdx.x;
    int t4 = threadIdx.x;
    float4* xp = (float4*)(x + (size_t)n*DD);
    float4 a = xp[t4];
    #pragma unroll
    for (int k = 0; k < 2; k++) {
        int i = n*2 + k;
        float w = wcomb[i];
        if (w != 0.f) {
            int e = topi[i], s = slot[i];
            const float4* yp = (const float4*)(yb + ((size_t)e*CAP + s)*DD);
            float4 yv = yp[t4];
            a.x += w*yv.x; a.y += w*yv.y; a.z += w*yv.z; a.w += w*yv.w;
        }
    }
    xp[t4] = a;
}

__global__ void aux_kernel(const int* __restrict__ counts,
                           const float* __restrict__ pmean,
                           float* __restrict__ out, int out_size)
{
    if (threadIdx.x == 0 && out_size > NTOK*DD) {
        float s = 0.f;
        for (int e = 0; e < EE; e++)
            s += ((float)counts[e] / (float)NTOK) * pmean[e];
        out[NTOK*DD] = (float)EE * s;
    }
}

__global__ void gate_kernel(const float* __restrict__ xn,
                            const float* __restrict__ gw,
                            const float* __restrict__ gb,
                            float* __restrict__ gate)
{
    int n = blockIdx.x, tid = threadIdx.x;
    const float4* xp = (const float4*)(xn + (size_t)n*DD);
    const float4* wp = (const float4*)gw;
    float4 xv = xp[tid], wv = wp[tid];
    float s = xv.x*wv.x + xv.y*wv.y + xv.z*wv.z + xv.w*wv.w;
    __shared__ float red[256];
    red[tid] = s;
    __syncthreads();
    for (int k = 128; k; k >>= 1) {
        if (tid < k) red[tid] += red[tid+k];
        __syncthreads();
    }
    if (tid == 0) gate[n] = 1.f / (1.f + __expf(-(red[0] + gb[0])));
}

__global__ void softmax512_kernel(float* __restrict__ tl)
{
    int n = blockIdx.x, tid = threadIdx.x;
    float* row = tl + (size_t)n*NPRIM;
    float v0 = row[tid]       * 0.0625f;
    float v1 = row[tid + 256] * 0.0625f;
    __shared__ float red[256];
    red[tid] = fmaxf(v0, v1);
    __syncthreads();
    for (int s = 128; s; s >>= 1) {
        if (tid < s) red[tid] = fmaxf(red[tid], red[tid+s]);
        __syncthreads();
    }
    float mx = red[0];
    __syncthreads();
    v0 = __expf(v0 - mx); v1 = __expf(v1 - mx);
    red[tid] = v0 + v1;
    __syncthreads();
    for (int s = 128; s; s >>= 1) {
        if (tid < s) red[tid] += red[tid+s];
        __syncthreads();
    }
    float inv = 1.f / red[0];
    row[tid] = v0*inv; row[tid+256] = v1*inv;
}

// ---------------------------------------------------------------------------
// Host launch with fork-join concurrency
// ---------------------------------------------------------------------------
extern "C" void kernel_launch(void* const* d_in, const int* in_sizes, int n_in,
                              void* d_out, int out_size)
{
    const float* x          = (const float*)d_in[0];
    const float* tou_embeds = (const float*)d_in[1];
    const float* norm1_w    = (const float*)d_in[2];
    const float* qkv_w      = (const float*)d_in[3];
    const float* attn_o_w   = (const float*)d_in[4];
    const float* norm2_w    = (const float*)d_in[5];
    const float* router_w   = (const float*)d_in[6];
    const float* moe_w1     = (const float*)d_in[7];
    const float* moe_w2     = (const float*)d_in[8];
    const float* norm3_w    = (const float*)d_in[9];
    const float* tou_q_w    = (const float*)d_in[10];
    const float* tou_k_w    = (const float*)d_in[11];
    const float* tou_v_w    = (const float*)d_in[12];
    const float* tou_o_w    = (const float*)d_in[13];
    const float* tou_gate_w = (const float*)d_in[14];
    const float* tou_gate_b = (const float*)d_in[15];

    cudaFuncSetAttribute(gemm128<true,0>,  cudaFuncAttributeMaxDynamicSharedMemorySize, SMEM_BT);
    cudaFuncSetAttribute(gemm128<true,4>,  cudaFuncAttributeMaxDynamicSharedMemorySize, SMEM_BT);
    cudaFuncSetAttribute(gemm128<true,5>,  cudaFuncAttributeMaxDynamicSharedMemorySize, SMEM_BT);
    cudaFuncSetAttribute(gemm128<false,0>, cudaFuncAttributeMaxDynamicSharedMemorySize, SMEM_KN);
    cudaFuncSetAttribute(gemm128<false,2>, cudaFuncAttributeMaxDynamicSharedMemorySize, SMEM_KN);
    cudaFuncSetAttribute(flash_attn_tc,    cudaFuncAttributeMaxDynamicSharedMemorySize, FLASH_SMEM);

    float *gx, *gxn, *gqkv, *gattn, *glogits, *gprobs, *gtopw, *gwcomb,
          *gpmean, *gbuf, *gh, *gyb, *gtq, *gtk, *gtv, *gtl, *gtout, *ggate;
    int *gtopi, *gslot, *gkeep, *gcounts;
    cudaGetSymbolAddress((void**)&gx, g_x);
    cudaGetSymbolAddress((void**)&gxn, g_xn);
    cudaGetSymbolAddress((void**)&gqkv, g_qkv);
    cudaGetSymbolAddress((void**)&gattn, g_attn);
    cudaGetSymbolAddress((void**)&glogits, g_logits);
    cudaGetSymbolAddress((void**)&gprobs, g_probs);
    cudaGetSymbolAddress((void**)&gtopi, g_topi);
    cudaGetSymbolAddress((void**)&gtopw, g_topw);
    cudaGetSymbolAddress((void**)&gslot, g_slot);
    cudaGetSymbolAddress((void**)&gkeep, g_keep);
    cudaGetSymbolAddress((void**)&gwcomb, g_wcomb);
    cudaGetSymbolAddress((void**)&gcounts, g_counts);
    cudaGetSymbolAddress((void**)&gpmean, g_pmean);
    cudaGetSymbolAddress((void**)&gbuf, g_buf);
    cudaGetSymbolAddress((void**)&gh, g_h);
    cudaGetSymbolAddress((void**)&gyb, g_yb);
    cudaGetSymbolAddress((void**)&gtq, g_tq);
    cudaGetSymbolAddress((void**)&gtk, g_tk);
    cudaGetSymbolAddress((void**)&gtv, g_tv);
    cudaGetSymbolAddress((void**)&gtl, g_tl);
    cudaGetSymbolAddress((void**)&gtout, g_tout);
    cudaGetSymbolAddress((void**)&ggate, g_gate);

    // ---- fork: side work independent of x ----
    cudaEventRecord(ev_root, 0);

    cudaStreamWaitEvent(s1, ev_root, 0);
    rope_table_kernel<<<TT*32/256, 256, 0, s1>>>();
    cudaEventRecord(ev_tab, s1);
    gemm128<true,0><<<dim3(DP/128, NPRIM/128, 1), 256, SMEM_BT, s1>>>(tou_embeds, tou_k_w, gtk,
        NPRIM, DP, DP, 0, 0, 0, nullptr, nullptr);
    gemm128<true,0><<<dim3(DP/128, NPRIM/128, 1), 256, SMEM_BT, s1>>>(tou_embeds, tou_v_w, gtv,
        NPRIM, DP, DP, 0, 0, 0, nullptr, nullptr);
    cudaEventRecord(ev_s1, s1);

    cudaStreamWaitEvent(s2, ev_root, 0);
    cudaMemsetAsync(gbuf, 0, (size_t)EE*CAP*DD*sizeof(float), s2);
    cudaEventRecord(ev_s2, s2);

    // ---- Block 1: RoPE attention (main) ----
    rmsnorm_kernel<<<NTOK, 256>>>(x, norm1_w, gxn);
    gemm128<true,0><<<dim3(3*DD/128, NTOK/128, 1), 256, SMEM_BT>>>(gxn, qkv_w, gqkv,
        NTOK, 3*DD, DD, 0, 0, 0, nullptr, nullptr);
    cudaStreamWaitEvent(0, ev_tab, 0);
    rope_kernel<<<NTOK, 256>>>(gqkv);
    flash_attn_tc<<<dim3(TT/128, BB*HH), 256, FLASH_SMEM>>>(gqkv, gattn);
    gemm128<true,4><<<dim3(DD/128, NTOK/128, 1), 256, SMEM_BT>>>(gattn, attn_o_w, gx,
        NTOK, DD, DD, 0, 0, 0, nullptr, x);           // gx = x + proj

    // ---- Block 2: MoE ----
    rmsnorm_kernel<<<NTOK, 256>>>(gx, norm2_w, gxn);
    router_kernel<<<NTOK, 128>>>(gxn, router_w, glogits);
    top2_kernel<<<NTOK/128, 128>>>(glogits, gprobs, gtopi, gtopw);
    cudaEventRecord(ev_top2, 0);
    cudaStreamWaitEvent(s2, ev_top2, 0);
    pmean_kernel<<<EE, 256, 0, s2>>>(gprobs, gpmean);
    cudaEventRecord(ev_pm, s2);
    assign_kernel<<<EE, 256>>>(gtopi, gtopw, gslot, gkeep, gwcomb, gcounts);
    cudaStreamWaitEvent(0, ev_s2, 0);
    scatter_kernel<<<NFLAT, 256>>>(gtopi, gslot, gkeep, gxn, gbuf);
    gemm128<false,2><<<dim3(FF/128, CAP/128, EE), 256, SMEM_KN>>>(gbuf, moe_w1, gh,
        CAP, FF, DD, (long long)CAP*DD, (long long)DD*FF, (long long)CAP*FF, nullptr, nullptr);
    gemm128<false,0><<<dim3(DD/128, CAP/128, EE), 256, SMEM_KN>>>(gh, moe_w2, gyb,
        CAP, DD, FF, (long long)CAP*FF, (long long)FF*DD, (long long)CAP*DD, nullptr, nullptr);
    gather_kernel<<<NTOK, 256>>>(gtopi, gslot, gwcomb, gyb, gx);
    cudaStreamWaitEvent(0, ev_pm, 0);
    aux_kernel<<<1, 32>>>(gcounts, gpmean, (float*)d_out, out_size);

    // ---- Block 3: ToU cross-attention ----
    rmsnorm_kernel<<<NTOK, 256>>>(gx, norm3_w, gxn);
    cudaEventRecord(ev_n3, 0);
    cudaStreamWaitEvent(s2, ev_n3, 0);
    gate_kernel<<<NTOK, 256, 0, s2>>>(gxn, tou_gate_w, tou_gate_b, ggate);
    cudaEventRecord(ev_gate, s2);
    gemm128<true,0><<<dim3(DP/128, NTOK/128, 1), 256, SMEM_BT>>>(gxn, tou_q_w, gtq,
        NTOK, DP, DD, 0, 0, 0, nullptr, nullptr);
    cudaStreamWaitEvent(0, ev_s1, 0);
    gemm128<true,0><<<dim3(NPRIM/128, NTOK/128, 1), 256, SMEM_BT>>>(gtq, gtk, gtl,
        NTOK, NPRIM, DP, 0, 0, 0, nullptr, nullptr);
    softmax512_kernel<<<NTOK, 256>>>(gtl);
    gemm128<false,0><<<dim3(DP/128, NTOK/128, 1), 256, SMEM_KN>>>(gtl, gtv, gtout,
        NTOK, DP, NPRIM, 0, 0, 0, nullptr, nullptr);
    cudaStreamWaitEvent(0, ev_gate, 0);
    gemm128<true,5><<<dim3(DD/128, NTOK/128, 1), 256, SMEM_BT>>>(gtout, tou_o_w, (float*)d_out,
        NTOK, DD, DP, 0, 0, 0, ggate, gx);            // d_out = gx + gate*proj
}

// round 8
// speedup vs baseline: 5.9469x; 1.5300x over previous
#include <cuda_runtime.h>
#include <cuda_bf16.h>
#include <cuda_fp16.h>
#include <math.h>

// ---------------------------------------------------------------------------
// Problem constants
// ---------------------------------------------------------------------------
#define BB 2
#define TT 2048
#define DD 1024
#define HH 16
#define DH 64
#define NTOK (BB*TT)            // 4096
#define EE 16
#define KK 2
#define FF 2048
#define CAP 640
#define DP 256
#define NPRIM 512
#define NFLAT (NTOK*KK)         // 8192

// ---------------------------------------------------------------------------
// Scratch (device globals; no allocation allowed)
// ---------------------------------------------------------------------------
__device__ float g_x[NTOK*DD];
__device__ float g_xn[NTOK*DD];          // fp32 xn (router bit-exactness)
__device__ float g_qkv[NTOK*3*DD];
__device__ float g_logits[NTOK*EE];
__device__ float g_probs[NTOK*EE];
__device__ int   g_topi[NFLAT];
__device__ float g_topw[NFLAT];
__device__ int   g_slot[NFLAT];
__device__ int   g_keep[NFLAT];
__device__ float g_wcomb[NFLAT];
__device__ int   g_counts[EE];
__device__ float g_pmean[EE];
__device__ float g_yb[EE*CAP*DD];
__device__ float g_tl[NTOK*NPRIM];
__device__ float g_gate[NTOK];
__device__ float g_ropec[TT*32];
__device__ float g_ropes[TT*32];

// fp16 buffers
__device__ __half gh_xn[NTOK*DD];
__device__ __half gh_attn[NTOK*DD];
__device__ __half gh_buf[EE*CAP*DD];
__device__ __half gh_h[EE*CAP*FF];
__device__ __half gh_tq[NTOK*DP];
__device__ __half gh_tk[NPRIM*DP];
__device__ __half gh_tv[NPRIM*DP];
__device__ __half gh_tl[NTOK*NPRIM];
__device__ __half gh_tout[NTOK*DP];
// fp16 weights (converted once per launch)
__device__ __half gh_qkvw[3*DD*DD];
__device__ __half gh_aow[DD*DD];
__device__ __half gh_w1[EE*DD*FF];
__device__ __half gh_w2[EE*FF*DD];
__device__ __half gh_tqw[DP*DD];
__device__ __half gh_tkw[DP*DP];
__device__ __half gh_tvw[DP*DP];
__device__ __half gh_tow[DD*DP];
__device__ __half gh_emb[NPRIM*DP];

// ---------------------------------------------------------------------------
// Streams / events (host resources, created once)
// ---------------------------------------------------------------------------
static cudaStream_t s1, s2;
static cudaEvent_t ev_root, ev_tab, ev_s1, ev_s2, ev_aow, ev_top2, ev_pm, ev_n3, ev_gate;
namespace {
struct InitOnce {
    InitOnce() {
        cudaStreamCreateWithFlags(&s1, cudaStreamNonBlocking);
        cudaStreamCreateWithFlags(&s2, cudaStreamNonBlocking);
        cudaEventCreateWithFlags(&ev_root, cudaEventDisableTiming);
        cudaEventCreateWithFlags(&ev_tab,  cudaEventDisableTiming);
        cudaEventCreateWithFlags(&ev_s1,   cudaEventDisableTiming);
        cudaEventCreateWithFlags(&ev_s2,   cudaEventDisableTiming);
        cudaEventCreateWithFlags(&ev_aow,  cudaEventDisableTiming);
        cudaEventCreateWithFlags(&ev_top2, cudaEventDisableTiming);
        cudaEventCreateWithFlags(&ev_pm,   cudaEventDisableTiming);
        cudaEventCreateWithFlags(&ev_n3,   cudaEventDisableTiming);
        cudaEventCreateWithFlags(&ev_gate, cudaEventDisableTiming);
    }
};
static InitOnce init_once_;
}

// ---------------------------------------------------------------------------
// MMA / cp.async / ldmatrix helpers
// ---------------------------------------------------------------------------
__device__ __forceinline__ void mma_tf32(float c[4], const unsigned a[4], const unsigned b[2])
{
    asm volatile(
        "mma.sync.aligned.m16n8k8.row.col.f32.tf32.tf32.f32 "
        "{%0,%1,%2,%3},{%4,%5,%6,%7},{%8,%9},{%0,%1,%2,%3};"
        : "+f"(c[0]), "+f"(c[1]), "+f"(c[2]), "+f"(c[3])
        : "r"(a[0]), "r"(a[1]), "r"(a[2]), "r"(a[3]),
          "r"(b[0]), "r"(b[1]));
}

__device__ __forceinline__ void mma_f16(float c[4], const unsigned a[4], const unsigned b[2])
{
    asm volatile(
        "mma.sync.aligned.m16n8k16.row.col.f32.f16.f16.f32 "
        "{%0,%1,%2,%3},{%4,%5,%6,%7},{%8,%9},{%0,%1,%2,%3};"
        : "+f"(c[0]), "+f"(c[1]), "+f"(c[2]), "+f"(c[3])
        : "r"(a[0]), "r"(a[1]), "r"(a[2]), "r"(a[3]),
          "r"(b[0]), "r"(b[1]));
}

__device__ __forceinline__ void ldsm4(unsigned r[4], unsigned addr)
{
    asm volatile("ldmatrix.sync.aligned.m8n8.x4.shared.b16 {%0,%1,%2,%3}, [%4];"
        : "=r"(r[0]), "=r"(r[1]), "=r"(r[2]), "=r"(r[3]) : "r"(addr));
}
__device__ __forceinline__ void ldsm4t(unsigned r[4], unsigned addr)
{
    asm volatile("ldmatrix.sync.aligned.m8n8.x4.trans.shared.b16 {%0,%1,%2,%3}, [%4];"
        : "=r"(r[0]), "=r"(r[1]), "=r"(r[2]), "=r"(r[3]) : "r"(addr));
}

__device__ __forceinline__ void cp16(void* smem_dst, const void* gptr)
{
    unsigned saddr = (unsigned)__cvta_generic_to_shared(smem_dst);
    asm volatile("cp.async.cg.shared.global [%0], [%1], 16;\n"
                 :: "r"(saddr), "l"(gptr));
}
__device__ __forceinline__ void cp_commit()  { asm volatile("cp.async.commit_group;\n"); }
__device__ __forceinline__ void cp_wait2()   { asm volatile("cp.async.wait_group 2;\n"); }
__device__ __forceinline__ void cp_wait1()   { asm volatile("cp.async.wait_group 1;\n"); }
__device__ __forceinline__ void cp_wait0()   { asm volatile("cp.async.wait_group 0;\n"); }

// ---------------------------------------------------------------------------
// f32 -> f16 conversion (vectorized, exact grids; n % 2048 == 0)
// ---------------------------------------------------------------------------
__global__ void f2h_kernel(const float* __restrict__ in, __half* __restrict__ out)
{
    int i = (blockIdx.x*256 + threadIdx.x) * 8;
    float4 v0 = *(const float4*)(in + i);
    float4 v1 = *(const float4*)(in + i + 4);
    __half2* o = (__half2*)(out + i);
    o[0] = __floats2half2_rn(v0.x, v0.y);
    o[1] = __floats2half2_rn(v0.z, v0.w);
    o[2] = __floats2half2_rn(v1.x, v1.y);
    o[3] = __floats2half2_rn(v1.z, v1.w);
}

// ---------------------------------------------------------------------------
// RMSNorm: one block per token; fp16 out (+optional fp32 out)
// ---------------------------------------------------------------------------
__global__ void rmsnorm_h(const float* __restrict__ x,
                          const float* __restrict__ w,
                          __half* __restrict__ outh,
                          float* __restrict__ outf)
{
    int n = blockIdx.x;
    int tid = threadIdx.x;
    const float4* xp = (const float4*)(x + (size_t)n*DD);
    float4 xv = xp[tid];
    float ss = xv.x*xv.x + xv.y*xv.y + xv.z*xv.z + xv.w*xv.w;
    __shared__ float red[256];
    red[tid] = ss;
    __syncthreads();
    for (int s = 128; s; s >>= 1) {
        if (tid < s) red[tid] += red[tid+s];
        __syncthreads();
    }
    float scale = rsqrtf(red[0] / (float)DD + 1e-6f);
    const float4* wp = (const float4*)w;
    float4 wv = wp[tid];
    float a = xv.x*scale*wv.x, b = xv.y*scale*wv.y;
    float c = xv.z*scale*wv.z, d = xv.w*scale*wv.w;
    __half2* oh = (__half2*)(outh + (size_t)n*DD);
    oh[2*tid]   = __floats2half2_rn(a, b);
    oh[2*tid+1] = __floats2half2_rn(c, d);
    if (outf) ((float4*)(outf + (size_t)n*DD))[tid] = make_float4(a, b, c, d);
}

// ---------------------------------------------------------------------------
// FP16 tensor-core GEMM (m16n8k16): 4-stage cp.async, ldmatrix fragments.
//   C[M,N] = A[M,K] * op(B);  BT ? B[N,K] : B[K,N]
// EPI: 0=store, 2=silu store, 4=C=Xin+v, 5=C=Xin+gate*v
// OUTH: output __half (else float)
// Smem: A [4][128][40] half, B BT [4][128][40] half, B KN [4][32][136] half
// ---------------------------------------------------------------------------
#define AH_STR 40
#define BH_STR 136
#define NSTG 4
#define AH_TILE (128*AH_STR)      // half elems / stage
#define BH_TILE (32*BH_STR)

template<bool BT, int EPI, bool OUTH>
__global__ __launch_bounds__(256, 2)
void gemm_h(const __half* __restrict__ A, const __half* __restrict__ Bm,
            void* __restrict__ Cv, int M, int N, int K,
            long long sA, long long sB, long long sC,
            const float* __restrict__ gate, const float* __restrict__ Xin)
{
    A  += blockIdx.z * sA;
    Bm += blockIdx.z * sB;

    extern __shared__ __half smem_h[];
    __half* AsP = smem_h;
    __half* BsP = smem_h + NSTG*AH_TILE;
    const unsigned sbase = (unsigned)__cvta_generic_to_shared(smem_h);
    const unsigned bbase = sbase + NSTG*AH_TILE*2;

    const int tid  = threadIdx.x;
    const int lane = tid & 31;
    const int warp = tid >> 5;
    const int lr   = lane >> 2;
    const int lq   = lane & 3;
    const int g    = lane >> 3;       // ldmatrix group
    const int tr   = lane & 7;
    const int wm   = warp & 1, wn = warp >> 1;
    const int m0   = wm * 64, n0 = wn * 32;
    const int row0 = blockIdx.y * 128, col0 = blockIdx.x * 128;

    // cp.async chunk decomposition: 512 chunks of 16B (8 halfs) per operand
    const int c0i = tid, c1i = tid + 256;
    const int ar0 = c0i >> 2, ac0 = (c0i & 3) * 8;
    const int ar1 = c1i >> 2, ac1 = (c1i & 3) * 8;
    const int fr0 = c0i >> 4, fo0 = (c0i & 15) * 8;
    const int fr1 = c1i >> 4, fo1 = (c1i & 15) * 8;

    const int nIter = K >> 5;   // BK = 32

    auto issue = [&](int stg, int k0) {
        cp16(&AsP[stg*AH_TILE + ar0*AH_STR + ac0], A + (size_t)(row0 + ar0) * K + k0 + ac0);
        cp16(&AsP[stg*AH_TILE + ar1*AH_STR + ac1], A + (size_t)(row0 + ar1) * K + k0 + ac1);
        if constexpr (BT) {
            cp16(&BsP[stg*AH_TILE + ar0*AH_STR + ac0], Bm + (size_t)(col0 + ar0) * K + k0 + ac0);
            cp16(&BsP[stg*AH_TILE + ar1*AH_STR + ac1], Bm + (size_t)(col0 + ar1) * K + k0 + ac1);
        } else {
            cp16(&BsP[stg*BH_TILE + fr0*BH_STR + fo0], Bm + (size_t)(k0 + fr0) * N + col0 + fo0);
            cp16(&BsP[stg*BH_TILE + fr1*BH_STR + fo1], Bm + (size_t)(k0 + fr1) * N + col0 + fo1);
        }
        cp_commit();
    };

    issue(0, 0);
    if (nIter > 1) issue(1, 32);
    if (nIter > 2) issue(2, 64);

    float c[4][4][4];
    #pragma unroll
    for (int mt = 0; mt < 4; mt++)
        #pragma unroll
        for (int nt = 0; nt < 4; nt++)
            #pragma unroll
            for (int i = 0; i < 4; i++) c[mt][nt][i] = 0.f;

    // precomputed fragment address components (in half elems)
    const int a_row = (g & 1) * 8 + tr;     // + m0 + mt*16
    const int a_col = (g >> 1) * 8;         // + kb
    const int bt_row = (g >> 1) * 8 + tr;   // + n0 + ntp*16
    const int bt_col = (g & 1) * 8;         // + kb
    const int bf_row = (g & 1) * 8 + tr;    // + kb
    const int bf_col = (g >> 1) * 8;        // + n0 + ntp*16

    for (int it = 0; it < nIter; it++) {
        if (it + 2 < nIter)      cp_wait2();
        else if (it + 1 < nIter) cp_wait1();
        else                     cp_wait0();
        __syncthreads();

        if (it + 3 < nIter) issue((it + 3) & 3, (it + 3) << 5);

        const int st = it & 3;
        const unsigned abase = sbase + st*AH_TILE*2;
        const unsigned btb   = bbase + (BT ? st*AH_TILE*2 : st*BH_TILE*2);

        #pragma unroll
        for (int ks = 0; ks < 2; ks++) {
            const int kb = ks * 16;
            unsigned a[4][4];
            #pragma unroll
            for (int mt = 0; mt < 4; mt++) {
                unsigned addr = abase + ((m0 + mt*16 + a_row)*AH_STR + kb + a_col)*2;
                ldsm4(a[mt], addr);
            }
            unsigned b[4][2];
            #pragma unroll
            for (int ntp = 0; ntp < 2; ntp++) {
                unsigned r[4];
                if constexpr (BT) {
                    unsigned addr = btb + ((n0 + ntp*16 + bt_row)*AH_STR + kb + bt_col)*2;
                    ldsm4(r, addr);
                } else {
                    unsigned addr = btb + ((kb + bf_row)*BH_STR + n0 + ntp*16 + bf_col)*2;
                    ldsm4t(r, addr);
                }
                b[ntp*2][0]   = r[0]; b[ntp*2][1]   = r[1];
                b[ntp*2+1][0] = r[2]; b[ntp*2+1][1] = r[3];
            }
            #pragma unroll
            for (int mt = 0; mt < 4; mt++)
                #pragma unroll
                for (int nt = 0; nt < 4; nt++)
                    mma_f16(c[mt][nt], a[mt], b[nt]);
        }
    }

    // epilogue
    float* Cf = (float*)Cv + (OUTH ? 0 : blockIdx.z * sC);
    __half* Ch = (__half*)Cv + (OUTH ? blockIdx.z * sC : 0);
    #pragma unroll
    for (int mt = 0; mt < 4; mt++) {
        int r0g = row0 + m0 + mt * 16 + lr;
        int r1g = r0g + 8;
        float g0 = (EPI == 5) ? gate[r0g] : 0.f;
        float g1 = (EPI == 5) ? gate[r1g] : 0.f;
        #pragma unroll
        for (int nt = 0; nt < 4; nt++) {
            int cg = col0 + n0 + nt * 8 + 2 * lq;
            size_t i0 = (size_t)r0g * N + cg;
            size_t i1 = (size_t)r1g * N + cg;
            float v0 = c[mt][nt][0], v1 = c[mt][nt][1];
            float v2 = c[mt][nt][2], v3 = c[mt][nt][3];
            if (EPI == 2) {
                v0 = v0 / (1.f + __expf(-v0));
                v1 = v1 / (1.f + __expf(-v1));
                v2 = v2 / (1.f + __expf(-v2));
                v3 = v3 / (1.f + __expf(-v3));
            } else if (EPI == 4) {
                float2 x0 = *(const float2*)&Xin[i0];
                float2 x1 = *(const float2*)&Xin[i1];
                v0 += x0.x; v1 += x0.y; v2 += x1.x; v3 += x1.y;
            } else if (EPI == 5) {
                float2 x0 = *(const float2*)&Xin[i0];
                float2 x1 = *(const float2*)&Xin[i1];
                v0 = x0.x + g0*v0; v1 = x0.y + g0*v1;
                v2 = x1.x + g1*v2; v3 = x1.y + g1*v3;
            }
            if (OUTH) {
                *(__half2*)&Ch[i0] = __floats2half2_rn(v0, v1);
                *(__half2*)&Ch[i1] = __floats2half2_rn(v2, v3);
            } else {
                *(float2*)&Cf[i0] = make_float2(v0, v1);
                *(float2*)&Cf[i1] = make_float2(v2, v3);
            }
        }
    }
}

#define SMEM_HBT ((NSTG*AH_TILE + NSTG*AH_TILE) * 2)   // 40960 B
#define SMEM_HKN ((NSTG*AH_TILE + NSTG*BH_TILE) * 2)   // 29184 B

// ---------------------------------------------------------------------------
// RoPE table + apply (fp32 qkv, unchanged)
// ---------------------------------------------------------------------------
__global__ void rope_table_kernel()
{
    int idx = blockIdx.x * 256 + threadIdx.x;
    int t = idx >> 5, i = idx & 31;
    float inv = powf(10000.f, -(float)i / 32.f);
    float s, c;
    sincosf((float)t * inv, &s, &c);
    g_ropec[idx] = c;
    g_ropes[idx] = s;
}

__global__ void rope_kernel(float* __restrict__ qkv)
{
    int n = blockIdx.x;
    int t = n & (TT-1);
    for (int p = threadIdx.x; p < 1024; p += 256) {
        int which = p >> 9;
        int rem = p & 511;
        int h = rem >> 5;
        int i = rem & 31;
        float c = g_ropec[t*32 + i];
        float s = g_ropes[t*32 + i];
        size_t base = (size_t)n*3072 + (size_t)which*1024 + h*64 + i;
        float u1 = qkv[base], u2 = qkv[base+32];
        qkv[base]    = u1*c - u2*s;
        qkv[base+32] = u2*c + u1*s;
    }
}

// ---------------------------------------------------------------------------
// Flash attention (TF32 internals unchanged; fp16 output)
// ---------------------------------------------------------------------------
#define FQ_STR 68
#define FK_STR 68
#define FV_STR 72
#define FP_STR 36
#define FQ_OFF 0
#define FK_OFF (128*FQ_STR)
#define FV_OFF (FK_OFF + 3*32*FK_STR)
#define FP_OFF (FV_OFF + 3*32*FV_STR)
#define FLASH_SMEM ((FP_OFF + 128*FP_STR) * 4)

__global__ __launch_bounds__(256)
void flash_attn_tc(const float* __restrict__ qkv, __half* __restrict__ out)
{
    extern __shared__ unsigned fsm[];
    unsigned* Qs = fsm + FQ_OFF;
    unsigned* Ks = fsm + FK_OFF;
    unsigned* Vs = fsm + FV_OFF;
    unsigned* Ps = fsm + FP_OFF;

    const int qb = blockIdx.x, bh = blockIdx.y;
    const int b = bh >> 4, h = bh & 15;
    const int tid = threadIdx.x, lane = tid & 31, warp = tid >> 5;
    const int lr = lane >> 2, lq = lane & 3;
    const int m0 = warp * 16;
    const int q0 = qb * 128;
    const int ntiles = 4*qb + 4;

    #pragma unroll
    for (int c = tid; c < 2048; c += 256) {
        int r = c >> 4, off = (c & 15) * 4;
        cp16(&Qs[r*FQ_STR + off], qkv + (size_t)(b*TT + q0 + r)*3072 + h*64 + off);
    }

    auto load_tile = [&](int kb, int buf) {
        unsigned* Kb = Ks + buf*(32*FK_STR);
        unsigned* Vb = Vs + buf*(32*FV_STR);
        #pragma unroll
        for (int c = tid; c < 512; c += 256) {
            int r = c >> 4, off = (c & 15) * 4;
            size_t base = (size_t)(b*TT + kb*32 + r)*3072 + h*64 + off;
            cp16(&Kb[r*FK_STR + off], qkv + base + 1024);
            cp16(&Vb[r*FV_STR + off], qkv + base + 2048);
        }
        cp_commit();
    };

    load_tile(0, 0);
    load_tile(1, 1);

    float mrow0 = -1e30f, mrow1 = -1e30f;
    float lrow0 = 0.f,    lrow1 = 0.f;
    float o[8][4];
    #pragma unroll
    for (int nt = 0; nt < 8; nt++)
        #pragma unroll
        for (int i = 0; i < 4; i++) o[nt][i] = 0.f;

    const int rg0 = q0 + m0 + lr, rg1 = rg0 + 8;

    for (int kb = 0; kb < ntiles; kb++) {
        if (kb + 1 < ntiles) cp_wait1(); else cp_wait0();
        __syncthreads();
        if (kb + 2 < ntiles) load_tile(kb + 2, (kb + 2) % 3);

        const unsigned* Kb = Ks + (kb % 3)*(32*FK_STR);
        const unsigned* Vb = Vs + (kb % 3)*(32*FV_STR);

        float s[4][4];
        #pragma unroll
        for (int nt = 0; nt < 4; nt++)
            #pragma unroll
            for (int i = 0; i < 4; i++) s[nt][i] = 0.f;
        #pragma unroll
        for (int kk = 0; kk < 8; kk++) {
            unsigned a[4];
            a[0] = Qs[(m0+lr)*FQ_STR + kk*8+lq];
            a[1] = Qs[(m0+lr+8)*FQ_STR + kk*8+lq];
            a[2] = Qs[(m0+lr)*FQ_STR + kk*8+lq+4];
            a[3] = Qs[(m0+lr+8)*FQ_STR + kk*8+lq+4];
            #pragma unroll
            for (int nt = 0; nt < 4; nt++) {
                unsigned bf[2] = { Kb[(nt*8+lr)*FK_STR + kk*8+lq],
                                   Kb[(nt*8+lr)*FK_STR + kk*8+lq+4] };
                mma_tf32(s[nt], a, bf);
            }
        }

        #pragma unroll
        for (int nt = 0; nt < 4; nt++)
            #pragma unroll
            for (int i = 0; i < 4; i++) s[nt][i] *= 0.125f;
        if (kb*32 + 31 > q0 + m0) {
            #pragma unroll
            for (int nt = 0; nt < 4; nt++) {
                int c0 = kb*32 + nt*8 + 2*lq;
                if (c0   > rg0) s[nt][0] = -1e30f;
                if (c0+1 > rg0) s[nt][1] = -1e30f;
                if (c0   > rg1) s[nt][2] = -1e30f;
                if (c0+1 > rg1) s[nt][3] = -1e30f;
            }
        }

        float mx0 = -1e30f, mx1 = -1e30f;
        #pragma unroll
        for (int nt = 0; nt < 4; nt++) {
            mx0 = fmaxf(mx0, fmaxf(s[nt][0], s[nt][1]));
            mx1 = fmaxf(mx1, fmaxf(s[nt][2], s[nt][3]));
        }
        mx0 = fmaxf(mx0, __shfl_xor_sync(0xffffffffu, mx0, 1));
        mx0 = fmaxf(mx0, __shfl_xor_sync(0xffffffffu, mx0, 2));
        mx1 = fmaxf(mx1, __shfl_xor_sync(0xffffffffu, mx1, 1));
        mx1 = fmaxf(mx1, __shfl_xor_sync(0xffffffffu, mx1, 2));
        float mn0 = fmaxf(mrow0, mx0), mn1 = fmaxf(mrow1, mx1);
        float corr0 = __expf(mrow0 - mn0), corr1 = __expf(mrow1 - mn1);
        float sum0 = 0.f, sum1 = 0.f;
        #pragma unroll
        for (int nt = 0; nt < 4; nt++) {
            s[nt][0] = __expf(s[nt][0] - mn0);
            s[nt][1] = __expf(s[nt][1] - mn0);
            s[nt][2] = __expf(s[nt][2] - mn1);
            s[nt][3] = __expf(s[nt][3] - mn1);
            sum0 += s[nt][0] + s[nt][1];
            sum1 += s[nt][2] + s[nt][3];
        }
        sum0 += __shfl_xor_sync(0xffffffffu, sum0, 1);
        sum0 += __shfl_xor_sync(0xffffffffu, sum0, 2);
        sum1 += __shfl_xor_sync(0xffffffffu, sum1, 1);
        sum1 += __shfl_xor_sync(0xffffffffu, sum1, 2);
        lrow0 = lrow0*corr0 + sum0;
        lrow1 = lrow1*corr1 + sum1;
        mrow0 = mn0; mrow1 = mn1;
        #pragma unroll
        for (int nt = 0; nt < 8; nt++) {
            o[nt][0] *= corr0; o[nt][1] *= corr0;
            o[nt][2] *= corr1; o[nt][3] *= corr1;
        }

        #pragma unroll
        for (int nt = 0; nt < 4; nt++) {
            Ps[(m0+lr)*FP_STR + nt*8+2*lq]     = __float_as_uint(s[nt][0]);
            Ps[(m0+lr)*FP_STR + nt*8+2*lq+1]   = __float_as_uint(s[nt][1]);
            Ps[(m0+lr+8)*FP_STR + nt*8+2*lq]   = __float_as_uint(s[nt][2]);
            Ps[(m0+lr+8)*FP_STR + nt*8+2*lq+1] = __float_as_uint(s[nt][3]);
        }
        __syncwarp();

        #pragma unroll
        for (int ks = 0; ks < 4; ks++) {
            unsigned a[4];
            a[0] = Ps[(m0+lr)*FP_STR + ks*8+lq];
            a[1] = Ps[(m0+lr+8)*FP_STR + ks*8+lq];
            a[2] = Ps[(m0+lr)*FP_STR + ks*8+lq+4];
            a[3] = Ps[(m0+lr+8)*FP_STR + ks*8+lq+4];
            #pragma unroll
            for (int nt = 0; nt < 8; nt++) {
                unsigned bf[2] = { Vb[(ks*8+lq)*FV_STR + nt*8+lr],
                                   Vb[(ks*8+4+lq)*FV_STR + nt*8+lr] };
                mma_tf32(o[nt], a, bf);
            }
        }
    }

    float inv0 = 1.f / lrow0, inv1 = 1.f / lrow1;
    #pragma unroll
    for (int nt = 0; nt < 8; nt++) {
        int cg = h*64 + nt*8 + 2*lq;
        size_t base0 = (size_t)(b*TT + rg0)*DD + cg;
        size_t base1 = (size_t)(b*TT + rg1)*DD + cg;
        ((__half2*)out)[base0>>1] = __floats2half2_rn(o[nt][0]*inv0, o[nt][1]*inv0);
        ((__half2*)out)[base1>>1] = __floats2half2_rn(o[nt][2]*inv1, o[nt][3]*inv1);
    }
}

// ---------------------------------------------------------------------------
// Router logits (fp32 xn — bit-identical to prior rounds)
// ---------------------------------------------------------------------------
__global__ void router_kernel(const float* __restrict__ xn,
                              const float* __restrict__ rw,
                              float* __restrict__ logits)
{
    int n = blockIdx.x;
    int warp = threadIdx.x >> 5, lane = threadIdx.x & 31;
    const float* xp = xn + (size_t)n*DD;
    for (int j = 0; j < 4; j++) {
        int e = warp*4 + j;
        const float* wp = rw + (size_t)e*DD;
        float s = 0.f;
        for (int i = lane; i < DD; i += 32) s += xp[i]*wp[i];
        #pragma unroll
        for (int off = 16; off; off >>= 1) s += __shfl_xor_sync(0xffffffffu, s, off);
        if (lane == 0) logits[n*EE + e] = s;
    }
}

__global__ void top2_kernel(const float* __restrict__ logits,
                            float* __restrict__ probs,
                            int* __restrict__ topi, float* __restrict__ topw)
{
    int n = blockIdx.x*blockDim.x + threadIdx.x;
    if (n >= NTOK) return;
    float l[EE];
    float mx = -1e30f;
    #pragma unroll
    for (int e = 0; e < EE; e++) { l[e] = logits[n*EE+e]; mx = fmaxf(mx, l[e]); }
    float sum = 0.f;
    #pragma unroll
    for (int e = 0; e < EE; e++) { l[e] = __expf(l[e]-mx); sum += l[e]; }
    float inv = 1.f/sum;
    #pragma unroll
    for (int e = 0; e < EE; e++) { l[e] *= inv; probs[n*EE+e] = l[e]; }
    int i0 = 0; float p0 = l[0];
    #pragma unroll
    for (int e = 1; e < EE; e++) if (l[e] > p0) { p0 = l[e]; i0 = e; }
    int i1 = (i0 == 0) ? 1 : 0; float p1 = l[i1];
    #pragma unroll
    for (int e = 0; e < EE; e++) if (e != i0 && l[e] > p1) { p1 = l[e]; i1 = e; }
    float ws = p0 + p1;
    topi[n*2]   = i0; topi[n*2+1] = i1;
    topw[n*2]   = p0/ws; topw[n*2+1] = p1/ws;
}

__global__ void pmean_kernel(const float* __restrict__ probs, float* __restrict__ pmean)
{
    int e = blockIdx.x, tid = threadIdx.x;
    float s = 0.f;
    for (int t = tid; t < NTOK; t += 256) s += probs[t*EE + e];
    __shared__ float red[256];
    red[tid] = s;
    __syncthreads();
    for (int k = 128; k; k >>= 1) {
        if (tid < k) red[tid] += red[tid+k];
        __syncthreads();
    }
    if (tid == 0) pmean[e] = red[0] / (float)NTOK;
}

__global__ void assign_kernel(const int* __restrict__ topi,
                              const float* __restrict__ topw,
                              int* __restrict__ slot, int* __restrict__ keep,
                              float* __restrict__ wcomb, int* __restrict__ counts)
{
    int e = blockIdx.x;
    int tid = threadIdx.x;
    int lane = tid & 31, warp = tid >> 5;
    __shared__ int warpsum[8];
    int running = 0;
    for (int base = 0; base < NFLAT; base += 256) {
        int i = base + tid;
        int match = (topi[i] == e) ? 1 : 0;
        unsigned mask = __ballot_sync(0xffffffffu, match);
        if (lane == 0) warpsum[warp] = __popc(mask);
        __syncthreads();
        int wbase = 0, tot = 0;
        #pragma unroll
        for (int w = 0; w < 8; w++) {
            int c = warpsum[w];
            if (w < warp) wbase += c;
            tot += c;
        }
        if (match) {
            int pos = running + wbase + __popc(mask & ((1u << lane) - 1u));
            int kp = (pos < CAP) ? 1 : 0;
            slot[i]  = (pos < CAP-1) ? pos : (CAP-1);
            keep[i]  = kp;
            wcomb[i] = kp ? topw[i] : 0.f;
        }
        running += tot;
        __syncthreads();
    }
    if (tid == 0) counts[e] = running;
}

// scatter fp16 rows (2KB per row, 256 threads x 8B)
__global__ void scatter_kernel(const int* __restrict__ topi,
                               const int* __restrict__ slot,
                               const int* __restrict__ keep,
                               const __half* __restrict__ xn,
                               __half* __restrict__ buf)
{
    int i = blockIdx.x;
    if (!keep[i]) return;
    int e = topi[i], s = slot[i], tok = i >> 1;
    const uint2* src = (const uint2*)(xn + (size_t)tok*DD);
    uint2* dst = (uint2*)(buf + ((size_t)e*CAP + s)*DD);
    dst[threadIdx.x] = src[threadIdx.x];
}

__global__ void gather_kernel(const int* __restrict__ topi,
                              const int* __restrict__ slot,
                              const float* __restrict__ wcomb,
                              const float* __restrict__ yb,
                              float* __restrict__ x)
{
    int n = blockIdx.x;
    int t4 = threadIdx.x;
    float4* xp = (float4*)(x + (size_t)n*DD);
    float4 a = xp[t4];
    #pragma unroll
    for (int k = 0; k < 2; k++) {
        int i = n*2 + k;
        float w = wcomb[i];
        if (w != 0.f) {
            int e = topi[i], s = slot[i];
            const float4* yp = (const float4*)(yb + ((size_t)e*CAP + s)*DD);
            float4 yv = yp[t4];
            a.x += w*yv.x; a.y += w*yv.y; a.z += w*yv.z; a.w += w*yv.w;
        }
    }
    xp[t4] = a;
}

__global__ void aux_kernel(const int* __restrict__ counts,
                           const float* __restrict__ pmean,
                           float* __restrict__ out, int out_size)
{
    if (threadIdx.x == 0 && out_size > NTOK*DD) {
        float s = 0.f;
        for (int e = 0; e < EE; e++)
            s += ((float)counts[e] / (float)NTOK) * pmean[e];
        out[NTOK*DD] = (float)EE * s;
    }
}

// gate from fp16 xn
__global__ void gate_kernel(const __half* __restrict__ xn,
                            const float* __restrict__ gw,
                            const float* __restrict__ gb,
                            float* __restrict__ gate)
{
    int n = blockIdx.x, tid = threadIdx.x;
    const __half2* xp = (const __half2*)(xn + (size_t)n*DD);
    const float4* wp = (const float4*)gw;
    float2 f0 = __half22float2(xp[2*tid]);
    float2 f1 = __half22float2(xp[2*tid+1]);
    float4 wv = wp[tid];
    float s = f0.x*wv.x + f0.y*wv.y + f1.x*wv.z + f1.y*wv.w;
    __shared__ float red[256];
    red[tid] = s;
    __syncthreads();
    for (int k = 128; k; k >>= 1) {
        if (tid < k) red[tid] += red[tid+k];
        __syncthreads();
    }
    if (tid == 0) gate[n] = 1.f / (1.f + __expf(-(red[0] + gb[0])));
}

// softmax over 512 (fp32 in, fp16 out)
__global__ void softmax512_kernel(const float* __restrict__ tl, __half* __restrict__ outh)
{
    int n = blockIdx.x, tid = threadIdx.x;
    const float* row = tl + (size_t)n*NPRIM;
    __half* orow = outh + (size_t)n*NPRIM;
    float v0 = row[tid]       * 0.0625f;
    float v1 = row[tid + 256] * 0.0625f;
    __shared__ float red[256];
    red[tid] = fmaxf(v0, v1);
    __syncthreads();
    for (int s = 128; s; s >>= 1) {
        if (tid < s) red[tid] = fmaxf(red[tid], red[tid+s]);
        __syncthreads();
    }
    float mx = red[0];
    __syncthreads();
    v0 = __expf(v0 - mx); v1 = __expf(v1 - mx);
    red[tid] = v0 + v1;
    __syncthreads();
    for (int s = 128; s; s >>= 1) {
        if (tid < s) red[tid] += red[tid+s];
        __syncthreads();
    }
    float inv = 1.f / red[0];
    orow[tid]       = __float2half_rn(v0*inv);
    orow[tid + 256] = __float2half_rn(v1*inv);
}

// ---------------------------------------------------------------------------
// Host launch
// ---------------------------------------------------------------------------
#define F2H(stream, src, dst, n) f2h_kernel<<<(n)/2048, 256, 0, stream>>>(src, dst)

extern "C" void kernel_launch(void* const* d_in, const int* in_sizes, int n_in,
                              void* d_out, int out_size)
{
    const float* x          = (const float*)d_in[0];
    const float* tou_embeds = (const float*)d_in[1];
    const float* norm1_w    = (const float*)d_in[2];
    const float* qkv_w      = (const float*)d_in[3];
    const float* attn_o_w   = (const float*)d_in[4];
    const float* norm2_w    = (const float*)d_in[5];
    const float* router_w   = (const float*)d_in[6];
    const float* moe_w1     = (const float*)d_in[7];
    const float* moe_w2     = (const float*)d_in[8];
    const float* norm3_w    = (const float*)d_in[9];
    const float* tou_q_w    = (const float*)d_in[10];
    const float* tou_k_w    = (const float*)d_in[11];
    const float* tou_v_w    = (const float*)d_in[12];
    const float* tou_o_w    = (const float*)d_in[13];
    const float* tou_gate_w = (const float*)d_in[14];
    const float* tou_gate_b = (const float*)d_in[15];

    cudaFuncSetAttribute(gemm_h<true,0,false>,  cudaFuncAttributeMaxDynamicSharedMemorySize, SMEM_HBT);
    cudaFuncSetAttribute(gemm_h<true,0,true>,   cudaFuncAttributeMaxDynamicSharedMemorySize, SMEM_HBT);
    cudaFuncSetAttribute(gemm_h<true,4,false>,  cudaFuncAttributeMaxDynamicSharedMemorySize, SMEM_HBT);
    cudaFuncSetAttribute(gemm_h<true,5,false>,  cudaFuncAttributeMaxDynamicSharedMemorySize, SMEM_HBT);
    cudaFuncSetAttribute(gemm_h<false,0,false>, cudaFuncAttributeMaxDynamicSharedMemorySize, SMEM_HKN);
    cudaFuncSetAttribute(gemm_h<false,0,true>,  cudaFuncAttributeMaxDynamicSharedMemorySize, SMEM_HKN);
    cudaFuncSetAttribute(gemm_h<false,2,true>,  cudaFuncAttributeMaxDynamicSharedMemorySize, SMEM_HKN);
    cudaFuncSetAttribute(flash_attn_tc,         cudaFuncAttributeMaxDynamicSharedMemorySize, FLASH_SMEM);

    float *gx, *gxn, *gqkv, *glogits, *gprobs, *gtopw, *gwcomb, *gpmean,
          *gyb, *gtl, *ggate;
    int *gtopi, *gslot, *gkeep, *gcounts;
    __half *hxn, *hattn, *hbuf, *hh, *htq, *htk, *htv, *htl, *htout;
    __half *hqkvw, *haow, *hw1, *hw2, *htqw, *htkw, *htvw, *htow, *hemb;
    cudaGetSymbolAddress((void**)&gx, g_x);
    cudaGetSymbolAddress((void**)&gxn, g_xn);
    cudaGetSymbolAddress((void**)&gqkv, g_qkv);
    cudaGetSymbolAddress((void**)&glogits, g_logits);
    cudaGetSymbolAddress((void**)&gprobs, g_probs);
    cudaGetSymbolAddress((void**)&gtopi, g_topi);
    cudaGetSymbolAddress((void**)&gtopw, g_topw);
    cudaGetSymbolAddress((void**)&gslot, g_slot);
    cudaGetSymbolAddress((void**)&gkeep, g_keep);
    cudaGetSymbolAddress((void**)&gwcomb, g_wcomb);
    cudaGetSymbolAddress((void**)&gcounts, g_counts);
    cudaGetSymbolAddress((void**)&gpmean, g_pmean);
    cudaGetSymbolAddress((void**)&gyb, g_yb);
    cudaGetSymbolAddress((void**)&gtl, g_tl);
    cudaGetSymbolAddress((void**)&ggate, g_gate);
    cudaGetSymbolAddress((void**)&hxn, gh_xn);
    cudaGetSymbolAddress((void**)&hattn, gh_attn);
    cudaGetSymbolAddress((void**)&hbuf, gh_buf);
    cudaGetSymbolAddress((void**)&hh, gh_h);
    cudaGetSymbolAddress((void**)&htq, gh_tq);
    cudaGetSymbolAddress((void**)&htk, gh_tk);
    cudaGetSymbolAddress((void**)&htv, gh_tv);
    cudaGetSymbolAddress((void**)&htl, gh_tl);
    cudaGetSymbolAddress((void**)&htout, gh_tout);
    cudaGetSymbolAddress((void**)&hqkvw, gh_qkvw);
    cudaGetSymbolAddress((void**)&haow, gh_aow);
    cudaGetSymbolAddress((void**)&hw1, gh_w1);
    cudaGetSymbolAddress((void**)&hw2, gh_w2);
    cudaGetSymbolAddress((void**)&htqw, gh_tqw);
    cudaGetSymbolAddress((void**)&htkw, gh_tkw);
    cudaGetSymbolAddress((void**)&htvw, gh_tvw);
    cudaGetSymbolAddress((void**)&htow, gh_tow);
    cudaGetSymbolAddress((void**)&hemb, gh_emb);

    cudaEventRecord(ev_root, 0);

    // ---- s1: rope table, ToU weight conversions + tiny GEMMs ----
    cudaStreamWaitEvent(s1, ev_root, 0);
    rope_table_kernel<<<TT*32/256, 256, 0, s1>>>();
    cudaEventRecord(ev_tab, s1);
    F2H(s1, tou_embeds, hemb, NPRIM*DP);
    F2H(s1, tou_k_w, htkw, DP*DP);
    F2H(s1, tou_v_w, htvw, DP*DP);
    F2H(s1, tou_q_w, htqw, DP*DD);
    F2H(s1, tou_o_w, htow, DD*DP);
    gemm_h<true,0,true><<<dim3(DP/128, NPRIM/128, 1), 256, SMEM_HBT, s1>>>(
        hemb, htkw, htk, NPRIM, DP, DP, 0, 0, 0, nullptr, nullptr);
    gemm_h<true,0,true><<<dim3(DP/128, NPRIM/128, 1), 256, SMEM_HBT, s1>>>(
        hemb, htvw, htv, NPRIM, DP, DP, 0, 0, 0, nullptr, nullptr);
    cudaEventRecord(ev_s1, s1);

    // ---- s2: attn_o conversion, gbuf memset, MoE weight conversions ----
    cudaStreamWaitEvent(s2, ev_root, 0);
    F2H(s2, attn_o_w, haow, DD*DD);
    cudaEventRecord(ev_aow, s2);
    cudaMemsetAsync(hbuf, 0, (size_t)EE*CAP*DD*sizeof(__half), s2);
    F2H(s2, moe_w1, hw1, EE*DD*FF);
    F2H(s2, moe_w2, hw2, EE*FF*DD);
    cudaEventRecord(ev_s2, s2);

    // ---- Block 1 ----
    F2H(0, qkv_w, hqkvw, 3*DD*DD);
    rmsnorm_h<<<NTOK, 256>>>(x, norm1_w, hxn, nullptr);
    gemm_h<true,0,false><<<dim3(3*DD/128, NTOK/128, 1), 256, SMEM_HBT>>>(
        hxn, hqkvw, gqkv, NTOK, 3*DD, DD, 0, 0, 0, nullptr, nullptr);
    cudaStreamWaitEvent(0, ev_tab, 0);
    rope_kernel<<<NTOK, 256>>>(gqkv);
    flash_attn_tc<<<dim3(TT/128, BB*HH), 256, FLASH_SMEM>>>(gqkv, hattn);
    cudaStreamWaitEvent(0, ev_aow, 0);
    gemm_h<true,4,false><<<dim3(DD/128, NTOK/128, 1), 256, SMEM_HBT>>>(
        hattn, haow, gx, NTOK, DD, DD, 0, 0, 0, nullptr, x);   // gx = x + proj

    // ---- Block 2: MoE ----
    rmsnorm_h<<<NTOK, 256>>>(gx, norm2_w, hxn, gxn);
    router_kernel<<<NTOK, 128>>>(gxn, router_w, glogits);
    top2_kernel<<<NTOK/128, 128>>>(glogits, gprobs, gtopi, gtopw);
    cudaEventRecord(ev_top2, 0);
    cudaStreamWaitEvent(s2, ev_top2, 0);
    pmean_kernel<<<EE, 256, 0, s2>>>(gprobs, gpmean);
    cudaEventRecord(ev_pm, s2);
    assign_kernel<<<EE, 256>>>(gtopi, gtopw, gslot, gkeep, gwcomb, gcounts);
    cudaStreamWaitEvent(0, ev_s2, 0);
    scatter_kernel<<<NFLAT, 256>>>(gtopi, gslot, gkeep, hxn, hbuf);
    gemm_h<false,2,true><<<dim3(FF/128, CAP/128, EE), 256, SMEM_HKN>>>(
        hbuf, hw1, hh, CAP, FF, DD,
        (long long)CAP*DD, (long long)DD*FF, (long long)CAP*FF, nullptr, nullptr);
    gemm_h<false,0,false><<<dim3(DD/128, CAP/128, EE), 256, SMEM_HKN>>>(
        hh, hw2, gyb, CAP, DD, FF,
        (long long)CAP*FF, (long long)FF*DD, (long long)CAP*DD, nullptr, nullptr);
    gather_kernel<<<NTOK, 256>>>(gtopi, gslot, gwcomb, gyb, gx);
    cudaStreamWaitEvent(0, ev_pm, 0);
    aux_kernel<<<1, 32>>>(gcounts, gpmean, (float*)d_out, out_size);

    // ---- Block 3: ToU cross-attention ----
    rmsnorm_h<<<NTOK, 256>>>(gx, norm3_w, hxn, nullptr);
    cudaEventRecord(ev_n3, 0);
    cudaStreamWaitEvent(s2, ev_n3, 0);
    gate_kernel<<<NTOK, 256, 0, s2>>>(hxn, tou_gate_w, tou_gate_b, ggate);
    cudaEventRecord(ev_gate, s2);
    cudaStreamWaitEvent(0, ev_s1, 0);
    gemm_h<true,0,true><<<dim3(DP/128, NTOK/128, 1), 256, SMEM_HBT>>>(
        hxn, htqw, htq, NTOK, DP, DD, 0, 0, 0, nullptr, nullptr);
    gemm_h<true,0,false><<<dim3(NPRIM/128, NTOK/128, 1), 256, SMEM_HBT>>>(
        htq, htk, gtl, NTOK, NPRIM, DP, 0, 0, 0, nullptr, nullptr);
    softmax512_kernel<<<NTOK, 256>>>(gtl, htl);
    gemm_h<false,0,true><<<dim3(DP/128, NTOK/128, 1), 256, SMEM_HKN>>>(
        htl, htv, htout, NTOK, DP, NPRIM, 0, 0, 0, nullptr, nullptr);
    cudaStreamWaitEvent(0, ev_gate, 0);
    gemm_h<true,5,false><<<dim3(DD/128, NTOK/128, 1), 256, SMEM_HBT>>>(
        htout, htow, (float*)d_out, NTOK, DD, DP, 0, 0, 0, ggate, gx);
}

// round 10
// speedup vs baseline: 6.6404x; 1.1166x over previous
#include <cuda_runtime.h>
#include <cuda_bf16.h>
#include <cuda_fp16.h>
#include <math.h>

// ---------------------------------------------------------------------------
// Problem constants
// ---------------------------------------------------------------------------
#define BB 2
#define TT 2048
#define DD 1024
#define HH 16
#define DH 64
#define NTOK (BB*TT)            // 4096
#define EE 16
#define KK 2
#define FF 2048
#define CAP 640
#define DP 256
#define NPRIM 512
#define NFLAT (NTOK*KK)         // 8192

// ---------------------------------------------------------------------------
// Scratch (device globals; no allocation allowed)
// ---------------------------------------------------------------------------
__device__ float g_x[NTOK*DD];
__device__ float g_xn[NTOK*DD];          // fp32 xn (router bit-exactness)
__device__ float g_qkv[NTOK*3*DD];
__device__ float g_logits[NTOK*EE];
__device__ float g_probs[NTOK*EE];
__device__ int   g_topi[NFLAT];
__device__ float g_topw[NFLAT];
__device__ int   g_slot[NFLAT];
__device__ int   g_keep[NFLAT];
__device__ float g_wcomb[NFLAT];
__device__ int   g_counts[EE];
__device__ float g_pmean[EE];
__device__ float g_yb[EE*CAP*DD];
__device__ float g_tl[NTOK*NPRIM];
__device__ float g_gate[NTOK];
__device__ float g_ropec[TT*32];
__device__ float g_ropes[TT*32];

// fp16 buffers
__device__ __half gh_qkv[NTOK*3*DD];
__device__ __half gh_xn[NTOK*DD];
__device__ __half gh_attn[NTOK*DD];
__device__ __half gh_buf[EE*CAP*DD];
__device__ __half gh_h[EE*CAP*FF];
__device__ __half gh_tq[NTOK*DP];
__device__ __half gh_tk[NPRIM*DP];
__device__ __half gh_tv[NPRIM*DP];
__device__ __half gh_tl[NTOK*NPRIM];
__device__ __half gh_tout[NTOK*DP];
// fp16 weights (converted once per launch)
__device__ __half gh_qkvw[3*DD*DD];
__device__ __half gh_aow[DD*DD];
__device__ __half gh_w1[EE*DD*FF];
__device__ __half gh_w2[EE*FF*DD];
__device__ __half gh_tqw[DP*DD];
__device__ __half gh_tkw[DP*DP];
__device__ __half gh_tvw[DP*DP];
__device__ __half gh_tow[DD*DP];
__device__ __half gh_emb[NPRIM*DP];

// ---------------------------------------------------------------------------
// Streams / events (host resources, created once)
// ---------------------------------------------------------------------------
static cudaStream_t s1, s2;
static cudaEvent_t ev_root, ev_tab, ev_s1, ev_s2, ev_qkvw, ev_aow,
                   ev_top2, ev_pm, ev_n3, ev_gate;
namespace {
struct InitOnce {
    InitOnce() {
        cudaStreamCreateWithFlags(&s1, cudaStreamNonBlocking);
        cudaStreamCreateWithFlags(&s2, cudaStreamNonBlocking);
        cudaEventCreateWithFlags(&ev_root, cudaEventDisableTiming);
        cudaEventCreateWithFlags(&ev_tab,  cudaEventDisableTiming);
        cudaEventCreateWithFlags(&ev_s1,   cudaEventDisableTiming);
        cudaEventCreateWithFlags(&ev_s2,   cudaEventDisableTiming);
        cudaEventCreateWithFlags(&ev_qkvw, cudaEventDisableTiming);
        cudaEventCreateWithFlags(&ev_aow,  cudaEventDisableTiming);
        cudaEventCreateWithFlags(&ev_top2, cudaEventDisableTiming);
        cudaEventCreateWithFlags(&ev_pm,   cudaEventDisableTiming);
        cudaEventCreateWithFlags(&ev_n3,   cudaEventDisableTiming);
        cudaEventCreateWithFlags(&ev_gate, cudaEventDisableTiming);
    }
};
static InitOnce init_once_;
}

// ---------------------------------------------------------------------------
// MMA / cp.async / ldmatrix helpers
// ---------------------------------------------------------------------------
__device__ __forceinline__ void mma_f16(float c[4], const unsigned a[4], const unsigned b[2])
{
    asm volatile(
        "mma.sync.aligned.m16n8k16.row.col.f32.f16.f16.f32 "
        "{%0,%1,%2,%3},{%4,%5,%6,%7},{%8,%9},{%0,%1,%2,%3};"
        : "+f"(c[0]), "+f"(c[1]), "+f"(c[2]), "+f"(c[3])
        : "r"(a[0]), "r"(a[1]), "r"(a[2]), "r"(a[3]),
          "r"(b[0]), "r"(b[1]));
}

__device__ __forceinline__ void ldsm4(unsigned r[4], unsigned addr)
{
    asm volatile("ldmatrix.sync.aligned.m8n8.x4.shared.b16 {%0,%1,%2,%3}, [%4];"
        : "=r"(r[0]), "=r"(r[1]), "=r"(r[2]), "=r"(r[3]) : "r"(addr));
}
__device__ __forceinline__ void ldsm4t(unsigned r[4], unsigned addr)
{
    asm volatile("ldmatrix.sync.aligned.m8n8.x4.trans.shared.b16 {%0,%1,%2,%3}, [%4];"
        : "=r"(r[0]), "=r"(r[1]), "=r"(r[2]), "=r"(r[3]) : "r"(addr));
}

__device__ __forceinline__ void cp16(void* smem_dst, const void* gptr)
{
    unsigned saddr = (unsigned)__cvta_generic_to_shared(smem_dst);
    asm volatile("cp.async.cg.shared.global [%0], [%1], 16;\n"
                 :: "r"(saddr), "l"(gptr));
}
__device__ __forceinline__ void cp_commit()  { asm volatile("cp.async.commit_group;\n"); }
__device__ __forceinline__ void cp_wait2()   { asm volatile("cp.async.wait_group 2;\n"); }
__device__ __forceinline__ void cp_wait1()   { asm volatile("cp.async.wait_group 1;\n"); }
__device__ __forceinline__ void cp_wait0()   { asm volatile("cp.async.wait_group 0;\n"); }

// ---------------------------------------------------------------------------
// f32 -> f16 conversion (n % 2048 == 0)
// ---------------------------------------------------------------------------
__global__ void f2h_kernel(const float* __restrict__ in, __half* __restrict__ out)
{
    int i = (blockIdx.x*256 + threadIdx.x) * 8;
    float4 v0 = *(const float4*)(in + i);
    float4 v1 = *(const float4*)(in + i + 4);
    __half2* o = (__half2*)(out + i);
    o[0] = __floats2half2_rn(v0.x, v0.y);
    o[1] = __floats2half2_rn(v0.z, v0.w);
    o[2] = __floats2half2_rn(v1.x, v1.y);
    o[3] = __floats2half2_rn(v1.z, v1.w);
}

// ---------------------------------------------------------------------------
// RMSNorm: one block per token; fp16 out (+optional fp32 out)
// ---------------------------------------------------------------------------
__global__ void rmsnorm_h(const float* __restrict__ x,
                          const float* __restrict__ w,
                          __half* __restrict__ outh,
                          float* __restrict__ outf)
{
    int n = blockIdx.x;
    int tid = threadIdx.x;
    const float4* xp = (const float4*)(x + (size_t)n*DD);
    float4 xv = xp[tid];
    float ss = xv.x*xv.x + xv.y*xv.y + xv.z*xv.z + xv.w*xv.w;
    __shared__ float red[256];
    red[tid] = ss;
    __syncthreads();
    for (int s = 128; s; s >>= 1) {
        if (tid < s) red[tid] += red[tid+s];
        __syncthreads();
    }
    float scale = rsqrtf(red[0] / (float)DD + 1e-6f);
    const float4* wp = (const float4*)w;
    float4 wv = wp[tid];
    float a = xv.x*scale*wv.x, b = xv.y*scale*wv.y;
    float c = xv.z*scale*wv.z, d = xv.w*scale*wv.w;
    __half2* oh = (__half2*)(outh + (size_t)n*DD);
    oh[2*tid]   = __floats2half2_rn(a, b);
    oh[2*tid+1] = __floats2half2_rn(c, d);
    if (outf) ((float4*)(outf + (size_t)n*DD))[tid] = make_float4(a, b, c, d);
}

// ---------------------------------------------------------------------------
// FP16 tensor-core GEMM (m16n8k16): 4-stage cp.async, ldmatrix fragments.
// (unchanged from R8)
// ---------------------------------------------------------------------------
#define AH_STR 40
#define BH_STR 136
#define NSTG 4
#define AH_TILE (128*AH_STR)
#define BH_TILE (32*BH_STR)

template<bool BT, int EPI, bool OUTH>
__global__ __launch_bounds__(256, 2)
void gemm_h(const __half* __restrict__ A, const __half* __restrict__ Bm,
            void* __restrict__ Cv, int M, int N, int K,
            long long sA, long long sB, long long sC,
            const float* __restrict__ gate, const float* __restrict__ Xin)
{
    A  += blockIdx.z * sA;
    Bm += blockIdx.z * sB;

    extern __shared__ __half smem_h[];
    __half* AsP = smem_h;
    __half* BsP = smem_h + NSTG*AH_TILE;
    const unsigned sbase = (unsigned)__cvta_generic_to_shared(smem_h);
    const unsigned bbase = sbase + NSTG*AH_TILE*2;

    const int tid  = threadIdx.x;
    const int lane = tid & 31;
    const int warp = tid >> 5;
    const int lr   = lane >> 2;
    const int lq   = lane & 3;
    const int g    = lane >> 3;
    const int tr   = lane & 7;
    const int wm   = warp & 1, wn = warp >> 1;
    const int m0   = wm * 64, n0 = wn * 32;
    const int row0 = blockIdx.y * 128, col0 = blockIdx.x * 128;

    const int c0i = tid, c1i = tid + 256;
    const int ar0 = c0i >> 2, ac0 = (c0i & 3) * 8;
    const int ar1 = c1i >> 2, ac1 = (c1i & 3) * 8;
    const int fr0 = c0i >> 4, fo0 = (c0i & 15) * 8;
    const int fr1 = c1i >> 4, fo1 = (c1i & 15) * 8;

    const int nIter = K >> 5;

    auto issue = [&](int stg, int k0) {
        cp16(&AsP[stg*AH_TILE + ar0*AH_STR + ac0], A + (size_t)(row0 + ar0) * K + k0 + ac0);
        cp16(&AsP[stg*AH_TILE + ar1*AH_STR + ac1], A + (size_t)(row0 + ar1) * K + k0 + ac1);
        if constexpr (BT) {
            cp16(&BsP[stg*AH_TILE + ar0*AH_STR + ac0], Bm + (size_t)(col0 + ar0) * K + k0 + ac0);
            cp16(&BsP[stg*AH_TILE + ar1*AH_STR + ac1], Bm + (size_t)(col0 + ar1) * K + k0 + ac1);
        } else {
            cp16(&BsP[stg*BH_TILE + fr0*BH_STR + fo0], Bm + (size_t)(k0 + fr0) * N + col0 + fo0);
            cp16(&BsP[stg*BH_TILE + fr1*BH_STR + fo1], Bm + (size_t)(k0 + fr1) * N + col0 + fo1);
        }
        cp_commit();
    };

    issue(0, 0);
    if (nIter > 1) issue(1, 32);
    if (nIter > 2) issue(2, 64);

    float c[4][4][4];
    #pragma unroll
    for (int mt = 0; mt < 4; mt++)
        #pragma unroll
        for (int nt = 0; nt < 4; nt++)
            #pragma unroll
            for (int i = 0; i < 4; i++) c[mt][nt][i] = 0.f;

    const int a_row = (g & 1) * 8 + tr;
    const int a_col = (g >> 1) * 8;
    const int bt_row = (g >> 1) * 8 + tr;
    const int bt_col = (g & 1) * 8;
    const int bf_row = (g & 1) * 8 + tr;
    const int bf_col = (g >> 1) * 8;

    for (int it = 0; it < nIter; it++) {
        if (it + 2 < nIter)      cp_wait2();
        else if (it + 1 < nIter) cp_wait1();
        else                     cp_wait0();
        __syncthreads();

        if (it + 3 < nIter) issue((it + 3) & 3, (it + 3) << 5);

        const int st = it & 3;
        const unsigned abase = sbase + st*AH_TILE*2;
        const unsigned btb   = bbase + (BT ? st*AH_TILE*2 : st*BH_TILE*2);

        #pragma unroll
        for (int ks = 0; ks < 2; ks++) {
            const int kb = ks * 16;
            unsigned a[4][4];
            #pragma unroll
            for (int mt = 0; mt < 4; mt++) {
                unsigned addr = abase + ((m0 + mt*16 + a_row)*AH_STR + kb + a_col)*2;
                ldsm4(a[mt], addr);
            }
            unsigned b[4][2];
            #pragma unroll
            for (int ntp = 0; ntp < 2; ntp++) {
                unsigned r[4];
                if constexpr (BT) {
                    unsigned addr = btb + ((n0 + ntp*16 + bt_row)*AH_STR + kb + bt_col)*2;
                    ldsm4(r, addr);
                } else {
                    unsigned addr = btb + ((kb + bf_row)*BH_STR + n0 + ntp*16 + bf_col)*2;
                    ldsm4t(r, addr);
                }
                b[ntp*2][0]   = r[0]; b[ntp*2][1]   = r[1];
                b[ntp*2+1][0] = r[2]; b[ntp*2+1][1] = r[3];
            }
            #pragma unroll
            for (int mt = 0; mt < 4; mt++)
                #pragma unroll
                for (int nt = 0; nt < 4; nt++)
                    mma_f16(c[mt][nt], a[mt], b[nt]);
        }
    }

    float* Cf = (float*)Cv + (OUTH ? 0 : blockIdx.z * sC);
    __half* Ch = (__half*)Cv + (OUTH ? blockIdx.z * sC : 0);
    #pragma unroll
    for (int mt = 0; mt < 4; mt++) {
        int r0g = row0 + m0 + mt * 16 + lr;
        int r1g = r0g + 8;
        float g0 = (EPI == 5) ? gate[r0g] : 0.f;
        float g1 = (EPI == 5) ? gate[r1g] : 0.f;
        #pragma unroll
        for (int nt = 0; nt < 4; nt++) {
            int cg = col0 + n0 + nt * 8 + 2 * lq;
            size_t i0 = (size_t)r0g * N + cg;
            size_t i1 = (size_t)r1g * N + cg;
            float v0 = c[mt][nt][0], v1 = c[mt][nt][1];
            float v2 = c[mt][nt][2], v3 = c[mt][nt][3];
            if (EPI == 2) {
                v0 = v0 / (1.f + __expf(-v0));
                v1 = v1 / (1.f + __expf(-v1));
                v2 = v2 / (1.f + __expf(-v2));
                v3 = v3 / (1.f + __expf(-v3));
            } else if (EPI == 4) {
                float2 x0 = *(const float2*)&Xin[i0];
                float2 x1 = *(const float2*)&Xin[i1];
                v0 += x0.x; v1 += x0.y; v2 += x1.x; v3 += x1.y;
            } else if (EPI == 5) {
                float2 x0 = *(const float2*)&Xin[i0];
                float2 x1 = *(const float2*)&Xin[i1];
                v0 = x0.x + g0*v0; v1 = x0.y + g0*v1;
                v2 = x1.x + g1*v2; v3 = x1.y + g1*v3;
            }
            if (OUTH) {
                *(__half2*)&Ch[i0] = __floats2half2_rn(v0, v1);
                *(__half2*)&Ch[i1] = __floats2half2_rn(v2, v3);
            } else {
                *(float2*)&Cf[i0] = make_float2(v0, v1);
                *(float2*)&Cf[i1] = make_float2(v2, v3);
            }
        }
    }
}

#define SMEM_HBT ((NSTG*AH_TILE + NSTG*AH_TILE) * 2)
#define SMEM_HKN ((NSTG*AH_TILE + NSTG*BH_TILE) * 2)

// ---------------------------------------------------------------------------
// RoPE table + apply (fp32 in, fp16 qkv out; v converted)
// ---------------------------------------------------------------------------
__global__ void rope_table_kernel()
{
    int idx = blockIdx.x * 256 + threadIdx.x;
    int t = idx >> 5, i = idx & 31;
    float inv = powf(10000.f, -(float)i / 32.f);
    float s, c;
    sincosf((float)t * inv, &s, &c);
    g_ropec[idx] = c;
    g_ropes[idx] = s;
}

__global__ void rope_h(const float* __restrict__ qkv, __half* __restrict__ qkvh)
{
    int n = blockIdx.x;
    int t = n & (TT-1);
    int tid = threadIdx.x;
    for (int p = tid; p < 1024; p += 256) {
        int which = p >> 9;
        int rem = p & 511;
        int h = rem >> 5;
        int i = rem & 31;
        float c = g_ropec[t*32 + i];
        float s = g_ropes[t*32 + i];
        size_t base = (size_t)n*3072 + (size_t)which*1024 + h*64 + i;
        float u1 = qkv[base], u2 = qkv[base+32];
        qkvh[base]    = __float2half_rn(u1*c - u2*s);
        qkvh[base+32] = __float2half_rn(u2*c + u1*s);
    }
    const float4* vp = (const float4*)(qkv + (size_t)n*3072 + 2048);
    __half2* vo = (__half2*)(qkvh + (size_t)n*3072 + 2048);
    float4 v = vp[tid];
    vo[2*tid]   = __floats2half2_rn(v.x, v.y);
    vo[2*tid+1] = __floats2half2_rn(v.z, v.w);
}

// ---------------------------------------------------------------------------
// Flash attention FP16 (m16n8k16): BQ=128, 8 warps, BK=32,
// cp.async triple-buffered fp16 K/V, ldmatrix fragments, fp32 softmax.
// ---------------------------------------------------------------------------
#define QH_STR 72
#define KH_STR 72
#define VH_STR 72
#define PH_STR 40
#define QH_OFF 0
#define KH_OFF (128*QH_STR)                 // 9216
#define VH_OFF (KH_OFF + 3*32*KH_STR)       // 16128
#define PH_OFF (VH_OFF + 3*32*VH_STR)       // 23040
#define FLASHH_SMEM ((PH_OFF + 128*PH_STR) * 2)   // 56320 B

__global__ __launch_bounds__(256)
void flash_attn_h(const __half* __restrict__ qkv, __half* __restrict__ out)
{
    extern __shared__ __half fsm_h[];
    __half* Qs = fsm_h + QH_OFF;
    __half* Ks = fsm_h + KH_OFF;
    __half* Vs = fsm_h + VH_OFF;
    __half* Ps = fsm_h + PH_OFF;
    const unsigned smem0 = (unsigned)__cvta_generic_to_shared(fsm_h);

    const int qb = blockIdx.x, bh = blockIdx.y;
    const int b = bh >> 4, h = bh & 15;
    const int tid = threadIdx.x, lane = tid & 31, warp = tid >> 5;
    const int lr = lane >> 2, lq = lane & 3;
    const int g = lane >> 3, tr = lane & 7;
    const int m0 = warp * 16;
    const int q0 = qb * 128;
    const int ntiles = 4*qb + 4;

    // Q: 128 rows x 8 chunks (16B) = 1024 chunks
    #pragma unroll
    for (int c = tid; c < 1024; c += 256) {
        int r = c >> 3, off = (c & 7) * 8;
        cp16(&Qs[r*QH_STR + off], qkv + (size_t)(b*TT + q0 + r)*3072 + h*64 + off);
    }

    auto load_tile = [&](int kb, int buf) {
        __half* Kb = Ks + buf*(32*KH_STR);
        __half* Vb = Vs + buf*(32*VH_STR);
        // 256 chunks each for K and V; one of each per thread
        int r = tid >> 3, off = (tid & 7) * 8;
        size_t base = (size_t)(b*TT + kb*32 + r)*3072 + h*64 + off;
        cp16(&Kb[r*KH_STR + off], qkv + base + 1024);
        cp16(&Vb[r*VH_STR + off], qkv + base + 2048);
        cp_commit();
    };

    load_tile(0, 0);
    load_tile(1, 1);

    float mrow0 = -1e30f, mrow1 = -1e30f;
    float lrow0 = 0.f,    lrow1 = 0.f;
    float o[8][4];
    #pragma unroll
    for (int nt = 0; nt < 8; nt++)
        #pragma unroll
        for (int i = 0; i < 4; i++) o[nt][i] = 0.f;

    const int rg0 = q0 + m0 + lr, rg1 = rg0 + 8;

    // ldmatrix address components
    const int a_row = (g & 1) * 8 + tr;   // A (row-major)
    const int a_col = (g >> 1) * 8;
    const int bt_row = (g >> 1) * 8 + tr; // B non-trans ([n][k])
    const int bt_col = (g & 1) * 8;
    const int bf_row = (g & 1) * 8 + tr;  // B trans ([k][n])
    const int bf_col = (g >> 1) * 8;

    for (int kb = 0; kb < ntiles; kb++) {
        if (kb + 1 < ntiles) cp_wait1(); else cp_wait0();
        __syncthreads();
        if (kb + 2 < ntiles) load_tile(kb + 2, (kb + 2) % 3);

        const unsigned kbb = smem0 + (KH_OFF + (kb % 3)*(32*KH_STR))*2;
        const unsigned vbb = smem0 + (VH_OFF + (kb % 3)*(32*VH_STR))*2;
        const unsigned qbb = smem0 + QH_OFF*2;
        const unsigned pbb = smem0 + PH_OFF*2;

        // ---- S = Q K^T  (4 k16-steps over dh=64) ----
        float s[4][4];
        #pragma unroll
        for (int nt = 0; nt < 4; nt++)
            #pragma unroll
            for (int i = 0; i < 4; i++) s[nt][i] = 0.f;
        #pragma unroll
        for (int ks = 0; ks < 4; ks++) {
            const int kk = ks * 16;
            unsigned a[4];
            ldsm4(a, qbb + ((m0 + a_row)*QH_STR + kk + a_col)*2);
            unsigned bfr[2][4];
            ldsm4(bfr[0], kbb + ((bt_row)*KH_STR + kk + bt_col)*2);
            ldsm4(bfr[1], kbb + ((16 + bt_row)*KH_STR + kk + bt_col)*2);
            unsigned bv[4][2];
            bv[0][0]=bfr[0][0]; bv[0][1]=bfr[0][1];
            bv[1][0]=bfr[0][2]; bv[1][1]=bfr[0][3];
            bv[2][0]=bfr[1][0]; bv[2][1]=bfr[1][1];
            bv[3][0]=bfr[1][2]; bv[3][1]=bfr[1][3];
            #pragma unroll
            for (int nt = 0; nt < 4; nt++)
                mma_f16(s[nt], a, bv[nt]);
        }

        // ---- scale + causal mask ----
        #pragma unroll
        for (int nt = 0; nt < 4; nt++)
            #pragma unroll
            for (int i = 0; i < 4; i++) s[nt][i] *= 0.125f;
        if (kb*32 + 31 > q0 + m0) {
            #pragma unroll
            for (int nt = 0; nt < 4; nt++) {
                int c0 = kb*32 + nt*8 + 2*lq;
                if (c0   > rg0) s[nt][0] = -1e30f;
                if (c0+1 > rg0) s[nt][1] = -1e30f;
                if (c0   > rg1) s[nt][2] = -1e30f;
                if (c0+1 > rg1) s[nt][3] = -1e30f;
            }
        }

        // ---- online softmax ----
        float mx0 = -1e30f, mx1 = -1e30f;
        #pragma unroll
        for (int nt = 0; nt < 4; nt++) {
            mx0 = fmaxf(mx0, fmaxf(s[nt][0], s[nt][1]));
            mx1 = fmaxf(mx1, fmaxf(s[nt][2], s[nt][3]));
        }
        mx0 = fmaxf(mx0, __shfl_xor_sync(0xffffffffu, mx0, 1));
        mx0 = fmaxf(mx0, __shfl_xor_sync(0xffffffffu, mx0, 2));
        mx1 = fmaxf(mx1, __shfl_xor_sync(0xffffffffu, mx1, 1));
        mx1 = fmaxf(mx1, __shfl_xor_sync(0xffffffffu, mx1, 2));
        float mn0 = fmaxf(mrow0, mx0), mn1 = fmaxf(mrow1, mx1);
        float corr0 = __expf(mrow0 - mn0), corr1 = __expf(mrow1 - mn1);
        float sum0 = 0.f, sum1 = 0.f;
        #pragma unroll
        for (int nt = 0; nt < 4; nt++) {
            s[nt][0] = __expf(s[nt][0] - mn0);
            s[nt][1] = __expf(s[nt][1] - mn0);
            s[nt][2] = __expf(s[nt][2] - mn1);
            s[nt][3] = __expf(s[nt][3] - mn1);
            sum0 += s[nt][0] + s[nt][1];
            sum1 += s[nt][2] + s[nt][3];
        }
        sum0 += __shfl_xor_sync(0xffffffffu, sum0, 1);
        sum0 += __shfl_xor_sync(0xffffffffu, sum0, 2);
        sum1 += __shfl_xor_sync(0xffffffffu, sum1, 1);
        sum1 += __shfl_xor_sync(0xffffffffu, sum1, 2);
        lrow0 = lrow0*corr0 + sum0;
        lrow1 = lrow1*corr1 + sum1;
        mrow0 = mn0; mrow1 = mn1;
        #pragma unroll
        for (int nt = 0; nt < 8; nt++) {
            o[nt][0] *= corr0; o[nt][1] *= corr0;
            o[nt][2] *= corr1; o[nt][3] *= corr1;
        }

        // ---- P -> smem as fp16 (warp-private rows) ----
        #pragma unroll
        for (int nt = 0; nt < 4; nt++) {
            *(__half2*)&Ps[(m0+lr)*PH_STR + nt*8+2*lq]   = __floats2half2_rn(s[nt][0], s[nt][1]);
            *(__half2*)&Ps[(m0+lr+8)*PH_STR + nt*8+2*lq] = __floats2half2_rn(s[nt][2], s[nt][3]);
        }
        __syncwarp();

        // ---- O += P V  (2 k16-steps over 32 keys; V [key][dh] trans) ----
        #pragma unroll
        for (int ks = 0; ks < 2; ks++) {
            const int kk = ks * 16;
            unsigned a[4];
            ldsm4(a, pbb + ((m0 + a_row)*PH_STR + kk + a_col)*2);
            #pragma unroll
            for (int ng = 0; ng < 4; ng++) {
                unsigned r[4];
                ldsm4t(r, vbb + ((kk + bf_row)*VH_STR + ng*16 + bf_col)*2);
                unsigned b0[2] = { r[0], r[1] };
                unsigned b1[2] = { r[2], r[3] };
                mma_f16(o[ng*2],   a, b0);
                mma_f16(o[ng*2+1], a, b1);
            }
        }
    }

    float inv0 = 1.f / lrow0, inv1 = 1.f / lrow1;
    #pragma unroll
    for (int nt = 0; nt < 8; nt++) {
        int cg = h*64 + nt*8 + 2*lq;
        size_t base0 = (size_t)(b*TT + rg0)*DD + cg;
        size_t base1 = (size_t)(b*TT + rg1)*DD + cg;
        ((__half2*)out)[base0>>1] = __floats2half2_rn(o[nt][0]*inv0, o[nt][1]*inv0);
        ((__half2*)out)[base1>>1] = __floats2half2_rn(o[nt][2]*inv1, o[nt][3]*inv1);
    }
}

// ---------------------------------------------------------------------------
// Router logits (fp32 xn)
// ---------------------------------------------------------------------------
__global__ void router_kernel(const float* __restrict__ xn,
                              const float* __restrict__ rw,
                              float* __restrict__ logits)
{
    int n = blockIdx.x;
    int warp = threadIdx.x >> 5, lane = threadIdx.x & 31;
    const float* xp = xn + (size_t)n*DD;
    for (int j = 0; j < 4; j++) {
        int e = warp*4 + j;
        const float* wp = rw + (size_t)e*DD;
        float s = 0.f;
        for (int i = lane; i < DD; i += 32) s += xp[i]*wp[i];
        #pragma unroll
        for (int off = 16; off; off >>= 1) s += __shfl_xor_sync(0xffffffffu, s, off);
        if (lane == 0) logits[n*EE + e] = s;
    }
}

__global__ void top2_kernel(const float* __restrict__ logits,
                            float* __restrict__ probs,
                            int* __restrict__ topi, float* __restrict__ topw)
{
    int n = blockIdx.x*blockDim.x + threadIdx.x;
    if (n >= NTOK) return;
    float l[EE];
    float mx = -1e30f;
    #pragma unroll
    for (int e = 0; e < EE; e++) { l[e] = logits[n*EE+e]; mx = fmaxf(mx, l[e]); }
    float sum = 0.f;
    #pragma unroll
    for (int e = 0; e < EE; e++) { l[e] = __expf(l[e]-mx); sum += l[e]; }
    float inv = 1.f/sum;
    #pragma unroll
    for (int e = 0; e < EE; e++) { l[e] *= inv; probs[n*EE+e] = l[e]; }
    int i0 = 0; float p0 = l[0];
    #pragma unroll
    for (int e = 1; e < EE; e++) if (l[e] > p0) { p0 = l[e]; i0 = e; }
    int i1 = (i0 == 0) ? 1 : 0; float p1 = l[i1];
    #pragma unroll
    for (int e = 0; e < EE; e++) if (e != i0 && l[e] > p1) { p1 = l[e]; i1 = e; }
    float ws = p0 + p1;
    topi[n*2]   = i0; topi[n*2+1] = i1;
    topw[n*2]   = p0/ws; topw[n*2+1] = p1/ws;
}

__global__ void pmean_kernel(const float* __restrict__ probs, float* __restrict__ pmean)
{
    int e = blockIdx.x, tid = threadIdx.x;
    float s = 0.f;
    for (int t = tid; t < NTOK; t += 256) s += probs[t*EE + e];
    __shared__ float red[256];
    red[tid] = s;
    __syncthreads();
    for (int k = 128; k; k >>= 1) {
        if (tid < k) red[tid] += red[tid+k];
        __syncthreads();
    }
    if (tid == 0) pmean[e] = red[0] / (float)NTOK;
}

__global__ void assign_kernel(const int* __restrict__ topi,
                              const float* __restrict__ topw,
                              int* __restrict__ slot, int* __restrict__ keep,
                              float* __restrict__ wcomb, int* __restrict__ counts)
{
    int e = blockIdx.x;
    int tid = threadIdx.x;
    int lane = tid & 31, warp = tid >> 5;
    __shared__ int warpsum[8];
    int running = 0;
    for (int base = 0; base < NFLAT; base += 256) {
        int i = base + tid;
        int match = (topi[i] == e) ? 1 : 0;
        unsigned mask = __ballot_sync(0xffffffffu, match);
        if (lane == 0) warpsum[warp] = __popc(mask);
        __syncthreads();
        int wbase = 0, tot = 0;
        #pragma unroll
        for (int w = 0; w < 8; w++) {
            int c = warpsum[w];
            if (w < warp) wbase += c;
            tot += c;
        }
        if (match) {
            int pos = running + wbase + __popc(mask & ((1u << lane) - 1u));
            int kp = (pos < CAP) ? 1 : 0;
            slot[i]  = (pos < CAP-1) ? pos : (CAP-1);
            keep[i]  = kp;
            wcomb[i] = kp ? topw[i] : 0.f;
        }
        running += tot;
        __syncthreads();
    }
    if (tid == 0) counts[e] = running;
}

__global__ void scatter_kernel(const int* __restrict__ topi,
                               const int* __restrict__ slot,
                               const int* __restrict__ keep,
                               const __half* __restrict__ xn,
                               __half* __restrict__ buf)
{
    int i = blockIdx.x;
    if (!keep[i]) return;
    int e = topi[i], s = slot[i], tok = i >> 1;
    const uint2* src = (const uint2*)(xn + (size_t)tok*DD);
    uint2* dst = (uint2*)(buf + ((size_t)e*CAP + s)*DD);
    dst[threadIdx.x] = src[threadIdx.x];
}

__global__ void gather_kernel(const int* __restrict__ topi,
                              const int* __restrict__ slot,
                              const float* __restrict__ wcomb,
                              const float* __restrict__ yb,
                              float* __restrict__ x)
{
    int n = blockIdx.x;
    int t4 = threadIdx.x;
    float4* xp = (float4*)(x + (size_t)n*DD);
    float4 a = xp[t4];
    #pragma unroll
    for (int k = 0; k < 2; k++) {
        int i = n*2 + k;
        float w = wcomb[i];
        if (w != 0.f) {
            int e = topi[i], s = slot[i];
            const float4* yp = (const float4*)(yb + ((size_t)e*CAP + s)*DD);
            float4 yv = yp[t4];
            a.x += w*yv.x; a.y += w*yv.y; a.z += w*yv.z; a.w += w*yv.w;
        }
    }
    xp[t4] = a;
}

__global__ void aux_kernel(const int* __restrict__ counts,
                           const float* __restrict__ pmean,
                           float* __restrict__ out, int out_size)
{
    if (threadIdx.x == 0 && out_size > NTOK*DD) {
        float s = 0.f;
        for (int e = 0; e < EE; e++)
            s += ((float)counts[e] / (float)NTOK) * pmean[e];
        out[NTOK*DD] = (float)EE * s;
    }
}

__global__ void gate_kernel(const __half* __restrict__ xn,
                            const float* __restrict__ gw,
                            const float* __restrict__ gb,
                            float* __restrict__ gate)
{
    int n = blockIdx.x, tid = threadIdx.x;
    const __half2* xp = (const __half2*)(xn + (size_t)n*DD);
    const float4* wp = (const float4*)gw;
    float2 f0 = __half22float2(xp[2*tid]);
    float2 f1 = __half22float2(xp[2*tid+1]);
    float4 wv = wp[tid];
    float s = f0.x*wv.x + f0.y*wv.y + f1.x*wv.z + f1.y*wv.w;
    __shared__ float red[256];
    red[tid] = s;
    __syncthreads();
    for (int k = 128; k; k >>= 1) {
        if (tid < k) red[tid] += red[tid+k];
        __syncthreads();
    }
    if (tid == 0) gate[n] = 1.f / (1.f + __expf(-(red[0] + gb[0])));
}

__global__ void softmax512_kernel(const float* __restrict__ tl, __half* __restrict__ outh)
{
    int n = blockIdx.x, tid = threadIdx.x;
    const float* row = tl + (size_t)n*NPRIM;
    __half* orow = outh + (size_t)n*NPRIM;
    float v0 = row[tid]       * 0.0625f;
    float v1 = row[tid + 256] * 0.0625f;
    __shared__ float red[256];
    red[tid] = fmaxf(v0, v1);
    __syncthreads();
    for (int s = 128; s; s >>= 1) {
        if (tid < s) red[tid] = fmaxf(red[tid], red[tid+s]);
        __syncthreads();
    }
    float mx = red[0];
    __syncthreads();
    v0 = __expf(v0 - mx); v1 = __expf(v1 - mx);
    red[tid] = v0 + v1;
    __syncthreads();
    for (int s = 128; s; s >>= 1) {
        if (tid < s) red[tid] += red[tid+s];
        __syncthreads();
    }
    float inv = 1.f / red[0];
    orow[tid]       = __float2half_rn(v0*inv);
    orow[tid + 256] = __float2half_rn(v1*inv);
}

// ---------------------------------------------------------------------------
// Host launch
// ---------------------------------------------------------------------------
#define F2H(stream, src, dst, n) f2h_kernel<<<(n)/2048, 256, 0, stream>>>(src, dst)

extern "C" void kernel_launch(void* const* d_in, const int* in_sizes, int n_in,
                              void* d_out, int out_size)
{
    const float* x          = (const float*)d_in[0];
    const float* tou_embeds = (const float*)d_in[1];
    const float* norm1_w    = (const float*)d_in[2];
    const float* qkv_w      = (const float*)d_in[3];
    const float* attn_o_w   = (const float*)d_in[4];
    const float* norm2_w    = (const float*)d_in[5];
    const float* router_w   = (const float*)d_in[6];
    const float* moe_w1     = (const float*)d_in[7];
    const float* moe_w2     = (const float*)d_in[8];
    const float* norm3_w    = (const float*)d_in[9];
    const float* tou_q_w    = (const float*)d_in[10];
    const float* tou_k_w    = (const float*)d_in[11];
    const float* tou_v_w    = (const float*)d_in[12];
    const float* tou_o_w    = (const float*)d_in[13];
    const float* tou_gate_w = (const float*)d_in[14];
    const float* tou_gate_b = (const float*)d_in[15];

    cudaFuncSetAttribute(gemm_h<true,0,false>,  cudaFuncAttributeMaxDynamicSharedMemorySize, SMEM_HBT);
    cudaFuncSetAttribute(gemm_h<true,0,true>,   cudaFuncAttributeMaxDynamicSharedMemorySize, SMEM_HBT);
    cudaFuncSetAttribute(gemm_h<true,4,false>,  cudaFuncAttributeMaxDynamicSharedMemorySize, SMEM_HBT);
    cudaFuncSetAttribute(gemm_h<true,5,false>,  cudaFuncAttributeMaxDynamicSharedMemorySize, SMEM_HBT);
    cudaFuncSetAttribute(gemm_h<false,0,false>, cudaFuncAttributeMaxDynamicSharedMemorySize, SMEM_HKN);
    cudaFuncSetAttribute(gemm_h<false,0,true>,  cudaFuncAttributeMaxDynamicSharedMemorySize, SMEM_HKN);
    cudaFuncSetAttribute(gemm_h<false,2,true>,  cudaFuncAttributeMaxDynamicSharedMemorySize, SMEM_HKN);
    cudaFuncSetAttribute(flash_attn_h,          cudaFuncAttributeMaxDynamicSharedMemorySize, FLASHH_SMEM);

    float *gx, *gxn, *gqkv, *glogits, *gprobs, *gtopw, *gwcomb, *gpmean,
          *gyb, *gtl, *ggate;
    int *gtopi, *gslot, *gkeep, *gcounts;
    __half *hqkv, *hxn, *hattn, *hbuf, *hh, *htq, *htk, *htv, *htl, *htout;
    __half *hqkvw, *haow, *hw1, *hw2, *htqw, *htkw, *htvw, *htow, *hemb;
    cudaGetSymbolAddress((void**)&gx, g_x);
    cudaGetSymbolAddress((void**)&gxn, g_xn);
    cudaGetSymbolAddress((void**)&gqkv, g_qkv);
    cudaGetSymbolAddress((void**)&glogits, g_logits);
    cudaGetSymbolAddress((void**)&gprobs, g_probs);
    cudaGetSymbolAddress((void**)&gtopi, g_topi);
    cudaGetSymbolAddress((void**)&gtopw, g_topw);
    cudaGetSymbolAddress((void**)&gslot, g_slot);
    cudaGetSymbolAddress((void**)&gkeep, g_keep);
    cudaGetSymbolAddress((void**)&gwcomb, g_wcomb);
    cudaGetSymbolAddress((void**)&gcounts, g_counts);
    cudaGetSymbolAddress((void**)&gpmean, g_pmean);
    cudaGetSymbolAddress((void**)&gyb, g_yb);
    cudaGetSymbolAddress((void**)&gtl, g_tl);
    cudaGetSymbolAddress((void**)&ggate, g_gate);
    cudaGetSymbolAddress((void**)&hqkv, gh_qkv);
    cudaGetSymbolAddress((void**)&hxn, gh_xn);
    cudaGetSymbolAddress((void**)&hattn, gh_attn);
    cudaGetSymbolAddress((void**)&hbuf, gh_buf);
    cudaGetSymbolAddress((void**)&hh, gh_h);
    cudaGetSymbolAddress((void**)&htq, gh_tq);
    cudaGetSymbolAddress((void**)&htk, gh_tk);
    cudaGetSymbolAddress((void**)&htv, gh_tv);
    cudaGetSymbolAddress((void**)&htl, gh_tl);
    cudaGetSymbolAddress((void**)&htout, gh_tout);
    cudaGetSymbolAddress((void**)&hqkvw, gh_qkvw);
    cudaGetSymbolAddress((void**)&haow, gh_aow);
    cudaGetSymbolAddress((void**)&hw1, gh_w1);
    cudaGetSymbolAddress((void**)&hw2, gh_w2);
    cudaGetSymbolAddress((void**)&htqw, gh_tqw);
    cudaGetSymbolAddress((void**)&htkw, gh_tkw);
    cudaGetSymbolAddress((void**)&htvw, gh_tvw);
    cudaGetSymbolAddress((void**)&htow, gh_tow);
    cudaGetSymbolAddress((void**)&hemb, gh_emb);

    cudaEventRecord(ev_root, 0);

    // ---- s1: rope table, ToU weight conversions + tiny GEMMs ----
    cudaStreamWaitEvent(s1, ev_root, 0);
    rope_table_kernel<<<TT*32/256, 256, 0, s1>>>();
    cudaEventRecord(ev_tab, s1);
    F2H(s1, tou_embeds, hemb, NPRIM*DP);
    F2H(s1, tou_k_w, htkw, DP*DP);
    F2H(s1, tou_v_w, htvw, DP*DP);
    F2H(s1, tou_q_w, htqw, DP*DD);
    F2H(s1, tou_o_w, htow, DD*DP);
    gemm_h<true,0,true><<<dim3(DP/128, NPRIM/128, 1), 256, SMEM_HBT, s1>>>(
        hemb, htkw, htk, NPRIM, DP, DP, 0, 0, 0, nullptr, nullptr);
    gemm_h<true,0,true><<<dim3(DP/128, NPRIM/128, 1), 256, SMEM_HBT, s1>>>(
        hemb, htvw, htv, NPRIM, DP, DP, 0, 0, 0, nullptr, nullptr);
    cudaEventRecord(ev_s1, s1);

    // ---- s2: qkv_w + attn_o conversions, gbuf memset, MoE weight conversions ----
    cudaStreamWaitEvent(s2, ev_root, 0);
    F2H(s2, qkv_w, hqkvw, 3*DD*DD);
    cudaEventRecord(ev_qkvw, s2);
    F2H(s2, attn_o_w, haow, DD*DD);
    cudaEventRecord(ev_aow, s2);
    cudaMemsetAsync(hbuf, 0, (size_t)EE*CAP*DD*sizeof(__half), s2);
    F2H(s2, moe_w1, hw1, EE*DD*FF);
    F2H(s2, moe_w2, hw2, EE*FF*DD);
    cudaEventRecord(ev_s2, s2);

    // ---- Block 1 ----
    rmsnorm_h<<<NTOK, 256>>>(x, norm1_w, hxn, nullptr);
    cudaStreamWaitEvent(0, ev_qkvw, 0);
    gemm_h<true,0,false><<<dim3(3*DD/128, NTOK/128, 1), 256, SMEM_HBT>>>(
        hxn, hqkvw, gqkv, NTOK, 3*DD, DD, 0, 0, 0, nullptr, nullptr);
    cudaStreamWaitEvent(0, ev_tab, 0);
    rope_h<<<NTOK, 256>>>(gqkv, hqkv);
    flash_attn_h<<<dim3(TT/128, BB*HH), 256, FLASHH_SMEM>>>(hqkv, hattn);
    cudaStreamWaitEvent(0, ev_aow, 0);
    gemm_h<true,4,false><<<dim3(DD/128, NTOK/128, 1), 256, SMEM_HBT>>>(
        hattn, haow, gx, NTOK, DD, DD, 0, 0, 0, nullptr, x);   // gx = x + proj

    // ---- Block 2: MoE ----
    rmsnorm_h<<<NTOK, 256>>>(gx, norm2_w, hxn, gxn);
    router_kernel<<<NTOK, 128>>>(gxn, router_w, glogits);
    top2_kernel<<<NTOK/128, 128>>>(glogits, gprobs, gtopi, gtopw);
    cudaEventRecord(ev_top2, 0);
    cudaStreamWaitEvent(s2, ev_top2, 0);
    pmean_kernel<<<EE, 256, 0, s2>>>(gprobs, gpmean);
    cudaEventRecord(ev_pm, s2);
    assign_kernel<<<EE, 256>>>(gtopi, gtopw, gslot, gkeep, gwcomb, gcounts);
    cudaStreamWaitEvent(0, ev_s2, 0);
    scatter_kernel<<<NFLAT, 256>>>(gtopi, gslot, gkeep, hxn, hbuf);
    gemm_h<false,2,true><<<dim3(FF/128, CAP/128, EE), 256, SMEM_HKN>>>(
        hbuf, hw1, hh, CAP, FF, DD,
        (long long)CAP*DD, (long long)DD*FF, (long long)CAP*FF, nullptr, nullptr);
    gemm_h<false,0,false><<<dim3(DD/128, CAP/128, EE), 256, SMEM_HKN>>>(
        hh, hw2, gyb, CAP, DD, FF,
        (long long)CAP*FF, (long long)FF*DD, (long long)CAP*DD, nullptr, nullptr);
    gather_kernel<<<NTOK, 256>>>(gtopi, gslot, gwcomb, gyb, gx);
    cudaStreamWaitEvent(0, ev_pm, 0);
    aux_kernel<<<1, 32>>>(gcounts, gpmean, (float*)d_out, out_size);

    // ---- Block 3: ToU cross-attention ----
    rmsnorm_h<<<NTOK, 256>>>(gx, norm3_w, hxn, nullptr);
    cudaEventRecord(ev_n3, 0);
    cudaStreamWaitEvent(s2, ev_n3, 0);
    gate_kernel<<<NTOK, 256, 0, s2>>>(hxn, tou_gate_w, tou_gate_b, ggate);
    cudaEventRecord(ev_gate, s2);
    cudaStreamWaitEvent(0, ev_s1, 0);
    gemm_h<true,0,true><<<dim3(DP/128, NTOK/128, 1), 256, SMEM_HBT>>>(
        hxn, htqw, htq, NTOK, DP, DD, 0, 0, 0, nullptr, nullptr);
    gemm_h<true,0,false><<<dim3(NPRIM/128, NTOK/128, 1), 256, SMEM_HBT>>>(
        htq, htk, gtl, NTOK, NPRIM, DP, 0, 0, 0, nullptr, nullptr);
    softmax512_kernel<<<NTOK, 256>>>(gtl, htl);
    gemm_h<false,0,true><<<dim3(DP/128, NTOK/128, 1), 256, SMEM_HKN>>>(
        htl, htv, htout, NTOK, DP, NPRIM, 0, 0, 0, nullptr, nullptr);
    cudaStreamWaitEvent(0, ev_gate, 0);
    gemm_h<true,5,false><<<dim3(DD/128, NTOK/128, 1), 256, SMEM_HBT>>>(
        htout, htow, (float*)d_out, NTOK, DD, DP, 0, 0, 0, ggate, gx);
}